// round 6
// baseline (speedup 1.0000x reference)
#include <cuda_runtime.h>
#include <math.h>

#define NN 100000
#define DIM 128
#define NREL 12
#define NBASES 8
#define NEDGE 1000000
#define NP 400000
#define NHYP 20000
#define NB 64
#define LREL 64
#define LKV 128
#define LCTX 32
#define NHEAD 8
#define HDIM 16
#define EDGE_TILES 7830
#define SMEM_DYN 71680   // (2*128*36 + 2*32*136) * 4 bytes

__device__ __forceinline__ void red_add_v4(float* p, float x, float y, float z, float w) {
    asm volatile("red.global.add.v4.f32 [%0], {%1,%2,%3,%4};"
                 :: "l"(p), "f"(x), "f"(y), "f"(z), "f"(w) : "memory");
}

// split fp32 into tf32 hi + tf32 lo (3xTF32 scheme)
__device__ __forceinline__ void split_tf32(float x, unsigned& hi, unsigned& lo) {
    unsigned h, l;
    asm("cvt.rna.tf32.f32 %0, %1;" : "=r"(h) : "f"(x));
    float lf = x - __uint_as_float(h);
    asm("cvt.rna.tf32.f32 %0, %1;" : "=r"(l) : "f"(lf));
    hi = h; lo = l;
}
__device__ __forceinline__ void split4(float4 v, uint4& h, uint4& l) {
    split_tf32(v.x, h.x, l.x); split_tf32(v.y, h.y, l.y);
    split_tf32(v.z, h.z, l.z); split_tf32(v.w, h.w, l.w);
}

__device__ __forceinline__ void mma8(float* c, const unsigned* a, const unsigned* b) {
    asm("mma.sync.aligned.m16n8k8.row.col.f32.tf32.tf32.f32 "
        "{%0,%1,%2,%3}, {%4,%5,%6,%7}, {%8,%9}, {%0,%1,%2,%3};"
        : "+f"(c[0]), "+f"(c[1]), "+f"(c[2]), "+f"(c[3])
        : "r"(a[0]), "r"(a[1]), "r"(a[2]), "r"(a[3]), "r"(b[0]), "r"(b[1]));
}

// one 32-deep K chunk over pre-split tiles: 32 rows x 64 cols per warp
__device__ __forceinline__ void tc_chunk_u(
    const unsigned (*Ah)[36], const unsigned (*Al)[36],
    const unsigned (*Bh)[136], const unsigned (*Bl)[136],
    float acc[2][8][4], int lane, int m0, int n0) {
    const int gr = lane >> 2, tg = lane & 3;
#pragma unroll
    for (int k8 = 0; k8 < 4; k8++) {
        const int kb = k8 * 8;
        unsigned bh[8][2], bl[8][2];
#pragma unroll
        for (int ns = 0; ns < 8; ns++) {
            int c = n0 + ns * 8 + gr;
            bh[ns][0] = Bh[kb + tg][c];     bh[ns][1] = Bh[kb + tg + 4][c];
            bl[ns][0] = Bl[kb + tg][c];     bl[ns][1] = Bl[kb + tg + 4][c];
        }
#pragma unroll
        for (int ms = 0; ms < 2; ms++) {
            int r0 = m0 + ms * 16 + gr;
            unsigned ah[4], al[4];
            ah[0] = Ah[r0][kb+tg];   ah[1] = Ah[r0+8][kb+tg];
            ah[2] = Ah[r0][kb+tg+4]; ah[3] = Ah[r0+8][kb+tg+4];
            al[0] = Al[r0][kb+tg];   al[1] = Al[r0+8][kb+tg];
            al[2] = Al[r0][kb+tg+4]; al[3] = Al[r0+8][kb+tg+4];
#pragma unroll
            for (int ns = 0; ns < 8; ns++) {
                mma8(acc[ms][ns], ah, bh[ns]);
                mma8(acc[ms][ns], ah, bl[ns]);
                mma8(acc[ms][ns], al, bh[ns]);
            }
        }
    }
}

// ---------------- device scratch ----------------
__device__ float g_W[NREL * DIM * DIM];
__device__ float g_kg[NN * DIM];
__device__ int   g_cnt[NN * NREL];
__device__ int   g_typeCnt[NREL];
__device__ int   g_typeOff[NREL + 1];
__device__ int   g_tileOff[NREL + 1];
__device__ int   g_cursor[NREL];
__device__ int   g_sorted[NEDGE];
__device__ float g_xt[NN * DIM];
__device__ int   g_bdegS[NHYP], g_bdegK[NHYP];
__device__ int   g_ddegS[NN], g_ddegK[NN];
__device__ float g_efS[NHYP * DIM], g_efK[NHYP * DIM];
__device__ int   g_flagS[NN], g_flagK[NN];
__device__ float g_noS[NN * DIM], g_noK[NN * DIM];
__device__ float g_related[NB * LKV * DIM];
__device__ float g_context[NB * LCTX * DIM];
__device__ float g_qh[NB * LCTX * DIM];
__device__ float g_kh[NB * LKV * DIM];
__device__ float g_vh[NB * LKV * DIM];
__device__ float g_o[NB * LCTX * DIM];
__device__ float g_attrel[NB * LCTX * DIM];
__device__ float g_t1[NB * LCTX * DIM];
__device__ float g_ucat[NB * 33 * DIM];
__device__ float g_t2[NB * 33 * DIM];
__device__ float g_his[NB * DIM];
__device__ float g_user[NB * DIM];

// ---------------- RGCN prep ----------------
__global__ void k_W(const float* __restrict__ bases, const float* __restrict__ comp) {
    int i = blockIdx.x * blockDim.x + threadIdx.x;
    if (i >= NREL * DIM * DIM) return;
    int r = i / (DIM * DIM), kn = i % (DIM * DIM);
    float s = 0.f;
#pragma unroll
    for (int b = 0; b < NBASES; b++)
        s = fmaf(comp[r * NBASES + b], bases[b * DIM * DIM + kn], s);
    g_W[i] = s;
}

__global__ void k_count(const int* __restrict__ dst, const int* __restrict__ ty) {
    __shared__ int h[NREL];
    int t = threadIdx.x;
    if (t < NREL) h[t] = 0;
    __syncthreads();
    int e = blockIdx.x * blockDim.x + t;
    if (e < NEDGE) {
        int tt = ty[e];
        atomicAdd(&g_cnt[dst[e] * NREL + tt], 1);
        atomicAdd(&h[tt], 1);
    }
    __syncthreads();
    if (t < NREL && h[t]) atomicAdd(&g_typeCnt[t], h[t]);
}

__global__ void k_prefix() {
    int off = 0, toff = 0;
    for (int r = 0; r < NREL; r++) {
        g_typeOff[r] = off; g_cursor[r] = off; g_tileOff[r] = toff;
        int c = g_typeCnt[r];
        off += c; toff += (c + 127) >> 7;
    }
    g_typeOff[NREL] = off; g_tileOff[NREL] = toff;
}

__global__ void k_sort(const int* __restrict__ ty) {
    __shared__ int h[NREL], base[NREL];
    int t = threadIdx.x;
    if (t < NREL) h[t] = 0;
    __syncthreads();
    int e = blockIdx.x * blockDim.x + t;
    int tt = -1, loc = 0;
    if (e < NEDGE) { tt = ty[e]; loc = atomicAdd(&h[tt], 1); }
    __syncthreads();
    if (t < NREL) base[t] = h[t] ? atomicAdd(&g_cursor[t], h[t]) : 0;
    __syncthreads();
    if (e < NEDGE) g_sorted[base[tt] + loc] = e;
}

// ------------- tensor-core GEMM: C[M,128] = A[M,128] @ op(B) (+bias) -------------
__global__ void __launch_bounds__(256) k_gemm128(
    const float* __restrict__ A, const float* __restrict__ Bm,
    const float* __restrict__ bias, float* __restrict__ C, int M, int transB) {
    extern __shared__ unsigned dsm[];
    unsigned (*Ah)[36]  = (unsigned(*)[36])dsm;
    unsigned (*Al)[36]  = (unsigned(*)[36])(dsm + 128 * 36);
    unsigned (*Bh)[136] = (unsigned(*)[136])(dsm + 2 * 128 * 36);
    unsigned (*Bl)[136] = (unsigned(*)[136])(dsm + 2 * 128 * 36 + 32 * 136);
    const int t = threadIdx.x, lane = t & 31, warp = t >> 5;
    const int m0w = (warp & 3) * 32, n0w = (warp >> 2) * 64;
    const int blkM = blockIdx.x * 128;
    float acc[2][8][4];
#pragma unroll
    for (int i = 0; i < 2; i++)
#pragma unroll
        for (int j = 0; j < 8; j++)
#pragma unroll
            for (int q = 0; q < 4; q++) acc[i][j][q] = 0.f;
    const int mA = t >> 1, ksA = (t & 1) * 16;

    for (int k0 = 0; k0 < 128; k0 += 32) {
        int gm = blkM + mA;
        if (gm < M) {
            const float4* ap = reinterpret_cast<const float4*>(A + (size_t)gm * DIM + k0 + ksA);
#pragma unroll
            for (int q = 0; q < 4; q++) {
                uint4 h4, l4; split4(ap[q], h4, l4);
                *reinterpret_cast<uint4*>(&Ah[mA][ksA + 4 * q]) = h4;
                *reinterpret_cast<uint4*>(&Al[mA][ksA + 4 * q]) = l4;
            }
        } else {
            uint4 z = make_uint4(0, 0, 0, 0);
#pragma unroll
            for (int q = 0; q < 4; q++) {
                *reinterpret_cast<uint4*>(&Ah[mA][ksA + 4 * q]) = z;
                *reinterpret_cast<uint4*>(&Al[mA][ksA + 4 * q]) = z;
            }
        }
        if (!transB) {
            int kk = t >> 3, nc = (t & 7) * 16;
            const float4* bp = reinterpret_cast<const float4*>(Bm + (size_t)(k0 + kk) * DIM + nc);
#pragma unroll
            for (int q = 0; q < 4; q++) {
                uint4 h4, l4; split4(bp[q], h4, l4);
                *reinterpret_cast<uint4*>(&Bh[kk][nc + 4 * q]) = h4;
                *reinterpret_cast<uint4*>(&Bl[kk][nc + 4 * q]) = l4;
            }
        } else {
            int n = t >> 1, ks = (t & 1) * 16;
            const float* bp = Bm + (size_t)n * DIM + k0 + ks;
#pragma unroll
            for (int q = 0; q < 16; q++) {
                unsigned h, l; split_tf32(bp[q], h, l);
                Bh[ks + q][n] = h; Bl[ks + q][n] = l;
            }
        }
        __syncthreads();
        tc_chunk_u(Ah, Al, Bh, Bl, acc, lane, m0w, n0w);
        __syncthreads();
    }
    const int gr = lane >> 2, tg = lane & 3;
#pragma unroll
    for (int ms = 0; ms < 2; ms++) {
#pragma unroll
        for (int half = 0; half < 2; half++) {
            int gm = blkM + m0w + ms * 16 + gr + half * 8;
            if (gm < M) {
                float* cp = C + (size_t)gm * DIM;
#pragma unroll
                for (int ns = 0; ns < 8; ns++) {
                    int col = n0w + ns * 8 + 2 * tg;
                    float b0 = bias ? bias[col] : 0.f;
                    float b1 = bias ? bias[col + 1] : 0.f;
                    float2 v = make_float2(acc[ms][ns][half * 2] + b0,
                                           acc[ms][ns][half * 2 + 1] + b1);
                    *reinterpret_cast<float2*>(cp + col) = v;
                }
            }
        }
    }
}

// ------------- RGCN edge GEMM (tensor core): kg[dst] += norm * x[src] @ W[type] -------------
__global__ void __launch_bounds__(256) k_edge_gemm(
    const float* __restrict__ X, const int* __restrict__ esrc, const int* __restrict__ edst) {
    extern __shared__ unsigned dsm[];
    unsigned (*Ah)[36]  = (unsigned(*)[36])dsm;
    unsigned (*Al)[36]  = (unsigned(*)[36])(dsm + 128 * 36);
    unsigned (*Bh)[136] = (unsigned(*)[136])(dsm + 2 * 128 * 36);
    unsigned (*Bl)[136] = (unsigned(*)[136])(dsm + 2 * 128 * 36 + 32 * 136);
    __shared__ int   sSrc[128], sDst[128];
    __shared__ float sNorm[128];
    const int bid = blockIdx.x;
    if (bid >= g_tileOff[NREL]) return;
    int r = 0;
    while (bid >= g_tileOff[r + 1]) r++;
    const int base = g_typeOff[r] + (bid - g_tileOff[r]) * 128;
    int cnt = g_typeOff[r + 1] - base;
    if (cnt > 128) cnt = 128;
    const int t = threadIdx.x, lane = t & 31, warp = t >> 5;
    const int m0w = (warp & 3) * 32, n0w = (warp >> 2) * 64;
    if (t < 128) {
        if (t < cnt) {
            int e = g_sorted[base + t];
            int d = edst[e];
            sSrc[t] = esrc[e]; sDst[t] = d;
            sNorm[t] = 1.0f / fmaxf((float)g_cnt[d * NREL + r], 1.0f);
        } else { sSrc[t] = 0; sDst[t] = -1; sNorm[t] = 0.f; }
    }
    __syncthreads();
    float acc[2][8][4];
#pragma unroll
    for (int i = 0; i < 2; i++)
#pragma unroll
        for (int j = 0; j < 8; j++)
#pragma unroll
            for (int q = 0; q < 4; q++) acc[i][j][q] = 0.f;
    const int mA = t >> 1, ksA = (t & 1) * 16;
    const float* Wr = g_W + (size_t)r * DIM * DIM;

    for (int k0 = 0; k0 < 128; k0 += 32) {
        {
            // gather raw x[src] rows (norm applied in epilogue)
            const float4* ap = reinterpret_cast<const float4*>(X + (size_t)sSrc[mA] * DIM + k0 + ksA);
#pragma unroll
            for (int q = 0; q < 4; q++) {
                uint4 h4, l4; split4(ap[q], h4, l4);
                *reinterpret_cast<uint4*>(&Ah[mA][ksA + 4 * q]) = h4;
                *reinterpret_cast<uint4*>(&Al[mA][ksA + 4 * q]) = l4;
            }
        }
        {
            int kk = t >> 3, nc = (t & 7) * 16;
            const float4* bp = reinterpret_cast<const float4*>(Wr + (size_t)(k0 + kk) * DIM + nc);
#pragma unroll
            for (int q = 0; q < 4; q++) {
                uint4 h4, l4; split4(bp[q], h4, l4);
                *reinterpret_cast<uint4*>(&Bh[kk][nc + 4 * q]) = h4;
                *reinterpret_cast<uint4*>(&Bl[kk][nc + 4 * q]) = l4;
            }
        }
        __syncthreads();
        tc_chunk_u(Ah, Al, Bh, Bl, acc, lane, m0w, n0w);
        __syncthreads();
    }
    const int gr = lane >> 2, tg = lane & 3;
#pragma unroll
    for (int ms = 0; ms < 2; ms++) {
#pragma unroll
        for (int half = 0; half < 2; half++) {
            int rr = m0w + ms * 16 + gr + half * 8;
            int dn = sDst[rr];
            float nrm = sNorm[rr];
#pragma unroll
            for (int ns = 0; ns < 8; ns++) {
                float v0 = acc[ms][ns][half * 2]     * nrm;
                float v1 = acc[ms][ns][half * 2 + 1] * nrm;
                float p0 = __shfl_xor_sync(0xffffffffu, v0, 1);
                float p1 = __shfl_xor_sync(0xffffffffu, v1, 1);
                if (((tg & 1) == 0) && dn >= 0)
                    red_add_v4(g_kg + (size_t)dn * DIM + n0w + ns * 8 + 2 * tg, v0, v1, p0, p1);
            }
        }
    }
}

// ---------------- hypergraph ----------------
__global__ void k_hyper_count(const int* __restrict__ nodes, const int* __restrict__ edges,
                              int* __restrict__ bdeg, int* __restrict__ ddeg) {
    int p = blockIdx.x * blockDim.x + threadIdx.x;
    if (p >= NP) return;
    atomicAdd(&bdeg[edges[p]], 1);
    atomicAdd(&ddeg[nodes[p]], 1);
}

__global__ void k_scatter_ef(const int* __restrict__ nodes, const int* __restrict__ edges,
                             float* __restrict__ ef) {
    int w = (blockIdx.x * blockDim.x + threadIdx.x) >> 5;
    int lane = threadIdx.x & 31;
    if (w >= NP) return;
    float4 v = *reinterpret_cast<const float4*>(&g_xt[(size_t)nodes[w] * DIM + lane * 4]);
    red_add_v4(ef + (size_t)edges[w] * DIM + lane * 4, v.x, v.y, v.z, v.w);
}

__global__ void k_flag(const int* __restrict__ idx, int* __restrict__ flag, float* __restrict__ no) {
    int i = blockIdx.x * blockDim.x + threadIdx.x;
    if (i >= NB * LREL) return;
    int n = idx[i];
    flag[n] = 1;
    float* p = no + (size_t)n * DIM;
    for (int d = 0; d < DIM; d++) p[d] = 0.f;
}

__global__ void k_scatter_node(const int* __restrict__ nodes, const int* __restrict__ edges,
                               const int* __restrict__ flag, const float* __restrict__ ef,
                               const int* __restrict__ bdeg, float* __restrict__ no) {
    int w = (blockIdx.x * blockDim.x + threadIdx.x) >> 5;
    int lane = threadIdx.x & 31;
    if (w >= NP) return;
    int n = nodes[w];
    if (!flag[n]) return;
    int he = edges[w];
    int d = bdeg[he];
    float inv = (d > 0) ? (1.0f / (float)d) : 0.0f;
    float4 v = *reinterpret_cast<const float4*>(ef + (size_t)he * DIM + lane * 4);
    red_add_v4(no + (size_t)n * DIM + lane * 4, v.x * inv, v.y * inv, v.z * inv, v.w * inv);
}

__global__ void k_gather_rel(const int* __restrict__ sidx, const int* __restrict__ kidx,
                             const float* __restrict__ biasS, const float* __restrict__ biasK) {
    int i = blockIdx.x * blockDim.x + threadIdx.x;
    if (i >= NB * LKV * DIM) return;
    int d = i & 127, l = (i >> 7) & 127, b = i >> 14;
    float v;
    if (l < LREL) {
        int n = sidx[b * LREL + l]; int dd = g_ddegS[n];
        v = g_noS[(size_t)n * DIM + d] * (dd > 0 ? 1.f / dd : 0.f) + biasS[d];
    } else {
        int n = kidx[b * LREL + l - LREL]; int dd = g_ddegK[n];
        v = g_noK[(size_t)n * DIM + d] * (dd > 0 ? 1.f / dd : 0.f) + biasK[d];
    }
    g_related[i] = v;
}

__global__ void k_gather_ctx(const int* __restrict__ idx) {
    int i = blockIdx.x * blockDim.x + threadIdx.x;
    if (i >= NB * LCTX * DIM) return;
    g_context[i] = g_kg[(size_t)idx[i >> 7] * DIM + (i & 127)];
}

// ---------------- attention ----------------
__global__ void k_mha() {
    int b = blockIdx.x / NHEAD, h = blockIdx.x % NHEAD;
    __shared__ float ks[LKV][HDIM], vs[LKV][HDIM];
    int t = threadIdx.x;
    for (int i = t; i < LKV * HDIM; i += 32) {
        int k = i / HDIM, d = i % HDIM;
        size_t off = ((size_t)b * LKV + k) * DIM + h * HDIM + d;
        ks[k][d] = g_kh[off]; vs[k][d] = g_vh[off];
    }
    __syncwarp();
    float q[HDIM];
    size_t qoff = ((size_t)b * LCTX + t) * DIM + h * HDIM;
#pragma unroll
    for (int d = 0; d < HDIM; d++) q[d] = g_qh[qoff + d];
    float lg[LKV], mx = -1e30f;
    for (int k = 0; k < LKV; k++) {
        float s = 0.f;
#pragma unroll
        for (int d = 0; d < HDIM; d++) s += q[d] * ks[k][d];
        s *= 0.25f; lg[k] = s; mx = fmaxf(mx, s);
    }
    float sum = 0.f;
    for (int k = 0; k < LKV; k++) { lg[k] = expf(lg[k] - mx); sum += lg[k]; }
    float inv = 1.f / sum;
    float acc[HDIM];
#pragma unroll
    for (int d = 0; d < HDIM; d++) acc[d] = 0.f;
    for (int k = 0; k < LKV; k++) {
        float w = lg[k];
#pragma unroll
        for (int d = 0; d < HDIM; d++) acc[d] += w * vs[k][d];
    }
#pragma unroll
    for (int d = 0; d < HDIM; d++) g_o[qoff + d] = acc[d] * inv;
}

__global__ void k_selfattn(const float* __restrict__ h, const float* __restrict__ t1,
                           const float* __restrict__ bvec, float* __restrict__ out, int L) {
    int b = blockIdx.x, t = threadIdx.x;
    __shared__ float w[40];
    if (t < L) {
        float e = 0.f;
        const float* tp = t1 + ((size_t)b * L + t) * DIM;
        for (int d = 0; d < DIM; d++) e += tanhf(tp[d]) * bvec[d];
        w[t] = e;
    }
    __syncthreads();
    float mx = -1e30f;
    for (int l = 0; l < L; l++) mx = fmaxf(mx, w[l]);
    float sum = 0.f;
    for (int l = 0; l < L; l++) sum += expf(w[l] - mx);
    float inv = 1.f / sum, acc = 0.f;
    for (int l = 0; l < L; l++) acc += expf(w[l] - mx) * h[((size_t)b * L + l) * DIM + t];
    out[(size_t)b * DIM + t] = acc * inv;
}

__global__ void k_ucat() {
    int i = blockIdx.x * blockDim.x + threadIdx.x;
    if (i >= NB * 33 * DIM) return;
    int d = i & 127, l = (i >> 7) % 33, b = i / (33 * DIM);
    g_ucat[i] = (l < 32) ? g_context[((size_t)b * 32 + l) * DIM + d] : g_his[(size_t)b * DIM + d];
}

__global__ void k_scores(const float* __restrict__ rb, float* __restrict__ out) {
    __shared__ float su[32][DIM];
    int t = threadIdx.x;
    int u0 = blockIdx.y * 32;
    for (int i = t; i < 32 * DIM; i += 128)
        su[i >> 7][i & 127] = g_user[(size_t)(u0 + (i >> 7)) * DIM + (i & 127)];
    __syncthreads();
    int n = blockIdx.x * 128 + t;
    if (n >= NN) return;
    float acc[32];
#pragma unroll
    for (int u = 0; u < 32; u++) acc[u] = 0.f;
    const float4* kr = reinterpret_cast<const float4*>(g_kg + (size_t)n * DIM);
    for (int kc = 0; kc < DIM / 4; kc++) {
        float4 v = kr[kc];
#pragma unroll
        for (int u = 0; u < 32; u++)
            acc[u] += su[u][kc*4]*v.x + su[u][kc*4+1]*v.y + su[u][kc*4+2]*v.z + su[u][kc*4+3]*v.w;
    }
    float b = rb[n];
    for (int u = 0; u < 32; u++) out[(size_t)(u0 + u) * NN + n] = acc[u] + b;
}

// ---------------- host ----------------
static void* sym(const void* s) { void* p = nullptr; cudaGetSymbolAddress(&p, s); return p; }

extern "C" void kernel_launch(void* const* d_in, const int* in_sizes, int n_in,
                              void* d_out, int out_size) {
    const float* emb   = (const float*)d_in[0];
    const float* bases = (const float*)d_in[1];
    const float* comp  = (const float*)d_in[2];
    const float* root  = (const float*)d_in[3];
    const float* rbias = (const float*)d_in[4];
    const float* sth   = (const float*)d_in[5];
    const float* sbi   = (const float*)d_in[6];
    const float* kth   = (const float*)d_in[7];
    const float* kbi   = (const float*)d_in[8];
    const float* ipw   = (const float*)d_in[9];
    const float* ipb   = (const float*)d_in[10];
    const float* opw   = (const float*)d_in[11];
    const float* opb   = (const float*)d_in[12];
    const float* aha   = (const float*)d_in[13];
    const float* ahb   = (const float*)d_in[14];
    const float* aa    = (const float*)d_in[15];
    const float* ab    = (const float*)d_in[16];
    const float* recb  = (const float*)d_in[17];
    const int* esrc = (const int*)d_in[18];
    const int* edst = (const int*)d_in[19];
    const int* ety  = (const int*)d_in[20];
    const int* snod = (const int*)d_in[21];
    const int* sedg = (const int*)d_in[22];
    const int* knod = (const int*)d_in[23];
    const int* kedg = (const int*)d_in[24];
    const int* sri  = (const int*)d_in[25];
    const int* kri  = (const int*)d_in[26];
    const int* cxi  = (const int*)d_in[27];
    float* out = (float*)d_out;

    cudaFuncSetAttribute(k_gemm128, cudaFuncAttributeMaxDynamicSharedMemorySize, SMEM_DYN);
    cudaFuncSetAttribute(k_edge_gemm, cudaFuncAttributeMaxDynamicSharedMemorySize, SMEM_DYN);

    cudaMemsetAsync(sym(g_cnt), 0, (size_t)NN * NREL * 4, 0);
    cudaMemsetAsync(sym(g_typeCnt), 0, NREL * 4, 0);
    cudaMemsetAsync(sym(g_bdegS), 0, NHYP * 4, 0);
    cudaMemsetAsync(sym(g_bdegK), 0, NHYP * 4, 0);
    cudaMemsetAsync(sym(g_ddegS), 0, (size_t)NN * 4, 0);
    cudaMemsetAsync(sym(g_ddegK), 0, (size_t)NN * 4, 0);
    cudaMemsetAsync(sym(g_efS), 0, (size_t)NHYP * DIM * 4, 0);
    cudaMemsetAsync(sym(g_efK), 0, (size_t)NHYP * DIM * 4, 0);
    cudaMemsetAsync(sym(g_flagS), 0, (size_t)NN * 4, 0);
    cudaMemsetAsync(sym(g_flagK), 0, (size_t)NN * 4, 0);

    float* kg  = (float*)sym(g_kg);
    float* xt  = (float*)sym(g_xt);

    k_W<<<(NREL * DIM * DIM + 255) / 256, 256>>>(bases, comp);
    k_count<<<(NEDGE + 255) / 256, 256>>>(edst, ety);
    k_prefix<<<1, 1>>>();
    k_sort<<<(NEDGE + 255) / 256, 256>>>(ety);

    k_gemm128<<<(NN + 127) / 128, 256, SMEM_DYN>>>(emb, root, rbias, kg, NN, 0);
    k_edge_gemm<<<EDGE_TILES, 256, SMEM_DYN>>>(emb, esrc, edst);

    // sess hypergraph
    k_gemm128<<<(NN + 127) / 128, 256, SMEM_DYN>>>(kg, sth, nullptr, xt, NN, 0);
    k_hyper_count<<<(NP + 255) / 256, 256>>>(snod, sedg, (int*)sym(g_bdegS), (int*)sym(g_ddegS));
    k_scatter_ef<<<(NP * 32 + 255) / 256, 256>>>(snod, sedg, (float*)sym(g_efS));
    k_flag<<<(NB * LREL + 255) / 256, 256>>>(sri, (int*)sym(g_flagS), (float*)sym(g_noS));
    k_scatter_node<<<(NP * 32 + 255) / 256, 256>>>(snod, sedg, (int*)sym(g_flagS),
                                                   (float*)sym(g_efS), (int*)sym(g_bdegS),
                                                   (float*)sym(g_noS));
    // know hypergraph
    k_gemm128<<<(NN + 127) / 128, 256, SMEM_DYN>>>(kg, kth, nullptr, xt, NN, 0);
    k_hyper_count<<<(NP + 255) / 256, 256>>>(knod, kedg, (int*)sym(g_bdegK), (int*)sym(g_ddegK));
    k_scatter_ef<<<(NP * 32 + 255) / 256, 256>>>(knod, kedg, (float*)sym(g_efK));
    k_flag<<<(NB * LREL + 255) / 256, 256>>>(kri, (int*)sym(g_flagK), (float*)sym(g_noK));
    k_scatter_node<<<(NP * 32 + 255) / 256, 256>>>(knod, kedg, (int*)sym(g_flagK),
                                                   (float*)sym(g_efK), (int*)sym(g_bdegK),
                                                   (float*)sym(g_noK));

    k_gather_rel<<<(NB * LKV * DIM + 255) / 256, 256>>>(sri, kri, sbi, kbi);
    k_gather_ctx<<<(NB * LCTX * DIM + 255) / 256, 256>>>(cxi);

    // MHA projections
    float* ctx = (float*)sym(g_context);
    float* rel = (float*)sym(g_related);
    k_gemm128<<<(NB * LCTX + 127) / 128, 256, SMEM_DYN>>>(ctx, ipw, ipb, (float*)sym(g_qh), NB * LCTX, 1);
    k_gemm128<<<(NB * LKV + 127) / 128, 256, SMEM_DYN>>>(rel, ipw + DIM * DIM, ipb + DIM,
                                                         (float*)sym(g_kh), NB * LKV, 1);
    k_gemm128<<<(NB * LKV + 127) / 128, 256, SMEM_DYN>>>(rel, ipw + 2 * DIM * DIM, ipb + 2 * DIM,
                                                         (float*)sym(g_vh), NB * LKV, 1);
    k_mha<<<NB * NHEAD, 32>>>();
    k_gemm128<<<(NB * LCTX + 127) / 128, 256, SMEM_DYN>>>((float*)sym(g_o), opw, opb,
                                                          (float*)sym(g_attrel), NB * LCTX, 1);

    // his self-attn
    k_gemm128<<<(NB * LCTX + 127) / 128, 256, SMEM_DYN>>>((float*)sym(g_attrel), aha, nullptr,
                                                          (float*)sym(g_t1), NB * LCTX, 0);
    k_selfattn<<<NB, 128>>>((float*)sym(g_attrel), (float*)sym(g_t1), ahb,
                            (float*)sym(g_his), LCTX);

    // user self-attn over [context, his]
    k_ucat<<<(NB * 33 * DIM + 255) / 256, 256>>>();
    k_gemm128<<<(NB * 33 + 127) / 128, 256, SMEM_DYN>>>((float*)sym(g_ucat), aa, nullptr,
                                                        (float*)sym(g_t2), NB * 33, 0);
    k_selfattn<<<NB, 128>>>((float*)sym(g_ucat), (float*)sym(g_t2), ab,
                            (float*)sym(g_user), 33);

    // scores
    dim3 sg((NN + 127) / 128, 2);
    k_scores<<<sg, 128>>>(recb, out);
}

// round 7
// speedup vs baseline: 1.3191x; 1.3191x over previous
#include <cuda_runtime.h>
#include <cuda_bf16.h>
#include <math.h>

#define NN 100000
#define DIM 128
#define NREL 12
#define NBASES 8
#define NEDGE 1000000
#define NP 400000
#define NHYP 20000
#define NB 64
#define LREL 64
#define LKV 128
#define LCTX 32
#define NHEAD 8
#define HDIM 16
#define EDGE_TILES 7830
#define NMAT 21
#define MATW 8192   // 128 rows x 64 packed words per matrix

__device__ __forceinline__ void red_add_v4(float* p, float x, float y, float z, float w) {
    asm volatile("red.global.add.v4.f32 [%0], {%1,%2,%3,%4};"
                 :: "l"(p), "f"(x), "f"(y), "f"(z), "f"(w) : "memory");
}
__device__ __forceinline__ void red_add_v2(float* p, float x, float y) {
    asm volatile("red.global.add.v2.f32 [%0], {%1,%2};"
                 :: "l"(p), "f"(x), "f"(y) : "memory");
}

// split two fp32 into packed bf16x2 hi word + lo word (2-way bf16 split)
__device__ __forceinline__ unsigned pack_split(float x0, float x1, unsigned& lo) {
    __nv_bfloat16 h0 = __float2bfloat16(x0), h1 = __float2bfloat16(x1);
    float r0 = x0 - __bfloat162float(h0), r1 = x1 - __bfloat162float(h1);
    __nv_bfloat16 l0 = __float2bfloat16(r0), l1 = __float2bfloat16(r1);
    lo = (unsigned)__bfloat16_as_ushort(l0) | ((unsigned)__bfloat16_as_ushort(l1) << 16);
    return (unsigned)__bfloat16_as_ushort(h0) | ((unsigned)__bfloat16_as_ushort(h1) << 16);
}

__device__ __forceinline__ void mma16(float* c, const unsigned* a, const unsigned* b) {
    asm("mma.sync.aligned.m16n8k16.row.col.f32.bf16.bf16.f32 "
        "{%0,%1,%2,%3}, {%4,%5,%6,%7}, {%8,%9}, {%0,%1,%2,%3};"
        : "+f"(c[0]), "+f"(c[1]), "+f"(c[2]), "+f"(c[3])
        : "r"(a[0]), "r"(a[1]), "r"(a[2]), "r"(a[3]), "r"(b[0]), "r"(b[1]));
}

// ---------------- device scratch ----------------
__device__ float    g_W[NREL * DIM * DIM];
__device__ unsigned g_Bh[NMAT * MATW];
__device__ unsigned g_Bl[NMAT * MATW];
__device__ float g_kg[NN * DIM];
__device__ int   g_cnt[NN * NREL];
__device__ int   g_typeCnt[NREL];
__device__ int   g_typeOff[NREL + 1];
__device__ int   g_tileOff[NREL + 1];
__device__ int   g_cursor[NREL];
__device__ int   g_sorted[NEDGE];
__device__ float g_xt[NN * DIM];
__device__ int   g_bdegS[NHYP], g_bdegK[NHYP];
__device__ int   g_ddegS[NN], g_ddegK[NN];
__device__ float g_efS[NHYP * DIM], g_efK[NHYP * DIM];
__device__ int   g_flagS[NN], g_flagK[NN];
__device__ float g_noS[NN * DIM], g_noK[NN * DIM];
__device__ float g_related[NB * LKV * DIM];
__device__ float g_context[NB * LCTX * DIM];
__device__ float g_qh[NB * LCTX * DIM];
__device__ float g_kh[NB * LKV * DIM];
__device__ float g_vh[NB * LKV * DIM];
__device__ float g_o[NB * LCTX * DIM];
__device__ float g_attrel[NB * LCTX * DIM];
__device__ float g_t1[NB * LCTX * DIM];
__device__ float g_ucat[NB * 33 * DIM];
__device__ float g_t2[NB * 33 * DIM];
__device__ float g_his[NB * DIM];
__device__ float g_user[NB * DIM];

// ---------------- RGCN prep ----------------
__global__ void k_W(const float* __restrict__ bases, const float* __restrict__ comp) {
    int i = blockIdx.x * blockDim.x + threadIdx.x;
    if (i >= NREL * DIM * DIM) return;
    int r = i / (DIM * DIM), kn = i % (DIM * DIM);
    float s = 0.f;
#pragma unroll
    for (int b = 0; b < NBASES; b++)
        s = fmaf(comp[r * NBASES + b], bases[b * DIM * DIM + kn], s);
    g_W[i] = s;
}

// pack all 21 B-matrices into split bf16x2 [mat][n][k/2] layout
__global__ void k_prep(const float* __restrict__ root, const float* __restrict__ sth,
                       const float* __restrict__ kth, const float* __restrict__ ipw,
                       const float* __restrict__ opw, const float* __restrict__ aha,
                       const float* __restrict__ aa) {
    int idx = blockIdx.x * blockDim.x + threadIdx.x;
    if (idx >= NMAT * MATW) return;
    int m = idx >> 13, rem = idx & (MATW - 1), n = rem >> 6, k2 = rem & 63;
    float s0, s1;
    if (m < 12) {
        const float* b = g_W + m * DIM * DIM;
        s0 = b[(2 * k2) * DIM + n]; s1 = b[(2 * k2 + 1) * DIM + n];
    } else {
        const float* b; int tr = 0;
        switch (m) {
            case 12: b = root; break;
            case 13: b = sth; break;
            case 14: b = kth; break;
            case 15: b = ipw; tr = 1; break;
            case 16: b = ipw + DIM * DIM; tr = 1; break;
            case 17: b = ipw + 2 * DIM * DIM; tr = 1; break;
            case 18: b = opw; tr = 1; break;
            case 19: b = aha; break;
            default: b = aa; break;
        }
        if (tr) { s0 = b[n * DIM + 2 * k2]; s1 = b[n * DIM + 2 * k2 + 1]; }
        else    { s0 = b[(2 * k2) * DIM + n]; s1 = b[(2 * k2 + 1) * DIM + n]; }
    }
    unsigned lo, hi = pack_split(s0, s1, lo);
    g_Bh[idx] = hi; g_Bl[idx] = lo;
}

__global__ void k_count(const int* __restrict__ dst, const int* __restrict__ ty) {
    __shared__ int h[NREL];
    int t = threadIdx.x;
    if (t < NREL) h[t] = 0;
    __syncthreads();
    int e = blockIdx.x * blockDim.x + t;
    if (e < NEDGE) {
        int tt = ty[e];
        atomicAdd(&g_cnt[dst[e] * NREL + tt], 1);
        atomicAdd(&h[tt], 1);
    }
    __syncthreads();
    if (t < NREL && h[t]) atomicAdd(&g_typeCnt[t], h[t]);
}

__global__ void k_prefix() {
    int off = 0, toff = 0;
    for (int r = 0; r < NREL; r++) {
        g_typeOff[r] = off; g_cursor[r] = off; g_tileOff[r] = toff;
        int c = g_typeCnt[r];
        off += c; toff += (c + 127) >> 7;
    }
    g_typeOff[NREL] = off; g_tileOff[NREL] = toff;
}

__global__ void k_sort(const int* __restrict__ ty) {
    __shared__ int h[NREL], base[NREL];
    int t = threadIdx.x;
    if (t < NREL) h[t] = 0;
    __syncthreads();
    int e = blockIdx.x * blockDim.x + t;
    int tt = -1, loc = 0;
    if (e < NEDGE) { tt = ty[e]; loc = atomicAdd(&h[tt], 1); }
    __syncthreads();
    if (t < NREL) base[t] = h[t] ? atomicAdd(&g_cursor[t], h[t]) : 0;
    __syncthreads();
    if (e < NEDGE) g_sorted[base[tt] + loc] = e;
}

// bf16x2 3-term compute over one K32 chunk (stride-20 padded smem, conflict-free)
__device__ __forceinline__ void bf_chunk(
    const unsigned (*Ah)[20], const unsigned (*Al)[20],
    const unsigned (*Bh)[20], const unsigned (*Bl)[20],
    float acc[2][8][4], int lane, int m0, int n0) {
    const int gr = lane >> 2, tg = lane & 3;
#pragma unroll
    for (int s = 0; s < 2; s++) {
        const int kb = s * 8;
        unsigned bh[8][2], bl[8][2];
#pragma unroll
        for (int ns = 0; ns < 8; ns++) {
            int n = n0 + ns * 8 + gr;
            bh[ns][0] = Bh[n][kb + tg]; bh[ns][1] = Bh[n][kb + tg + 4];
            bl[ns][0] = Bl[n][kb + tg]; bl[ns][1] = Bl[n][kb + tg + 4];
        }
#pragma unroll
        for (int ms = 0; ms < 2; ms++) {
            int r = m0 + ms * 16 + gr;
            unsigned ah[4], al[4];
            ah[0] = Ah[r][kb+tg];   ah[1] = Ah[r+8][kb+tg];
            ah[2] = Ah[r][kb+tg+4]; ah[3] = Ah[r+8][kb+tg+4];
            al[0] = Al[r][kb+tg];   al[1] = Al[r+8][kb+tg];
            al[2] = Al[r][kb+tg+4]; al[3] = Al[r+8][kb+tg+4];
#pragma unroll
            for (int ns = 0; ns < 8; ns++) {
                mma16(acc[ms][ns], ah, bh[ns]);
                mma16(acc[ms][ns], ah, bl[ns]);
                mma16(acc[ms][ns], al, bh[ns]);
            }
        }
    }
}

// convert 16 fp32 (scaled) -> 8 packed hi + 8 lo words, store as 2 uint4 each
__device__ __forceinline__ void conv_store_row(const float4* ap, float scale,
                                               unsigned* dh, unsigned* dl) {
    unsigned hw[8], lw[8];
#pragma unroll
    for (int q = 0; q < 4; q++) {
        float4 v = ap[q];
        v.x *= scale; v.y *= scale; v.z *= scale; v.w *= scale;
        hw[2*q]   = pack_split(v.x, v.y, lw[2*q]);
        hw[2*q+1] = pack_split(v.z, v.w, lw[2*q+1]);
    }
    *reinterpret_cast<uint4*>(dh)     = make_uint4(hw[0], hw[1], hw[2], hw[3]);
    *reinterpret_cast<uint4*>(dh + 4) = make_uint4(hw[4], hw[5], hw[6], hw[7]);
    *reinterpret_cast<uint4*>(dl)     = make_uint4(lw[0], lw[1], lw[2], lw[3]);
    *reinterpret_cast<uint4*>(dl + 4) = make_uint4(lw[4], lw[5], lw[6], lw[7]);
}

// ------------- bf16x2 tensor GEMM: C[M,128] = A[M,128] @ B(mat) (+bias) -------------
__global__ void __launch_bounds__(256) k_gemm128b(
    const float* __restrict__ A, int mat, const float* __restrict__ bias,
    float* __restrict__ C, int M) {
    __shared__ unsigned Ah[128][20], Al[128][20], Bh[128][20], Bl[128][20];
    const int t = threadIdx.x, lane = t & 31, warp = t >> 5;
    const int m0w = (warp & 3) * 32, n0w = (warp >> 2) * 64;
    const int blkM = blockIdx.x * 128;
    const unsigned* Bhg = g_Bh + mat * MATW;
    const unsigned* Blg = g_Bl + mat * MATW;
    float acc[2][8][4];
#pragma unroll
    for (int i = 0; i < 2; i++)
#pragma unroll
        for (int j = 0; j < 8; j++)
#pragma unroll
            for (int q = 0; q < 4; q++) acc[i][j][q] = 0.f;
    const int mA = t >> 1, half = t & 1;
    const int nB = t >> 1, hB = (t & 1) * 8;

    for (int k0 = 0; k0 < 128; k0 += 32) {
        int gm = blkM + mA;
        if (gm < M) {
            const float4* ap = reinterpret_cast<const float4*>(A + (size_t)gm * DIM + k0 + half * 16);
            conv_store_row(ap, 1.0f, &Ah[mA][half * 8], &Al[mA][half * 8]);
        } else {
            uint4 z = make_uint4(0, 0, 0, 0);
            *reinterpret_cast<uint4*>(&Ah[mA][half*8]) = z;
            *reinterpret_cast<uint4*>(&Ah[mA][half*8+4]) = z;
            *reinterpret_cast<uint4*>(&Al[mA][half*8]) = z;
            *reinterpret_cast<uint4*>(&Al[mA][half*8+4]) = z;
        }
        {
            const unsigned* sh = Bhg + nB * 64 + k0 / 2 + hB;
            const unsigned* sl = Blg + nB * 64 + k0 / 2 + hB;
            *reinterpret_cast<uint4*>(&Bh[nB][hB])     = *reinterpret_cast<const uint4*>(sh);
            *reinterpret_cast<uint4*>(&Bh[nB][hB + 4]) = *reinterpret_cast<const uint4*>(sh + 4);
            *reinterpret_cast<uint4*>(&Bl[nB][hB])     = *reinterpret_cast<const uint4*>(sl);
            *reinterpret_cast<uint4*>(&Bl[nB][hB + 4]) = *reinterpret_cast<const uint4*>(sl + 4);
        }
        __syncthreads();
        bf_chunk(Ah, Al, Bh, Bl, acc, lane, m0w, n0w);
        __syncthreads();
    }
    const int gr = lane >> 2, tg = lane & 3;
#pragma unroll
    for (int ms = 0; ms < 2; ms++) {
#pragma unroll
        for (int hf = 0; hf < 2; hf++) {
            int gm = blkM + m0w + ms * 16 + gr + hf * 8;
            if (gm < M) {
                float* cp = C + (size_t)gm * DIM;
#pragma unroll
                for (int ns = 0; ns < 8; ns++) {
                    int col = n0w + ns * 8 + 2 * tg;
                    float b0 = bias ? bias[col] : 0.f;
                    float b1 = bias ? bias[col + 1] : 0.f;
                    float2 v = make_float2(acc[ms][ns][hf * 2] + b0,
                                           acc[ms][ns][hf * 2 + 1] + b1);
                    *reinterpret_cast<float2*>(cp + col) = v;
                }
            }
        }
    }
}

// ------------- RGCN edge GEMM (bf16x2): kg[dst] += norm * x[src] @ W[type] -------------
__global__ void __launch_bounds__(256) k_edge_gemm(
    const float* __restrict__ X, const int* __restrict__ esrc, const int* __restrict__ edst) {
    __shared__ unsigned Ah[128][20], Al[128][20], Bh[128][20], Bl[128][20];
    __shared__ int   sSrc[128], sDst[128];
    __shared__ float sNorm[128];
    const int bid = blockIdx.x;
    if (bid >= g_tileOff[NREL]) return;
    int r = 0;
    while (bid >= g_tileOff[r + 1]) r++;
    const int base = g_typeOff[r] + (bid - g_tileOff[r]) * 128;
    int cnt = g_typeOff[r + 1] - base;
    if (cnt > 128) cnt = 128;
    const int t = threadIdx.x, lane = t & 31, warp = t >> 5;
    const int m0w = (warp & 3) * 32, n0w = (warp >> 2) * 64;
    if (t < 128) {
        if (t < cnt) {
            int e = g_sorted[base + t];
            int d = edst[e];
            sSrc[t] = esrc[e]; sDst[t] = d;
            sNorm[t] = 1.0f / fmaxf((float)g_cnt[d * NREL + r], 1.0f);
        } else { sSrc[t] = 0; sDst[t] = -1; sNorm[t] = 0.f; }
    }
    __syncthreads();
    float acc[2][8][4];
#pragma unroll
    for (int i = 0; i < 2; i++)
#pragma unroll
        for (int j = 0; j < 8; j++)
#pragma unroll
            for (int q = 0; q < 4; q++) acc[i][j][q] = 0.f;
    const int mA = t >> 1, half = t & 1;
    const int nB = t >> 1, hB = (t & 1) * 8;
    const unsigned* Bhg = g_Bh + r * MATW;
    const unsigned* Blg = g_Bl + r * MATW;

    for (int k0 = 0; k0 < 128; k0 += 32) {
        {
            const float4* ap = reinterpret_cast<const float4*>(X + (size_t)sSrc[mA] * DIM + k0 + half * 16);
            conv_store_row(ap, sNorm[mA], &Ah[mA][half * 8], &Al[mA][half * 8]);
        }
        {
            const unsigned* sh = Bhg + nB * 64 + k0 / 2 + hB;
            const unsigned* sl = Blg + nB * 64 + k0 / 2 + hB;
            *reinterpret_cast<uint4*>(&Bh[nB][hB])     = *reinterpret_cast<const uint4*>(sh);
            *reinterpret_cast<uint4*>(&Bh[nB][hB + 4]) = *reinterpret_cast<const uint4*>(sh + 4);
            *reinterpret_cast<uint4*>(&Bl[nB][hB])     = *reinterpret_cast<const uint4*>(sl);
            *reinterpret_cast<uint4*>(&Bl[nB][hB + 4]) = *reinterpret_cast<const uint4*>(sl + 4);
        }
        __syncthreads();
        bf_chunk(Ah, Al, Bh, Bl, acc, lane, m0w, n0w);
        __syncthreads();
    }
    const int gr = lane >> 2, tg = lane & 3;
#pragma unroll
    for (int ms = 0; ms < 2; ms++) {
#pragma unroll
        for (int hf = 0; hf < 2; hf++) {
            int dn = sDst[m0w + ms * 16 + gr + hf * 8];
            if (dn >= 0) {
                float* op = g_kg + (size_t)dn * DIM;
#pragma unroll
                for (int ns = 0; ns < 8; ns++) {
                    int col = n0w + ns * 8 + 2 * tg;
                    red_add_v2(op + col, acc[ms][ns][hf * 2], acc[ms][ns][hf * 2 + 1]);
                }
            }
        }
    }
}

// ---------------- hypergraph ----------------
__global__ void k_hyper_count(const int* __restrict__ nodes, const int* __restrict__ edges,
                              int* __restrict__ bdeg, int* __restrict__ ddeg) {
    int p = blockIdx.x * blockDim.x + threadIdx.x;
    if (p >= NP) return;
    atomicAdd(&bdeg[edges[p]], 1);
    atomicAdd(&ddeg[nodes[p]], 1);
}

__global__ void k_scatter_ef(const int* __restrict__ nodes, const int* __restrict__ edges,
                             float* __restrict__ ef) {
    int w = (blockIdx.x * blockDim.x + threadIdx.x) >> 5;
    int lane = threadIdx.x & 31;
    if (w >= NP) return;
    float4 v = *reinterpret_cast<const float4*>(&g_xt[(size_t)nodes[w] * DIM + lane * 4]);
    red_add_v4(ef + (size_t)edges[w] * DIM + lane * 4, v.x, v.y, v.z, v.w);
}

__global__ void k_flag(const int* __restrict__ idx, int* __restrict__ flag, float* __restrict__ no) {
    int i = blockIdx.x * blockDim.x + threadIdx.x;
    if (i >= NB * LREL) return;
    int n = idx[i];
    flag[n] = 1;
    float* p = no + (size_t)n * DIM;
    for (int d = 0; d < DIM; d++) p[d] = 0.f;
}

__global__ void k_scatter_node(const int* __restrict__ nodes, const int* __restrict__ edges,
                               const int* __restrict__ flag, const float* __restrict__ ef,
                               const int* __restrict__ bdeg, float* __restrict__ no) {
    int w = (blockIdx.x * blockDim.x + threadIdx.x) >> 5;
    int lane = threadIdx.x & 31;
    if (w >= NP) return;
    int n = nodes[w];
    if (!flag[n]) return;
    int he = edges[w];
    int d = bdeg[he];
    float inv = (d > 0) ? (1.0f / (float)d) : 0.0f;
    float4 v = *reinterpret_cast<const float4*>(ef + (size_t)he * DIM + lane * 4);
    red_add_v4(no + (size_t)n * DIM + lane * 4, v.x * inv, v.y * inv, v.z * inv, v.w * inv);
}

__global__ void k_gather_rel(const int* __restrict__ sidx, const int* __restrict__ kidx,
                             const float* __restrict__ biasS, const float* __restrict__ biasK) {
    int i = blockIdx.x * blockDim.x + threadIdx.x;
    if (i >= NB * LKV * DIM) return;
    int d = i & 127, l = (i >> 7) & 127, b = i >> 14;
    float v;
    if (l < LREL) {
        int n = sidx[b * LREL + l]; int dd = g_ddegS[n];
        v = g_noS[(size_t)n * DIM + d] * (dd > 0 ? 1.f / dd : 0.f) + biasS[d];
    } else {
        int n = kidx[b * LREL + l - LREL]; int dd = g_ddegK[n];
        v = g_noK[(size_t)n * DIM + d] * (dd > 0 ? 1.f / dd : 0.f) + biasK[d];
    }
    g_related[i] = v;
}

__global__ void k_gather_ctx(const int* __restrict__ idx) {
    int i = blockIdx.x * blockDim.x + threadIdx.x;
    if (i >= NB * LCTX * DIM) return;
    g_context[i] = g_kg[(size_t)idx[i >> 7] * DIM + (i & 127)];
}

// ---------------- attention ----------------
__global__ void k_mha() {
    int b = blockIdx.x / NHEAD, h = blockIdx.x % NHEAD;
    __shared__ float ks[LKV][HDIM], vs[LKV][HDIM];
    int t = threadIdx.x;
    for (int i = t; i < LKV * HDIM; i += 32) {
        int k = i / HDIM, d = i % HDIM;
        size_t off = ((size_t)b * LKV + k) * DIM + h * HDIM + d;
        ks[k][d] = g_kh[off]; vs[k][d] = g_vh[off];
    }
    __syncwarp();
    float q[HDIM];
    size_t qoff = ((size_t)b * LCTX + t) * DIM + h * HDIM;
#pragma unroll
    for (int d = 0; d < HDIM; d++) q[d] = g_qh[qoff + d];
    float lg[LKV], mx = -1e30f;
    for (int k = 0; k < LKV; k++) {
        float s = 0.f;
#pragma unroll
        for (int d = 0; d < HDIM; d++) s += q[d] * ks[k][d];
        s *= 0.25f; lg[k] = s; mx = fmaxf(mx, s);
    }
    float sum = 0.f;
    for (int k = 0; k < LKV; k++) { lg[k] = expf(lg[k] - mx); sum += lg[k]; }
    float inv = 1.f / sum;
    float acc[HDIM];
#pragma unroll
    for (int d = 0; d < HDIM; d++) acc[d] = 0.f;
    for (int k = 0; k < LKV; k++) {
        float w = lg[k];
#pragma unroll
        for (int d = 0; d < HDIM; d++) acc[d] += w * vs[k][d];
    }
#pragma unroll
    for (int d = 0; d < HDIM; d++) g_o[qoff + d] = acc[d] * inv;
}

__global__ void k_selfattn(const float* __restrict__ h, const float* __restrict__ t1,
                           const float* __restrict__ bvec, float* __restrict__ out, int L) {
    int b = blockIdx.x, t = threadIdx.x;
    __shared__ float w[40];
    if (t < L) {
        float e = 0.f;
        const float* tp = t1 + ((size_t)b * L + t) * DIM;
        for (int d = 0; d < DIM; d++) e += tanhf(tp[d]) * bvec[d];
        w[t] = e;
    }
    __syncthreads();
    float mx = -1e30f;
    for (int l = 0; l < L; l++) mx = fmaxf(mx, w[l]);
    float sum = 0.f;
    for (int l = 0; l < L; l++) sum += expf(w[l] - mx);
    float inv = 1.f / sum, acc = 0.f;
    for (int l = 0; l < L; l++) acc += expf(w[l] - mx) * h[((size_t)b * L + l) * DIM + t];
    out[(size_t)b * DIM + t] = acc * inv;
}

__global__ void k_ucat() {
    int i = blockIdx.x * blockDim.x + threadIdx.x;
    if (i >= NB * 33 * DIM) return;
    int d = i & 127, l = (i >> 7) % 33, b = i / (33 * DIM);
    g_ucat[i] = (l < 32) ? g_context[((size_t)b * 32 + l) * DIM + d] : g_his[(size_t)b * DIM + d];
}

__global__ void k_scores(const float* __restrict__ rb, float* __restrict__ out) {
    __shared__ float su[32][DIM];
    int t = threadIdx.x;
    int u0 = blockIdx.y * 32;
    for (int i = t; i < 32 * DIM; i += 128)
        su[i >> 7][i & 127] = g_user[(size_t)(u0 + (i >> 7)) * DIM + (i & 127)];
    __syncthreads();
    int n = blockIdx.x * 128 + t;
    if (n >= NN) return;
    float acc[32];
#pragma unroll
    for (int u = 0; u < 32; u++) acc[u] = 0.f;
    const float4* kr = reinterpret_cast<const float4*>(g_kg + (size_t)n * DIM);
    for (int kc = 0; kc < DIM / 4; kc++) {
        float4 v = kr[kc];
#pragma unroll
        for (int u = 0; u < 32; u++)
            acc[u] += su[u][kc*4]*v.x + su[u][kc*4+1]*v.y + su[u][kc*4+2]*v.z + su[u][kc*4+3]*v.w;
    }
    float b = rb[n];
    for (int u = 0; u < 32; u++) out[(size_t)(u0 + u) * NN + n] = acc[u] + b;
}

// ---------------- host ----------------
static void* sym(const void* s) { void* p = nullptr; cudaGetSymbolAddress(&p, s); return p; }

extern "C" void kernel_launch(void* const* d_in, const int* in_sizes, int n_in,
                              void* d_out, int out_size) {
    const float* emb   = (const float*)d_in[0];
    const float* bases = (const float*)d_in[1];
    const float* comp  = (const float*)d_in[2];
    const float* root  = (const float*)d_in[3];
    const float* rbias = (const float*)d_in[4];
    const float* sth   = (const float*)d_in[5];
    const float* sbi   = (const float*)d_in[6];
    const float* kth   = (const float*)d_in[7];
    const float* kbi   = (const float*)d_in[8];
    const float* ipw   = (const float*)d_in[9];
    const float* ipb   = (const float*)d_in[10];
    const float* opw   = (const float*)d_in[11];
    const float* opb   = (const float*)d_in[12];
    const float* aha   = (const float*)d_in[13];
    const float* ahb   = (const float*)d_in[14];
    const float* aa    = (const float*)d_in[15];
    const float* ab    = (const float*)d_in[16];
    const float* recb  = (const float*)d_in[17];
    const int* esrc = (const int*)d_in[18];
    const int* edst = (const int*)d_in[19];
    const int* ety  = (const int*)d_in[20];
    const int* snod = (const int*)d_in[21];
    const int* sedg = (const int*)d_in[22];
    const int* knod = (const int*)d_in[23];
    const int* kedg = (const int*)d_in[24];
    const int* sri  = (const int*)d_in[25];
    const int* kri  = (const int*)d_in[26];
    const int* cxi  = (const int*)d_in[27];
    float* out = (float*)d_out;

    cudaMemsetAsync(sym(g_cnt), 0, (size_t)NN * NREL * 4, 0);
    cudaMemsetAsync(sym(g_typeCnt), 0, NREL * 4, 0);
    cudaMemsetAsync(sym(g_bdegS), 0, NHYP * 4, 0);
    cudaMemsetAsync(sym(g_bdegK), 0, NHYP * 4, 0);
    cudaMemsetAsync(sym(g_ddegS), 0, (size_t)NN * 4, 0);
    cudaMemsetAsync(sym(g_ddegK), 0, (size_t)NN * 4, 0);
    cudaMemsetAsync(sym(g_efS), 0, (size_t)NHYP * DIM * 4, 0);
    cudaMemsetAsync(sym(g_efK), 0, (size_t)NHYP * DIM * 4, 0);
    cudaMemsetAsync(sym(g_flagS), 0, (size_t)NN * 4, 0);
    cudaMemsetAsync(sym(g_flagK), 0, (size_t)NN * 4, 0);

    float* kg  = (float*)sym(g_kg);
    float* xt  = (float*)sym(g_xt);

    k_W<<<(NREL * DIM * DIM + 255) / 256, 256>>>(bases, comp);
    k_prep<<<(NMAT * MATW + 255) / 256, 256>>>(root, sth, kth, ipw, opw, aha, aa);
    k_count<<<(NEDGE + 255) / 256, 256>>>(edst, ety);
    k_prefix<<<1, 1>>>();
    k_sort<<<(NEDGE + 255) / 256, 256>>>(ety);

    k_gemm128b<<<(NN + 127) / 128, 256>>>(emb, 12, rbias, kg, NN);
    k_edge_gemm<<<EDGE_TILES, 256>>>(emb, esrc, edst);

    // sess hypergraph
    k_gemm128b<<<(NN + 127) / 128, 256>>>(kg, 13, nullptr, xt, NN);
    k_hyper_count<<<(NP + 255) / 256, 256>>>(snod, sedg, (int*)sym(g_bdegS), (int*)sym(g_ddegS));
    k_scatter_ef<<<(NP * 32 + 255) / 256, 256>>>(snod, sedg, (float*)sym(g_efS));
    k_flag<<<(NB * LREL + 255) / 256, 256>>>(sri, (int*)sym(g_flagS), (float*)sym(g_noS));
    k_scatter_node<<<(NP * 32 + 255) / 256, 256>>>(snod, sedg, (int*)sym(g_flagS),
                                                   (float*)sym(g_efS), (int*)sym(g_bdegS),
                                                   (float*)sym(g_noS));
    // know hypergraph
    k_gemm128b<<<(NN + 127) / 128, 256>>>(kg, 14, nullptr, xt, NN);
    k_hyper_count<<<(NP + 255) / 256, 256>>>(knod, kedg, (int*)sym(g_bdegK), (int*)sym(g_ddegK));
    k_scatter_ef<<<(NP * 32 + 255) / 256, 256>>>(knod, kedg, (float*)sym(g_efK));
    k_flag<<<(NB * LREL + 255) / 256, 256>>>(kri, (int*)sym(g_flagK), (float*)sym(g_noK));
    k_scatter_node<<<(NP * 32 + 255) / 256, 256>>>(knod, kedg, (int*)sym(g_flagK),
                                                   (float*)sym(g_efK), (int*)sym(g_bdegK),
                                                   (float*)sym(g_noK));

    k_gather_rel<<<(NB * LKV * DIM + 255) / 256, 256>>>(sri, kri, sbi, kbi);
    k_gather_ctx<<<(NB * LCTX * DIM + 255) / 256, 256>>>(cxi);

    // MHA projections
    float* ctx = (float*)sym(g_context);
    float* rel = (float*)sym(g_related);
    k_gemm128b<<<(NB * LCTX + 127) / 128, 256>>>(ctx, 15, ipb, (float*)sym(g_qh), NB * LCTX);
    k_gemm128b<<<(NB * LKV + 127) / 128, 256>>>(rel, 16, ipb + DIM, (float*)sym(g_kh), NB * LKV);
    k_gemm128b<<<(NB * LKV + 127) / 128, 256>>>(rel, 17, ipb + 2 * DIM, (float*)sym(g_vh), NB * LKV);
    k_mha<<<NB * NHEAD, 32>>>();
    k_gemm128b<<<(NB * LCTX + 127) / 128, 256>>>((float*)sym(g_o), 18, opb,
                                                 (float*)sym(g_attrel), NB * LCTX);

    // his self-attn
    k_gemm128b<<<(NB * LCTX + 127) / 128, 256>>>((float*)sym(g_attrel), 19, nullptr,
                                                 (float*)sym(g_t1), NB * LCTX);
    k_selfattn<<<NB, 128>>>((float*)sym(g_attrel), (float*)sym(g_t1), ahb,
                            (float*)sym(g_his), LCTX);

    // user self-attn over [context, his]
    k_ucat<<<(NB * 33 * DIM + 255) / 256, 256>>>();
    k_gemm128b<<<(NB * 33 + 127) / 128, 256>>>((float*)sym(g_ucat), 20, nullptr,
                                               (float*)sym(g_t2), NB * 33);
    k_selfattn<<<NB, 128>>>((float*)sym(g_ucat), (float*)sym(g_t2), ab,
                            (float*)sym(g_user), 33);

    // scores
    dim3 sg((NN + 127) / 128, 2);
    k_scores<<<sg, 128>>>(recb, out);
}

// round 8
// speedup vs baseline: 1.4980x; 1.1356x over previous
#include <cuda_runtime.h>
#include <cuda_bf16.h>
#include <math.h>

#define NN 100000
#define DIM 128
#define NREL 12
#define NBASES 8
#define NEDGE 1000000
#define NP 400000
#define NHYP 20000
#define NB 64
#define LREL 64
#define LKV 128
#define LCTX 32
#define NHEAD 8
#define HDIM 16
#define EDGE_TILES 7830
#define NMAT 22
#define MATW 8192   // 128 rows x 64 packed words per matrix

#define ROOTB 782
#define COUNTB 3907
#define HCB 1563
#define FLAGB 16
#define EFB 157

__device__ __forceinline__ void red_add_v4(float* p, float x, float y, float z, float w) {
    asm volatile("red.global.add.v4.f32 [%0], {%1,%2,%3,%4};"
                 :: "l"(p), "f"(x), "f"(y), "f"(z), "f"(w) : "memory");
}

// split two fp32 into packed bf16x2 hi word + lo word
__device__ __forceinline__ unsigned pack_split(float x0, float x1, unsigned& lo) {
    __nv_bfloat16 h0 = __float2bfloat16(x0), h1 = __float2bfloat16(x1);
    float r0 = x0 - __bfloat162float(h0), r1 = x1 - __bfloat162float(h1);
    __nv_bfloat16 l0 = __float2bfloat16(r0), l1 = __float2bfloat16(r1);
    lo = (unsigned)__bfloat16_as_ushort(l0) | ((unsigned)__bfloat16_as_ushort(l1) << 16);
    return (unsigned)__bfloat16_as_ushort(h0) | ((unsigned)__bfloat16_as_ushort(h1) << 16);
}

__device__ __forceinline__ void mma16(float* c, const unsigned* a, const unsigned* b) {
    asm("mma.sync.aligned.m16n8k16.row.col.f32.bf16.bf16.f32 "
        "{%0,%1,%2,%3}, {%4,%5,%6,%7}, {%8,%9}, {%0,%1,%2,%3};"
        : "+f"(c[0]), "+f"(c[1]), "+f"(c[2]), "+f"(c[3])
        : "r"(a[0]), "r"(a[1]), "r"(a[2]), "r"(a[3]), "r"(b[0]), "r"(b[1]));
}

// ---------------- device scratch ----------------
__device__ float    g_W[NREL * DIM * DIM];
__device__ unsigned g_Bh[NMAT * MATW];
__device__ unsigned g_Bl[NMAT * MATW];
__device__ float g_kg[NN * DIM];
__device__ int   g_cnt[NN * NREL];
__device__ int   g_typeCnt[NREL];
__device__ int   g_typeOff[NREL + 1];
__device__ int   g_tileOff[NREL + 1];
__device__ int   g_cursor[NREL];
__device__ int   g_sorted[NEDGE];
__device__ int   g_bdegS[NHYP], g_bdegK[NHYP];
__device__ int   g_ddegS[NN], g_ddegK[NN];
__device__ float g_accS[NHYP * DIM], g_accK[NHYP * DIM];
__device__ float g_efS[NHYP * DIM], g_efK[NHYP * DIM];
__device__ int   g_flagS[NN], g_flagK[NN];
__device__ float g_noS[NN * DIM], g_noK[NN * DIM];
__device__ float g_related[NB * LKV * DIM];
__device__ float g_context[NB * LCTX * DIM];
__device__ float g_qh[NB * LCTX * DIM];
__device__ float g_kh[NB * LKV * DIM];
__device__ float g_vh[NB * LKV * DIM];
__device__ float g_o[NB * LCTX * DIM];
__device__ float g_attrel[NB * LCTX * DIM];
__device__ float g_t1[NB * LCTX * DIM];
__device__ float g_ucat[NB * 33 * DIM];
__device__ float g_t2[NB * 33 * DIM];
__device__ float g_his[NB * DIM];
__device__ float g_user[NB * DIM];

// ---------------- prep ----------------
__global__ void k_W(const float* __restrict__ bases, const float* __restrict__ comp) {
    int i = blockIdx.x * blockDim.x + threadIdx.x;
    if (i >= NREL * DIM * DIM) return;
    int r = i / (DIM * DIM), kn = i % (DIM * DIM);
    float s = 0.f;
#pragma unroll
    for (int b = 0; b < NBASES; b++)
        s = fmaf(comp[r * NBASES + b], bases[b * DIM * DIM + kn], s);
    g_W[i] = s;
}

// pack 21 static B-matrices into split bf16x2 [mat][n][k/2] layout
__global__ void k_prep(const float* __restrict__ root, const float* __restrict__ sth,
                       const float* __restrict__ kth, const float* __restrict__ ipw,
                       const float* __restrict__ opw, const float* __restrict__ aha,
                       const float* __restrict__ aa) {
    int idx = blockIdx.x * blockDim.x + threadIdx.x;
    if (idx >= 21 * MATW) return;
    int m = idx >> 13, rem = idx & (MATW - 1), n = rem >> 6, k2 = rem & 63;
    float s0, s1;
    if (m < 12) {
        const float* b = g_W + m * DIM * DIM;
        s0 = b[(2 * k2) * DIM + n]; s1 = b[(2 * k2 + 1) * DIM + n];
    } else {
        const float* b; int tr = 0;
        switch (m) {
            case 12: b = root; break;
            case 13: b = sth; break;
            case 14: b = kth; break;
            case 15: b = ipw; tr = 1; break;
            case 16: b = ipw + DIM * DIM; tr = 1; break;
            case 17: b = ipw + 2 * DIM * DIM; tr = 1; break;
            case 18: b = opw; tr = 1; break;
            case 19: b = aha; break;
            default: b = aa; break;
        }
        if (tr) { s0 = b[n * DIM + 2 * k2]; s1 = b[n * DIM + 2 * k2 + 1]; }
        else    { s0 = b[(2 * k2) * DIM + n]; s1 = b[(2 * k2 + 1) * DIM + n]; }
    }
    unsigned lo, hi = pack_split(s0, s1, lo);
    g_Bh[idx] = hi; g_Bl[idx] = lo;
}

__global__ void k_packU() {
    int idx = blockIdx.x * blockDim.x + threadIdx.x;
    if (idx >= MATW) return;
    int n = idx >> 6, k2 = idx & 63;
    float s0 = 0.f, s1 = 0.f;
    if (n < NB) { s0 = g_user[n * DIM + 2 * k2]; s1 = g_user[n * DIM + 2 * k2 + 1]; }
    unsigned lo, hi = pack_split(s0, s1, lo);
    g_Bh[21 * MATW + idx] = hi; g_Bl[21 * MATW + idx] = lo;
}

__global__ void k_prefix() {
    int off = 0, toff = 0;
    for (int r = 0; r < NREL; r++) {
        g_typeOff[r] = off; g_cursor[r] = off; g_tileOff[r] = toff;
        int c = g_typeCnt[r];
        off += c; toff += (c + 127) >> 7;
    }
    g_typeOff[NREL] = off; g_tileOff[NREL] = toff;
}

__global__ void k_sort(const int* __restrict__ ty) {
    __shared__ int h[NREL], base[NREL];
    int t = threadIdx.x;
    if (t < NREL) h[t] = 0;
    __syncthreads();
    int e = blockIdx.x * blockDim.x + t;
    int tt = -1, loc = 0;
    if (e < NEDGE) { tt = ty[e]; loc = atomicAdd(&h[tt], 1); }
    __syncthreads();
    if (t < NREL) base[t] = h[t] ? atomicAdd(&g_cursor[t], h[t]) : 0;
    __syncthreads();
    if (e < NEDGE) g_sorted[base[tt] + loc] = e;
}

// bf16x2 3-term compute over one K32 chunk
__device__ __forceinline__ void bf_chunk(
    const unsigned (*Ah)[20], const unsigned (*Al)[20],
    const unsigned (*Bh)[20], const unsigned (*Bl)[20],
    float acc[2][8][4], int lane, int m0, int n0) {
    const int gr = lane >> 2, tg = lane & 3;
#pragma unroll
    for (int s = 0; s < 2; s++) {
        const int kb = s * 8;
        unsigned bh[8][2], bl[8][2];
#pragma unroll
        for (int ns = 0; ns < 8; ns++) {
            int n = n0 + ns * 8 + gr;
            bh[ns][0] = Bh[n][kb + tg]; bh[ns][1] = Bh[n][kb + tg + 4];
            bl[ns][0] = Bl[n][kb + tg]; bl[ns][1] = Bl[n][kb + tg + 4];
        }
#pragma unroll
        for (int ms = 0; ms < 2; ms++) {
            int r = m0 + ms * 16 + gr;
            unsigned ah[4], al[4];
            ah[0] = Ah[r][kb+tg];   ah[1] = Ah[r+8][kb+tg];
            ah[2] = Ah[r][kb+tg+4]; ah[3] = Ah[r+8][kb+tg+4];
            al[0] = Al[r][kb+tg];   al[1] = Al[r+8][kb+tg];
            al[2] = Al[r][kb+tg+4]; al[3] = Al[r+8][kb+tg+4];
#pragma unroll
            for (int ns = 0; ns < 8; ns++) {
                mma16(acc[ms][ns], ah, bh[ns]);
                mma16(acc[ms][ns], ah, bl[ns]);
                mma16(acc[ms][ns], al, bh[ns]);
            }
        }
    }
}

// convert 16 fp32 (scaled) -> 8 hi + 8 lo packed words
__device__ __forceinline__ void conv_store_row(const float4* ap, float scale,
                                               unsigned* dh, unsigned* dl) {
    unsigned hw[8], lw[8];
#pragma unroll
    for (int q = 0; q < 4; q++) {
        float4 v = ap[q];
        v.x *= scale; v.y *= scale; v.z *= scale; v.w *= scale;
        hw[2*q]   = pack_split(v.x, v.y, lw[2*q]);
        hw[2*q+1] = pack_split(v.z, v.w, lw[2*q+1]);
    }
    *reinterpret_cast<uint4*>(dh)     = make_uint4(hw[0], hw[1], hw[2], hw[3]);
    *reinterpret_cast<uint4*>(dh + 4) = make_uint4(hw[4], hw[5], hw[6], hw[7]);
    *reinterpret_cast<uint4*>(dl)     = make_uint4(lw[0], lw[1], lw[2], lw[3]);
    *reinterpret_cast<uint4*>(dl + 4) = make_uint4(lw[4], lw[5], lw[6], lw[7]);
}

// ------------- generic GEMM body: C[M,128] = A[M,128] @ B(mat) (+bias, row scale 1/deg) ----
__device__ __forceinline__ void gemm_body(
    unsigned (*Ah)[20], unsigned (*Al)[20], unsigned (*Bh)[20], unsigned (*Bl)[20],
    const float* __restrict__ A, int mat, const float* __restrict__ bias,
    float* __restrict__ C, int M, const int* __restrict__ rowdeg, int blk) {
    const int t = threadIdx.x, lane = t & 31, warp = t >> 5;
    const int m0w = (warp & 3) * 32, n0w = (warp >> 2) * 64;
    const int blkM = blk * 128;
    const unsigned* Bhg = g_Bh + mat * MATW;
    const unsigned* Blg = g_Bl + mat * MATW;
    float acc[2][8][4];
#pragma unroll
    for (int i = 0; i < 2; i++)
#pragma unroll
        for (int j = 0; j < 8; j++)
#pragma unroll
            for (int q = 0; q < 4; q++) acc[i][j][q] = 0.f;
    const int mA = t >> 1, half = t & 1;
    const int nB = t >> 1, hB = (t & 1) * 8;

    for (int k0 = 0; k0 < 128; k0 += 32) {
        int gm = blkM + mA;
        if (gm < M) {
            const float4* ap = reinterpret_cast<const float4*>(A + (size_t)gm * DIM + k0 + half * 16);
            conv_store_row(ap, 1.0f, &Ah[mA][half * 8], &Al[mA][half * 8]);
        } else {
            uint4 z = make_uint4(0, 0, 0, 0);
            *reinterpret_cast<uint4*>(&Ah[mA][half*8]) = z;
            *reinterpret_cast<uint4*>(&Ah[mA][half*8+4]) = z;
            *reinterpret_cast<uint4*>(&Al[mA][half*8]) = z;
            *reinterpret_cast<uint4*>(&Al[mA][half*8+4]) = z;
        }
        {
            const unsigned* sh = Bhg + nB * 64 + k0 / 2 + hB;
            const unsigned* sl = Blg + nB * 64 + k0 / 2 + hB;
            *reinterpret_cast<uint4*>(&Bh[nB][hB])     = *reinterpret_cast<const uint4*>(sh);
            *reinterpret_cast<uint4*>(&Bh[nB][hB + 4]) = *reinterpret_cast<const uint4*>(sh + 4);
            *reinterpret_cast<uint4*>(&Bl[nB][hB])     = *reinterpret_cast<const uint4*>(sl);
            *reinterpret_cast<uint4*>(&Bl[nB][hB + 4]) = *reinterpret_cast<const uint4*>(sl + 4);
        }
        __syncthreads();
        bf_chunk(Ah, Al, Bh, Bl, acc, lane, m0w, n0w);
        __syncthreads();
    }
    const int gr = lane >> 2, tg = lane & 3;
#pragma unroll
    for (int ms = 0; ms < 2; ms++) {
#pragma unroll
        for (int hf = 0; hf < 2; hf++) {
            int gm = blkM + m0w + ms * 16 + gr + hf * 8;
            if (gm < M) {
                float scale = 1.f;
                if (rowdeg) { int dg = rowdeg[gm]; scale = dg > 0 ? 1.f / (float)dg : 0.f; }
                float* cp = C + (size_t)gm * DIM;
#pragma unroll
                for (int ns = 0; ns < 8; ns++) {
                    int col = n0w + ns * 8 + 2 * tg;
                    float b0 = bias ? bias[col] : 0.f;
                    float b1 = bias ? bias[col + 1] : 0.f;
                    float2 v = make_float2(acc[ms][ns][hf * 2] * scale + b0,
                                           acc[ms][ns][hf * 2 + 1] * scale + b1);
                    *reinterpret_cast<float2*>(cp + col) = v;
                }
            }
        }
    }
}

__global__ void __launch_bounds__(256) k_gemm128b(
    const float* __restrict__ A, int mat, const float* __restrict__ bias,
    float* __restrict__ C, int M) {
    __shared__ unsigned Ah[128][20], Al[128][20], Bh[128][20], Bl[128][20];
    gemm_body(Ah, Al, Bh, Bl, A, mat, bias, C, M, nullptr, blockIdx.x);
}

// ------------- F1: root GEMM || edge count || hyper counts || flags -------------
__global__ void __launch_bounds__(256) k_fuse1(
    const float* __restrict__ emb, const float* __restrict__ rbias,
    const int* __restrict__ edst, const int* __restrict__ ety,
    const int* __restrict__ snod, const int* __restrict__ sedg,
    const int* __restrict__ knod, const int* __restrict__ kedg,
    const int* __restrict__ sri, const int* __restrict__ kri) {
    __shared__ unsigned Ah[128][20], Al[128][20], Bh[128][20], Bl[128][20];
    __shared__ int fh[NREL];
    int b = blockIdx.x;
    int t = threadIdx.x;
    if (b < ROOTB) {
        gemm_body(Ah, Al, Bh, Bl, emb, 12, rbias, g_kg, NN, nullptr, b);
        return;
    }
    b -= ROOTB;
    if (b < COUNTB) {
        if (t < NREL) fh[t] = 0;
        __syncthreads();
        int e = b * 256 + t;
        if (e < NEDGE) {
            int tt = ety[e];
            atomicAdd(&g_cnt[edst[e] * NREL + tt], 1);
            atomicAdd(&fh[tt], 1);
        }
        __syncthreads();
        if (t < NREL && fh[t]) atomicAdd(&g_typeCnt[t], fh[t]);
        return;
    }
    b -= COUNTB;
    if (b < 2 * HCB) {
        const int* nodes; const int* edges; int* bdeg; int* ddeg;
        int lb = b;
        if (lb < HCB) { nodes = snod; edges = sedg; bdeg = g_bdegS; ddeg = g_ddegS; }
        else { lb -= HCB; nodes = knod; edges = kedg; bdeg = g_bdegK; ddeg = g_ddegK; }
        int p = lb * 256 + t;
        if (p < NP) {
            atomicAdd(&bdeg[edges[p]], 1);
            atomicAdd(&ddeg[nodes[p]], 1);
        }
        return;
    }
    b -= 2 * HCB;
    {
        const int* idx; int* flag; float* no;
        int lb = b;
        if (lb < FLAGB) { idx = sri; flag = g_flagS; no = g_noS; }
        else { lb -= FLAGB; idx = kri; flag = g_flagK; no = g_noK; }
        int i = lb * 256 + t;
        if (i < NB * LREL) {
            int n = idx[i];
            flag[n] = 1;
            float* p = no + (size_t)n * DIM;
            for (int d = 0; d < DIM; d++) p[d] = 0.f;
        }
    }
}

// ------------- RGCN edge GEMM: kg[dst] += norm * x[src] @ W[type] -------------
__global__ void __launch_bounds__(256) k_edge_gemm(
    const float* __restrict__ X, const int* __restrict__ esrc, const int* __restrict__ edst) {
    __shared__ unsigned Ah[128][20], Al[128][20], Bh[128][20], Bl[128][20];
    __shared__ int   sSrc[128], sDst[128];
    __shared__ float sNorm[128];
    const int bid = blockIdx.x;
    if (bid >= g_tileOff[NREL]) return;
    int r = 0;
    while (bid >= g_tileOff[r + 1]) r++;
    const int base = g_typeOff[r] + (bid - g_tileOff[r]) * 128;
    int cnt = g_typeOff[r + 1] - base;
    if (cnt > 128) cnt = 128;
    const int t = threadIdx.x, lane = t & 31, warp = t >> 5;
    const int m0w = (warp & 3) * 32, n0w = (warp >> 2) * 64;
    if (t < 128) {
        if (t < cnt) {
            int e = g_sorted[base + t];
            int d = edst[e];
            sSrc[t] = esrc[e]; sDst[t] = d;
            sNorm[t] = 1.0f / fmaxf((float)g_cnt[d * NREL + r], 1.0f);
        } else { sSrc[t] = 0; sDst[t] = -1; sNorm[t] = 0.f; }
    }
    __syncthreads();
    float acc[2][8][4];
#pragma unroll
    for (int i = 0; i < 2; i++)
#pragma unroll
        for (int j = 0; j < 8; j++)
#pragma unroll
            for (int q = 0; q < 4; q++) acc[i][j][q] = 0.f;
    const int mA = t >> 1, half = t & 1;
    const int nB = t >> 1, hB = (t & 1) * 8;
    const unsigned* Bhg = g_Bh + r * MATW;
    const unsigned* Blg = g_Bl + r * MATW;

    for (int k0 = 0; k0 < 128; k0 += 32) {
        {
            const float4* ap = reinterpret_cast<const float4*>(X + (size_t)sSrc[mA] * DIM + k0 + half * 16);
            conv_store_row(ap, sNorm[mA], &Ah[mA][half * 8], &Al[mA][half * 8]);
        }
        {
            const unsigned* sh = Bhg + nB * 64 + k0 / 2 + hB;
            const unsigned* sl = Blg + nB * 64 + k0 / 2 + hB;
            *reinterpret_cast<uint4*>(&Bh[nB][hB])     = *reinterpret_cast<const uint4*>(sh);
            *reinterpret_cast<uint4*>(&Bh[nB][hB + 4]) = *reinterpret_cast<const uint4*>(sh + 4);
            *reinterpret_cast<uint4*>(&Bl[nB][hB])     = *reinterpret_cast<const uint4*>(sl);
            *reinterpret_cast<uint4*>(&Bl[nB][hB + 4]) = *reinterpret_cast<const uint4*>(sl + 4);
        }
        __syncthreads();
        bf_chunk(Ah, Al, Bh, Bl, acc, lane, m0w, n0w);
        __syncthreads();
    }
    const int gr = lane >> 2, tg = lane & 3;
#pragma unroll
    for (int ms = 0; ms < 2; ms++) {
#pragma unroll
        for (int hf = 0; hf < 2; hf++) {
            int dn = sDst[m0w + ms * 16 + gr + hf * 8];
#pragma unroll
            for (int ns = 0; ns < 8; ns++) {
                float v0 = acc[ms][ns][hf * 2];
                float v1 = acc[ms][ns][hf * 2 + 1];
                float p0 = __shfl_xor_sync(0xffffffffu, v0, 1);
                float p1 = __shfl_xor_sync(0xffffffffu, v1, 1);
                if (((tg & 1) == 0) && dn >= 0)
                    red_add_v4(g_kg + (size_t)dn * DIM + n0w + ns * 8 + 2 * tg, v0, v1, p0, p1);
            }
        }
    }
}

// ------------- fused S/K hyperedge accumulation: acc[he] += kg[node] -------------
__global__ void k_scatter_acc2(const int* __restrict__ snod, const int* __restrict__ sedg,
                               const int* __restrict__ knod, const int* __restrict__ kedg) {
    int w = (blockIdx.x * blockDim.x + threadIdx.x) >> 5;
    int lane = threadIdx.x & 31;
    const int* nodes; const int* edges; float* accum;
    if (w < NP) { nodes = snod; edges = sedg; accum = g_accS; }
    else { w -= NP; if (w >= NP) return; nodes = knod; edges = kedg; accum = g_accK; }
    float4 v = *reinterpret_cast<const float4*>(&g_kg[(size_t)nodes[w] * DIM + lane * 4]);
    red_add_v4(accum + (size_t)edges[w] * DIM + lane * 4, v.x, v.y, v.z, v.w);
}

// fused S/K edge-feature GEMMs: ef = (acc @ theta) / b_deg
__global__ void __launch_bounds__(256) k_gemm_ef2() {
    __shared__ unsigned Ah[128][20], Al[128][20], Bh[128][20], Bl[128][20];
    int b = blockIdx.x;
    if (b < EFB) gemm_body(Ah, Al, Bh, Bl, g_accS, 13, nullptr, g_efS, NHYP, g_bdegS, b);
    else gemm_body(Ah, Al, Bh, Bl, g_accK, 14, nullptr, g_efK, NHYP, g_bdegK, b - EFB);
}

// fused S/K node scatter (flag-masked)
__global__ void k_scatter_node2(const int* __restrict__ snod, const int* __restrict__ sedg,
                                const int* __restrict__ knod, const int* __restrict__ kedg) {
    int w = (blockIdx.x * blockDim.x + threadIdx.x) >> 5;
    int lane = threadIdx.x & 31;
    const int* nodes; const int* edges; const int* flag; const float* ef; float* no;
    if (w < NP) { nodes = snod; edges = sedg; flag = g_flagS; ef = g_efS; no = g_noS; }
    else { w -= NP; if (w >= NP) return; nodes = knod; edges = kedg; flag = g_flagK; ef = g_efK; no = g_noK; }
    int n = nodes[w];
    if (!flag[n]) return;
    float4 v = *reinterpret_cast<const float4*>(ef + (size_t)edges[w] * DIM + lane * 4);
    red_add_v4(no + (size_t)n * DIM + lane * 4, v.x, v.y, v.z, v.w);
}

// fused gathers: related + context
__global__ void k_gather(const int* __restrict__ sidx, const int* __restrict__ kidx,
                         const float* __restrict__ biasS, const float* __restrict__ biasK,
                         const int* __restrict__ cidx) {
    int i = blockIdx.x * blockDim.x + threadIdx.x;
    if (i < NB * LKV * DIM) {
        int d = i & 127, l = (i >> 7) & 127, b = i >> 14;
        float v;
        if (l < LREL) {
            int n = sidx[b * LREL + l]; int dd = g_ddegS[n];
            v = g_noS[(size_t)n * DIM + d] * (dd > 0 ? 1.f / dd : 0.f) + biasS[d];
        } else {
            int n = kidx[b * LREL + l - LREL]; int dd = g_ddegK[n];
            v = g_noK[(size_t)n * DIM + d] * (dd > 0 ? 1.f / dd : 0.f) + biasK[d];
        }
        g_related[i] = v;
        return;
    }
    int j = i - NB * LKV * DIM;
    if (j < NB * LCTX * DIM)
        g_context[j] = g_kg[(size_t)cidx[j >> 7] * DIM + (j & 127)];
}

// fused Q/K/V projections
__global__ void __launch_bounds__(256) k_qkv(const float* __restrict__ ipb) {
    __shared__ unsigned Ah[128][20], Al[128][20], Bh[128][20], Bl[128][20];
    int b = blockIdx.x;
    if (b < 16) gemm_body(Ah, Al, Bh, Bl, g_context, 15, ipb, g_qh, NB * LCTX, nullptr, b);
    else if (b < 80) gemm_body(Ah, Al, Bh, Bl, g_related, 16, ipb + DIM, g_kh, NB * LKV, nullptr, b - 16);
    else gemm_body(Ah, Al, Bh, Bl, g_related, 17, ipb + 2 * DIM, g_vh, NB * LKV, nullptr, b - 80);
}

// ---------------- attention ----------------
__global__ void k_mha() {
    int b = blockIdx.x / NHEAD, h = blockIdx.x % NHEAD;
    __shared__ float ks[LKV][HDIM], vs[LKV][HDIM];
    int t = threadIdx.x;
    for (int i = t; i < LKV * HDIM; i += 32) {
        int k = i / HDIM, d = i % HDIM;
        size_t off = ((size_t)b * LKV + k) * DIM + h * HDIM + d;
        ks[k][d] = g_kh[off]; vs[k][d] = g_vh[off];
    }
    __syncwarp();
    float q[HDIM];
    size_t qoff = ((size_t)b * LCTX + t) * DIM + h * HDIM;
#pragma unroll
    for (int d = 0; d < HDIM; d++) q[d] = g_qh[qoff + d];
    float lg[LKV], mx = -1e30f;
    for (int k = 0; k < LKV; k++) {
        float s = 0.f;
#pragma unroll
        for (int d = 0; d < HDIM; d++) s += q[d] * ks[k][d];
        s *= 0.25f; lg[k] = s; mx = fmaxf(mx, s);
    }
    float sum = 0.f;
    for (int k = 0; k < LKV; k++) { lg[k] = expf(lg[k] - mx); sum += lg[k]; }
    float inv = 1.f / sum;
    float acc[HDIM];
#pragma unroll
    for (int d = 0; d < HDIM; d++) acc[d] = 0.f;
    for (int k = 0; k < LKV; k++) {
        float w = lg[k];
#pragma unroll
        for (int d = 0; d < HDIM; d++) acc[d] += w * vs[k][d];
    }
#pragma unroll
    for (int d = 0; d < HDIM; d++) g_o[qoff + d] = acc[d] * inv;
}

__global__ void k_selfattn(const float* __restrict__ h, const float* __restrict__ t1,
                           const float* __restrict__ bvec, float* __restrict__ out, int L) {
    int b = blockIdx.x, t = threadIdx.x;
    __shared__ float w[40];
    if (t < L) {
        float e = 0.f;
        const float* tp = t1 + ((size_t)b * L + t) * DIM;
        for (int d = 0; d < DIM; d++) e += tanhf(tp[d]) * bvec[d];
        w[t] = e;
    }
    __syncthreads();
    float mx = -1e30f;
    for (int l = 0; l < L; l++) mx = fmaxf(mx, w[l]);
    float sum = 0.f;
    for (int l = 0; l < L; l++) sum += expf(w[l] - mx);
    float inv = 1.f / sum, acc = 0.f;
    for (int l = 0; l < L; l++) acc += expf(w[l] - mx) * h[((size_t)b * L + l) * DIM + t];
    out[(size_t)b * DIM + t] = acc * inv;
}

__global__ void k_ucat() {
    int i = blockIdx.x * blockDim.x + threadIdx.x;
    if (i >= NB * 33 * DIM) return;
    int d = i & 127, l = (i >> 7) % 33, b = i / (33 * DIM);
    g_ucat[i] = (l < 32) ? g_context[((size_t)b * 32 + l) * DIM + d] : g_his[(size_t)b * DIM + d];
}

// ------------- scores via tensor cores: out[u, n] = kg[n] . user[u] + rb[n] -------------
__global__ void __launch_bounds__(128) k_scores_mma(const float* __restrict__ rb,
                                                    float* __restrict__ out) {
    __shared__ unsigned Ah[128][20], Al[128][20], Bh[64][20], Bl[64][20];
    const int t = threadIdx.x, lane = t & 31, warp = t >> 5;
    const int m0w = warp * 32;
    const int blkM = blockIdx.x * 128;
    const unsigned* Bhg = g_Bh + 21 * MATW;
    const unsigned* Blg = g_Bl + 21 * MATW;
    float acc[2][8][4];
#pragma unroll
    for (int i = 0; i < 2; i++)
#pragma unroll
        for (int j = 0; j < 8; j++)
#pragma unroll
            for (int q = 0; q < 4; q++) acc[i][j][q] = 0.f;

    for (int k0 = 0; k0 < 128; k0 += 32) {
        int gm = blkM + t;
        if (gm < NN) {
            const float4* ap = reinterpret_cast<const float4*>(g_kg + (size_t)gm * DIM + k0);
            conv_store_row(ap, 1.0f, &Ah[t][0], &Al[t][0]);
            conv_store_row(ap + 4, 1.0f, &Ah[t][8], &Al[t][8]);
        } else {
            uint4 z = make_uint4(0, 0, 0, 0);
#pragma unroll
            for (int q = 0; q < 4; q++) {
                *reinterpret_cast<uint4*>(&Ah[t][4 * q]) = z;
                *reinterpret_cast<uint4*>(&Al[t][4 * q]) = z;
            }
        }
        {
            int nB = t & 63, hB = (t >> 6) * 8;
            const unsigned* sh = Bhg + nB * 64 + k0 / 2 + hB;
            const unsigned* sl = Blg + nB * 64 + k0 / 2 + hB;
            *reinterpret_cast<uint4*>(&Bh[nB][hB])     = *reinterpret_cast<const uint4*>(sh);
            *reinterpret_cast<uint4*>(&Bh[nB][hB + 4]) = *reinterpret_cast<const uint4*>(sh + 4);
            *reinterpret_cast<uint4*>(&Bl[nB][hB])     = *reinterpret_cast<const uint4*>(sl);
            *reinterpret_cast<uint4*>(&Bl[nB][hB + 4]) = *reinterpret_cast<const uint4*>(sl + 4);
        }
        __syncthreads();
        bf_chunk(Ah, Al, Bh, Bl, acc, lane, m0w, 0);
        __syncthreads();
    }
    const int gr = lane >> 2, tg = lane & 3;
#pragma unroll
    for (int ms = 0; ms < 2; ms++) {
#pragma unroll
        for (int hf = 0; hf < 2; hf++) {
            int gm = blkM + m0w + ms * 16 + gr + hf * 8;
            if (gm < NN) {
                float rv = rb[gm];
#pragma unroll
                for (int ns = 0; ns < 8; ns++) {
                    int col = ns * 8 + 2 * tg;
                    out[(size_t)col * NN + gm]       = acc[ms][ns][hf * 2] + rv;
                    out[(size_t)(col + 1) * NN + gm] = acc[ms][ns][hf * 2 + 1] + rv;
                }
            }
        }
    }
}

// ---------------- host ----------------
static void* sym(const void* s) { void* p = nullptr; cudaGetSymbolAddress(&p, s); return p; }

extern "C" void kernel_launch(void* const* d_in, const int* in_sizes, int n_in,
                              void* d_out, int out_size) {
    const float* emb   = (const float*)d_in[0];
    const float* bases = (const float*)d_in[1];
    const float* comp  = (const float*)d_in[2];
    const float* root  = (const float*)d_in[3];
    const float* rbias = (const float*)d_in[4];
    const float* sth   = (const float*)d_in[5];
    const float* sbi   = (const float*)d_in[6];
    const float* kth   = (const float*)d_in[7];
    const float* kbi   = (const float*)d_in[8];
    const float* ipw   = (const float*)d_in[9];
    const float* ipb   = (const float*)d_in[10];
    const float* opw   = (const float*)d_in[11];
    const float* opb   = (const float*)d_in[12];
    const float* aha   = (const float*)d_in[13];
    const float* ahb   = (const float*)d_in[14];
    const float* aa    = (const float*)d_in[15];
    const float* ab    = (const float*)d_in[16];
    const float* recb  = (const float*)d_in[17];
    const int* esrc = (const int*)d_in[18];
    const int* edst = (const int*)d_in[19];
    const int* ety  = (const int*)d_in[20];
    const int* snod = (const int*)d_in[21];
    const int* sedg = (const int*)d_in[22];
    const int* knod = (const int*)d_in[23];
    const int* kedg = (const int*)d_in[24];
    const int* sri  = (const int*)d_in[25];
    const int* kri  = (const int*)d_in[26];
    const int* cxi  = (const int*)d_in[27];
    float* out = (float*)d_out;

    cudaMemsetAsync(sym(g_cnt), 0, (size_t)NN * NREL * 4, 0);
    cudaMemsetAsync(sym(g_typeCnt), 0, NREL * 4, 0);
    cudaMemsetAsync(sym(g_bdegS), 0, NHYP * 4, 0);
    cudaMemsetAsync(sym(g_bdegK), 0, NHYP * 4, 0);
    cudaMemsetAsync(sym(g_ddegS), 0, (size_t)NN * 4, 0);
    cudaMemsetAsync(sym(g_ddegK), 0, (size_t)NN * 4, 0);
    cudaMemsetAsync(sym(g_accS), 0, (size_t)NHYP * DIM * 4, 0);
    cudaMemsetAsync(sym(g_accK), 0, (size_t)NHYP * DIM * 4, 0);
    cudaMemsetAsync(sym(g_flagS), 0, (size_t)NN * 4, 0);
    cudaMemsetAsync(sym(g_flagK), 0, (size_t)NN * 4, 0);

    k_W<<<(NREL * DIM * DIM + 255) / 256, 256>>>(bases, comp);
    k_prep<<<(21 * MATW + 255) / 256, 256>>>(root, sth, kth, ipw, opw, aha, aa);

    // F1: root GEMM || edge count || hyper counts || flags
    k_fuse1<<<ROOTB + COUNTB + 2 * HCB + 2 * FLAGB, 256>>>(
        emb, rbias, edst, ety, snod, sedg, knod, kedg, sri, kri);
    k_prefix<<<1, 1>>>();
    k_sort<<<(NEDGE + 255) / 256, 256>>>(ety);
    k_edge_gemm<<<EDGE_TILES, 256>>>(emb, esrc, edst);

    // hypergraphs (linearity: scatter kg, then small GEMM with 1/b_deg)
    k_scatter_acc2<<<(2 * NP * 32) / 256, 256>>>(snod, sedg, knod, kedg);
    k_gemm_ef2<<<2 * EFB, 256>>>();
    k_scatter_node2<<<(2 * NP * 32) / 256, 256>>>(snod, sedg, knod, kedg);

    k_gather<<<(NB * LKV * DIM + NB * LCTX * DIM + 255) / 256, 256>>>(sri, kri, sbi, kbi, cxi);

    // MHA
    k_qkv<<<144, 256>>>(ipb);
    k_mha<<<NB * NHEAD, 32>>>();
    k_gemm128b<<<16, 256>>>((float*)sym(g_o), 18, opb, (float*)sym(g_attrel), NB * LCTX);

    // his self-attn
    k_gemm128b<<<16, 256>>>((float*)sym(g_attrel), 19, nullptr, (float*)sym(g_t1), NB * LCTX);
    k_selfattn<<<NB, 128>>>((float*)sym(g_attrel), (float*)sym(g_t1), ahb,
                            (float*)sym(g_his), LCTX);

    // user self-attn over [context, his]
    k_ucat<<<(NB * 33 * DIM + 255) / 256, 256>>>();
    k_gemm128b<<<17, 256>>>((float*)sym(g_ucat), 20, nullptr, (float*)sym(g_t2), NB * 33);
    k_selfattn<<<NB, 128>>>((float*)sym(g_ucat), (float*)sym(g_t2), ab,
                            (float*)sym(g_user), 33);

    // scores on tensor cores
    k_packU<<<(MATW + 255) / 256, 256>>>();
    k_scores_mma<<<(NN + 127) / 128, 128>>>(recb, out);
}

// round 9
// speedup vs baseline: 1.6569x; 1.1061x over previous
#include <cuda_runtime.h>
#include <cuda_bf16.h>
#include <math.h>

#define NN 100000
#define DIM 128
#define NREL 12
#define NBASES 8
#define NEDGE 1000000
#define NP 400000
#define NHYP 20000
#define NB 64
#define LREL 64
#define LKV 128
#define LCTX 32
#define NHEAD 8
#define HDIM 16
#define EDGE_TILES 7830
#define NMAT 22
#define MATW 8192   // 128 rows x 64 packed words per matrix

#define ROOTB 782
#define COUNTB 3907
#define HCB 1563
#define FLAGB 16
#define PACKB 3125
#define EFB 157

__device__ __forceinline__ void red_add_v4(float* p, float x, float y, float z, float w) {
    asm volatile("red.global.add.v4.f32 [%0], {%1,%2,%3,%4};"
                 :: "l"(p), "f"(x), "f"(y), "f"(z), "f"(w) : "memory");
}

// split two fp32 into packed bf16x2 hi word + lo word
__device__ __forceinline__ unsigned pack_split(float x0, float x1, unsigned& lo) {
    __nv_bfloat16 h0 = __float2bfloat16(x0), h1 = __float2bfloat16(x1);
    float r0 = x0 - __bfloat162float(h0), r1 = x1 - __bfloat162float(h1);
    __nv_bfloat16 l0 = __float2bfloat16(r0), l1 = __float2bfloat16(r1);
    lo = (unsigned)__bfloat16_as_ushort(l0) | ((unsigned)__bfloat16_as_ushort(l1) << 16);
    return (unsigned)__bfloat16_as_ushort(h0) | ((unsigned)__bfloat16_as_ushort(h1) << 16);
}

__device__ __forceinline__ void mma16(float* c, const unsigned* a, const unsigned* b) {
    asm("mma.sync.aligned.m16n8k16.row.col.f32.bf16.bf16.f32 "
        "{%0,%1,%2,%3}, {%4,%5,%6,%7}, {%8,%9}, {%0,%1,%2,%3};"
        : "+f"(c[0]), "+f"(c[1]), "+f"(c[2]), "+f"(c[3])
        : "r"(a[0]), "r"(a[1]), "r"(a[2]), "r"(a[3]), "r"(b[0]), "r"(b[1]));
}

// ---------------- device scratch ----------------
__device__ float    g_W[NREL * DIM * DIM];
__device__ unsigned g_Bh[NMAT * MATW];
__device__ unsigned g_Bl[NMAT * MATW];
__device__ unsigned g_Xh[NN * 64];
__device__ unsigned g_Xl[NN * 64];
__device__ float g_kg[NN * DIM];
__device__ int   g_cnt[NN * NREL];
__device__ int   g_typeCnt[NREL];
__device__ int   g_cursor[NREL];
__device__ int   g_sorted[NEDGE];
__device__ int   g_bdegS[NHYP], g_bdegK[NHYP];
__device__ int   g_ddegS[NN], g_ddegK[NN];
__device__ float g_accS[NHYP * DIM], g_accK[NHYP * DIM];
__device__ float g_efS[NHYP * DIM], g_efK[NHYP * DIM];
__device__ int   g_flagS[NN], g_flagK[NN];
__device__ float g_noS[NN * DIM], g_noK[NN * DIM];
__device__ float g_related[NB * LKV * DIM];
__device__ float g_context[NB * LCTX * DIM];
__device__ float g_qh[NB * LCTX * DIM];
__device__ float g_kh[NB * LKV * DIM];
__device__ float g_vh[NB * LKV * DIM];
__device__ float g_o[NB * LCTX * DIM];
__device__ float g_attrel[NB * LCTX * DIM];
__device__ float g_t1[NB * LCTX * DIM];
__device__ float g_ucat[NB * 33 * DIM];
__device__ float g_t2[NB * 33 * DIM];
__device__ float g_his[NB * DIM];
__device__ float g_user[NB * DIM];

// ---------------- prep ----------------
__global__ void k_W(const float* __restrict__ bases, const float* __restrict__ comp) {
    int i = blockIdx.x * blockDim.x + threadIdx.x;
    if (i >= NREL * DIM * DIM) return;
    int r = i / (DIM * DIM), kn = i % (DIM * DIM);
    float s = 0.f;
#pragma unroll
    for (int b = 0; b < NBASES; b++)
        s = fmaf(comp[r * NBASES + b], bases[b * DIM * DIM + kn], s);
    g_W[i] = s;
}

// pack 21 static B-matrices into split bf16x2 [mat][n][k/2] layout
__global__ void k_prep(const float* __restrict__ root, const float* __restrict__ sth,
                       const float* __restrict__ kth, const float* __restrict__ ipw,
                       const float* __restrict__ opw, const float* __restrict__ aha,
                       const float* __restrict__ aa) {
    int idx = blockIdx.x * blockDim.x + threadIdx.x;
    if (idx >= 21 * MATW) return;
    int m = idx >> 13, rem = idx & (MATW - 1), n = rem >> 6, k2 = rem & 63;
    float s0, s1;
    if (m < 12) {
        const float* b = g_W + m * DIM * DIM;
        s0 = b[(2 * k2) * DIM + n]; s1 = b[(2 * k2 + 1) * DIM + n];
    } else {
        const float* b; int tr = 0;
        switch (m) {
            case 12: b = root; break;
            case 13: b = sth; break;
            case 14: b = kth; break;
            case 15: b = ipw; tr = 1; break;
            case 16: b = ipw + DIM * DIM; tr = 1; break;
            case 17: b = ipw + 2 * DIM * DIM; tr = 1; break;
            case 18: b = opw; tr = 1; break;
            case 19: b = aha; break;
            default: b = aa; break;
        }
        if (tr) { s0 = b[n * DIM + 2 * k2]; s1 = b[n * DIM + 2 * k2 + 1]; }
        else    { s0 = b[(2 * k2) * DIM + n]; s1 = b[(2 * k2 + 1) * DIM + n]; }
    }
    unsigned lo, hi = pack_split(s0, s1, lo);
    g_Bh[idx] = hi; g_Bl[idx] = lo;
}

__global__ void k_packU() {
    int idx = blockIdx.x * blockDim.x + threadIdx.x;
    if (idx >= MATW) return;
    int n = idx >> 6, k2 = idx & 63;
    float s0 = 0.f, s1 = 0.f;
    if (n < NB) { s0 = g_user[n * DIM + 2 * k2]; s1 = g_user[n * DIM + 2 * k2 + 1]; }
    unsigned lo, hi = pack_split(s0, s1, lo);
    g_Bh[21 * MATW + idx] = hi; g_Bl[21 * MATW + idx] = lo;
}

// counting sort with block aggregation; per-block prefix from g_typeCnt
__global__ void k_sort(const int* __restrict__ ty) {
    __shared__ int h[NREL], base[NREL];
    int t = threadIdx.x;
    if (t < NREL) h[t] = 0;
    __syncthreads();
    int e = blockIdx.x * blockDim.x + t;
    int tt = -1, loc = 0;
    if (e < NEDGE) { tt = ty[e]; loc = atomicAdd(&h[tt], 1); }
    __syncthreads();
    if (t < NREL) {
        int off = 0;
        for (int i = 0; i < t; i++) off += g_typeCnt[i];
        base[t] = off + (h[t] ? atomicAdd(&g_cursor[t], h[t]) : 0);
    }
    __syncthreads();
    if (e < NEDGE) g_sorted[base[tt] + loc] = e;
}

// bf16x2 3-term compute over one K32 chunk
__device__ __forceinline__ void bf_chunk(
    const unsigned (*Ah)[20], const unsigned (*Al)[20],
    const unsigned (*Bh)[20], const unsigned (*Bl)[20],
    float acc[2][8][4], int lane, int m0, int n0) {
    const int gr = lane >> 2, tg = lane & 3;
#pragma unroll
    for (int s = 0; s < 2; s++) {
        const int kb = s * 8;
        unsigned bh[8][2], bl[8][2];
#pragma unroll
        for (int ns = 0; ns < 8; ns++) {
            int n = n0 + ns * 8 + gr;
            bh[ns][0] = Bh[n][kb + tg]; bh[ns][1] = Bh[n][kb + tg + 4];
            bl[ns][0] = Bl[n][kb + tg]; bl[ns][1] = Bl[n][kb + tg + 4];
        }
#pragma unroll
        for (int ms = 0; ms < 2; ms++) {
            int r = m0 + ms * 16 + gr;
            unsigned ah[4], al[4];
            ah[0] = Ah[r][kb+tg];   ah[1] = Ah[r+8][kb+tg];
            ah[2] = Ah[r][kb+tg+4]; ah[3] = Ah[r+8][kb+tg+4];
            al[0] = Al[r][kb+tg];   al[1] = Al[r+8][kb+tg];
            al[2] = Al[r][kb+tg+4]; al[3] = Al[r+8][kb+tg+4];
#pragma unroll
            for (int ns = 0; ns < 8; ns++) {
                mma16(acc[ms][ns], ah, bh[ns]);
                mma16(acc[ms][ns], ah, bl[ns]);
                mma16(acc[ms][ns], al, bh[ns]);
            }
        }
    }
}

// convert 16 fp32 (scaled) -> 8 hi + 8 lo packed words
__device__ __forceinline__ void conv_store_row(const float4* ap, float scale,
                                               unsigned* dh, unsigned* dl) {
    unsigned hw[8], lw[8];
#pragma unroll
    for (int q = 0; q < 4; q++) {
        float4 v = ap[q];
        v.x *= scale; v.y *= scale; v.z *= scale; v.w *= scale;
        hw[2*q]   = pack_split(v.x, v.y, lw[2*q]);
        hw[2*q+1] = pack_split(v.z, v.w, lw[2*q+1]);
    }
    *reinterpret_cast<uint4*>(dh)     = make_uint4(hw[0], hw[1], hw[2], hw[3]);
    *reinterpret_cast<uint4*>(dh + 4) = make_uint4(hw[4], hw[5], hw[6], hw[7]);
    *reinterpret_cast<uint4*>(dl)     = make_uint4(lw[0], lw[1], lw[2], lw[3]);
    *reinterpret_cast<uint4*>(dl + 4) = make_uint4(lw[4], lw[5], lw[6], lw[7]);
}

// ------------- generic GEMM body: C[M,128] = A[M,128] @ B(mat) (+bias, row scale 1/deg) ----
__device__ __forceinline__ void gemm_body(
    unsigned (*Ah)[20], unsigned (*Al)[20], unsigned (*Bh)[20], unsigned (*Bl)[20],
    const float* __restrict__ A, int mat, const float* __restrict__ bias,
    float* __restrict__ C, int M, const int* __restrict__ rowdeg, int blk) {
    const int t = threadIdx.x, lane = t & 31, warp = t >> 5;
    const int m0w = (warp & 3) * 32, n0w = (warp >> 2) * 64;
    const int blkM = blk * 128;
    const unsigned* Bhg = g_Bh + mat * MATW;
    const unsigned* Blg = g_Bl + mat * MATW;
    float acc[2][8][4];
#pragma unroll
    for (int i = 0; i < 2; i++)
#pragma unroll
        for (int j = 0; j < 8; j++)
#pragma unroll
            for (int q = 0; q < 4; q++) acc[i][j][q] = 0.f;
    const int mA = t >> 1, half = t & 1;
    const int nB = t >> 1, hB = (t & 1) * 8;

    for (int k0 = 0; k0 < 128; k0 += 32) {
        int gm = blkM + mA;
        if (gm < M) {
            const float4* ap = reinterpret_cast<const float4*>(A + (size_t)gm * DIM + k0 + half * 16);
            conv_store_row(ap, 1.0f, &Ah[mA][half * 8], &Al[mA][half * 8]);
        } else {
            uint4 z = make_uint4(0, 0, 0, 0);
            *reinterpret_cast<uint4*>(&Ah[mA][half*8]) = z;
            *reinterpret_cast<uint4*>(&Ah[mA][half*8+4]) = z;
            *reinterpret_cast<uint4*>(&Al[mA][half*8]) = z;
            *reinterpret_cast<uint4*>(&Al[mA][half*8+4]) = z;
        }
        {
            const unsigned* sh = Bhg + nB * 64 + k0 / 2 + hB;
            const unsigned* sl = Blg + nB * 64 + k0 / 2 + hB;
            *reinterpret_cast<uint4*>(&Bh[nB][hB])     = *reinterpret_cast<const uint4*>(sh);
            *reinterpret_cast<uint4*>(&Bh[nB][hB + 4]) = *reinterpret_cast<const uint4*>(sh + 4);
            *reinterpret_cast<uint4*>(&Bl[nB][hB])     = *reinterpret_cast<const uint4*>(sl);
            *reinterpret_cast<uint4*>(&Bl[nB][hB + 4]) = *reinterpret_cast<const uint4*>(sl + 4);
        }
        __syncthreads();
        bf_chunk(Ah, Al, Bh, Bl, acc, lane, m0w, n0w);
        __syncthreads();
    }
    const int gr = lane >> 2, tg = lane & 3;
#pragma unroll
    for (int ms = 0; ms < 2; ms++) {
#pragma unroll
        for (int hf = 0; hf < 2; hf++) {
            int gm = blkM + m0w + ms * 16 + gr + hf * 8;
            if (gm < M) {
                float scale = 1.f;
                if (rowdeg) { int dg = rowdeg[gm]; scale = dg > 0 ? 1.f / (float)dg : 0.f; }
                float* cp = C + (size_t)gm * DIM;
#pragma unroll
                for (int ns = 0; ns < 8; ns++) {
                    int col = n0w + ns * 8 + 2 * tg;
                    float b0 = bias ? bias[col] : 0.f;
                    float b1 = bias ? bias[col + 1] : 0.f;
                    float2 v = make_float2(acc[ms][ns][hf * 2] * scale + b0,
                                           acc[ms][ns][hf * 2 + 1] * scale + b1);
                    *reinterpret_cast<float2*>(cp + col) = v;
                }
            }
        }
    }
}

__global__ void __launch_bounds__(256) k_gemm128b(
    const float* __restrict__ A, int mat, const float* __restrict__ bias,
    float* __restrict__ C, int M) {
    __shared__ unsigned Ah[128][20], Al[128][20], Bh[128][20], Bl[128][20];
    gemm_body(Ah, Al, Bh, Bl, A, mat, bias, C, M, nullptr, blockIdx.x);
}

// ------------- F1: root GEMM || edge count || hyper counts || flags || pack X -------------
__global__ void __launch_bounds__(256) k_fuse1(
    const float* __restrict__ emb, const float* __restrict__ rbias,
    const int* __restrict__ edst, const int* __restrict__ ety,
    const int* __restrict__ snod, const int* __restrict__ sedg,
    const int* __restrict__ knod, const int* __restrict__ kedg,
    const int* __restrict__ sri, const int* __restrict__ kri) {
    __shared__ unsigned Ah[128][20], Al[128][20], Bh[128][20], Bl[128][20];
    __shared__ int fh[NREL];
    int b = blockIdx.x;
    int t = threadIdx.x;
    if (b < ROOTB) {
        gemm_body(Ah, Al, Bh, Bl, emb, 12, rbias, g_kg, NN, nullptr, b);
        return;
    }
    b -= ROOTB;
    if (b < COUNTB) {
        if (t < NREL) fh[t] = 0;
        __syncthreads();
        int e = b * 256 + t;
        if (e < NEDGE) {
            int tt = ety[e];
            atomicAdd(&g_cnt[edst[e] * NREL + tt], 1);
            atomicAdd(&fh[tt], 1);
        }
        __syncthreads();
        if (t < NREL && fh[t]) atomicAdd(&g_typeCnt[t], fh[t]);
        return;
    }
    b -= COUNTB;
    if (b < 2 * HCB) {
        const int* nodes; const int* edges; int* bdeg; int* ddeg;
        int lb = b;
        if (lb < HCB) { nodes = snod; edges = sedg; bdeg = g_bdegS; ddeg = g_ddegS; }
        else { lb -= HCB; nodes = knod; edges = kedg; bdeg = g_bdegK; ddeg = g_ddegK; }
        int p = lb * 256 + t;
        if (p < NP) {
            atomicAdd(&bdeg[edges[p]], 1);
            atomicAdd(&ddeg[nodes[p]], 1);
        }
        return;
    }
    b -= 2 * HCB;
    if (b < 2 * FLAGB) {
        const int* idx; int* flag; float* no;
        int lb = b;
        if (lb < FLAGB) { idx = sri; flag = g_flagS; no = g_noS; }
        else { lb -= FLAGB; idx = kri; flag = g_flagK; no = g_noK; }
        int i = lb * 256 + t;
        if (i < NB * LREL) {
            int n = idx[i];
            flag[n] = 1;
            float* p = no + (size_t)n * DIM;
            for (int d = 0; d < DIM; d++) p[d] = 0.f;
        }
        return;
    }
    b -= 2 * FLAGB;
    {
        int i = b * 256 + t;
        if (i < NN * 8) {
            int n = i >> 3, part = i & 7;
            const float4* ap = reinterpret_cast<const float4*>(emb + (size_t)n * DIM + part * 16);
            conv_store_row(ap, 1.0f, &g_Xh[(size_t)n * 64 + part * 8],
                           &g_Xl[(size_t)n * 64 + part * 8]);
        }
    }
}

// ------------- RGCN edge GEMM (pre-packed A): kg[dst] += norm * x[src] @ W[type] -------------
__global__ void __launch_bounds__(256) k_edge_gemm(
    const int* __restrict__ esrc, const int* __restrict__ edst) {
    __shared__ unsigned Ah[128][20], Al[128][20], Bh[128][20], Bl[128][20];
    __shared__ int   sSrc[128], sDst[128];
    __shared__ float sNorm[128];
    const int bid = blockIdx.x;
    // local prefix over g_typeCnt
    int r = -1, base = 0, cnt = 0;
    {
        int off = 0, toff = 0;
#pragma unroll
        for (int i = 0; i < NREL; i++) {
            int c = g_typeCnt[i];
            int nt = (c + 127) >> 7;
            if (r < 0 && bid < toff + nt) {
                int local = bid - toff;
                r = i; base = off + local * 128;
                cnt = c - local * 128; if (cnt > 128) cnt = 128;
            }
            off += c; toff += nt;
        }
    }
    if (r < 0) return;
    const int t = threadIdx.x, lane = t & 31, warp = t >> 5;
    const int m0w = (warp & 3) * 32, n0w = (warp >> 2) * 64;
    if (t < 128) {
        if (t < cnt) {
            int e = g_sorted[base + t];
            int d = edst[e];
            sSrc[t] = esrc[e]; sDst[t] = d;
            sNorm[t] = 1.0f / fmaxf((float)g_cnt[d * NREL + r], 1.0f);
        } else { sSrc[t] = 0; sDst[t] = -1; sNorm[t] = 0.f; }
    }
    __syncthreads();
    float acc[2][8][4];
#pragma unroll
    for (int i = 0; i < 2; i++)
#pragma unroll
        for (int j = 0; j < 8; j++)
#pragma unroll
            for (int q = 0; q < 4; q++) acc[i][j][q] = 0.f;
    const int mA = t >> 1, half = t & 1;
    const int nB = t >> 1, hB = (t & 1) * 8;
    const unsigned* Bhg = g_Bh + r * MATW;
    const unsigned* Blg = g_Bl + r * MATW;

    for (int k0 = 0; k0 < 128; k0 += 32) {
        {
            size_t xoff = (size_t)sSrc[mA] * 64 + k0 / 2 + half * 8;
            const unsigned* xh = g_Xh + xoff;
            const unsigned* xl = g_Xl + xoff;
            *reinterpret_cast<uint4*>(&Ah[mA][half*8])     = *reinterpret_cast<const uint4*>(xh);
            *reinterpret_cast<uint4*>(&Ah[mA][half*8 + 4]) = *reinterpret_cast<const uint4*>(xh + 4);
            *reinterpret_cast<uint4*>(&Al[mA][half*8])     = *reinterpret_cast<const uint4*>(xl);
            *reinterpret_cast<uint4*>(&Al[mA][half*8 + 4]) = *reinterpret_cast<const uint4*>(xl + 4);
        }
        {
            const unsigned* sh = Bhg + nB * 64 + k0 / 2 + hB;
            const unsigned* sl = Blg + nB * 64 + k0 / 2 + hB;
            *reinterpret_cast<uint4*>(&Bh[nB][hB])     = *reinterpret_cast<const uint4*>(sh);
            *reinterpret_cast<uint4*>(&Bh[nB][hB + 4]) = *reinterpret_cast<const uint4*>(sh + 4);
            *reinterpret_cast<uint4*>(&Bl[nB][hB])     = *reinterpret_cast<const uint4*>(sl);
            *reinterpret_cast<uint4*>(&Bl[nB][hB + 4]) = *reinterpret_cast<const uint4*>(sl + 4);
        }
        __syncthreads();
        bf_chunk(Ah, Al, Bh, Bl, acc, lane, m0w, n0w);
        __syncthreads();
    }
    const int gr = lane >> 2, tg = lane & 3;
#pragma unroll
    for (int ms = 0; ms < 2; ms++) {
#pragma unroll
        for (int hf = 0; hf < 2; hf++) {
            int rr = m0w + ms * 16 + gr + hf * 8;
            int dn = sDst[rr];
            float nrm = sNorm[rr];
#pragma unroll
            for (int ns = 0; ns < 8; ns++) {
                float v0 = acc[ms][ns][hf * 2] * nrm;
                float v1 = acc[ms][ns][hf * 2 + 1] * nrm;
                float p0 = __shfl_xor_sync(0xffffffffu, v0, 1);
                float p1 = __shfl_xor_sync(0xffffffffu, v1, 1);
                if (((tg & 1) == 0) && dn >= 0)
                    red_add_v4(g_kg + (size_t)dn * DIM + n0w + ns * 8 + 2 * tg, v0, v1, p0, p1);
            }
        }
    }
}

// ------------- fused S/K hyperedge accumulation: acc[he] += kg[node] -------------
__global__ void k_scatter_acc2(const int* __restrict__ snod, const int* __restrict__ sedg,
                               const int* __restrict__ knod, const int* __restrict__ kedg) {
    int w = (blockIdx.x * blockDim.x + threadIdx.x) >> 5;
    int lane = threadIdx.x & 31;
    const int* nodes; const int* edges; float* accum;
    if (w < NP) { nodes = snod; edges = sedg; accum = g_accS; }
    else { w -= NP; if (w >= NP) return; nodes = knod; edges = kedg; accum = g_accK; }
    float4 v = *reinterpret_cast<const float4*>(&g_kg[(size_t)nodes[w] * DIM + lane * 4]);
    red_add_v4(accum + (size_t)edges[w] * DIM + lane * 4, v.x, v.y, v.z, v.w);
}

// fused S/K edge-feature GEMMs: ef = (acc @ theta) / b_deg
__global__ void __launch_bounds__(256) k_gemm_ef2() {
    __shared__ unsigned Ah[128][20], Al[128][20], Bh[128][20], Bl[128][20];
    int b = blockIdx.x;
    if (b < EFB) gemm_body(Ah, Al, Bh, Bl, g_accS, 13, nullptr, g_efS, NHYP, g_bdegS, b);
    else gemm_body(Ah, Al, Bh, Bl, g_accK, 14, nullptr, g_efK, NHYP, g_bdegK, b - EFB);
}

// fused S/K node scatter (flag-masked)
__global__ void k_scatter_node2(const int* __restrict__ snod, const int* __restrict__ sedg,
                                const int* __restrict__ knod, const int* __restrict__ kedg) {
    int w = (blockIdx.x * blockDim.x + threadIdx.x) >> 5;
    int lane = threadIdx.x & 31;
    const int* nodes; const int* edges; const int* flag; const float* ef; float* no;
    if (w < NP) { nodes = snod; edges = sedg; flag = g_flagS; ef = g_efS; no = g_noS; }
    else { w -= NP; if (w >= NP) return; nodes = knod; edges = kedg; flag = g_flagK; ef = g_efK; no = g_noK; }
    int n = nodes[w];
    if (!flag[n]) return;
    float4 v = *reinterpret_cast<const float4*>(ef + (size_t)edges[w] * DIM + lane * 4);
    red_add_v4(no + (size_t)n * DIM + lane * 4, v.x, v.y, v.z, v.w);
}

// fused gathers: related + context
__global__ void k_gather(const int* __restrict__ sidx, const int* __restrict__ kidx,
                         const float* __restrict__ biasS, const float* __restrict__ biasK,
                         const int* __restrict__ cidx) {
    int i = blockIdx.x * blockDim.x + threadIdx.x;
    if (i < NB * LKV * DIM) {
        int d = i & 127, l = (i >> 7) & 127, b = i >> 14;
        float v;
        if (l < LREL) {
            int n = sidx[b * LREL + l]; int dd = g_ddegS[n];
            v = g_noS[(size_t)n * DIM + d] * (dd > 0 ? 1.f / dd : 0.f) + biasS[d];
        } else {
            int n = kidx[b * LREL + l - LREL]; int dd = g_ddegK[n];
            v = g_noK[(size_t)n * DIM + d] * (dd > 0 ? 1.f / dd : 0.f) + biasK[d];
        }
        g_related[i] = v;
        return;
    }
    int j = i - NB * LKV * DIM;
    if (j < NB * LCTX * DIM)
        g_context[j] = g_kg[(size_t)cidx[j >> 7] * DIM + (j & 127)];
}

// fused Q/K/V projections
__global__ void __launch_bounds__(256) k_qkv(const float* __restrict__ ipb) {
    __shared__ unsigned Ah[128][20], Al[128][20], Bh[128][20], Bl[128][20];
    int b = blockIdx.x;
    if (b < 16) gemm_body(Ah, Al, Bh, Bl, g_context, 15, ipb, g_qh, NB * LCTX, nullptr, b);
    else if (b < 80) gemm_body(Ah, Al, Bh, Bl, g_related, 16, ipb + DIM, g_kh, NB * LKV, nullptr, b - 16);
    else gemm_body(Ah, Al, Bh, Bl, g_related, 17, ipb + 2 * DIM, g_vh, NB * LKV, nullptr, b - 80);
}

// ---------------- attention ----------------
__global__ void k_mha() {
    int b = blockIdx.x / NHEAD, h = blockIdx.x % NHEAD;
    __shared__ float ks[LKV][HDIM], vs[LKV][HDIM];
    int t = threadIdx.x;
    for (int i = t; i < LKV * HDIM; i += 32) {
        int k = i / HDIM, d = i % HDIM;
        size_t off = ((size_t)b * LKV + k) * DIM + h * HDIM + d;
        ks[k][d] = g_kh[off]; vs[k][d] = g_vh[off];
    }
    __syncwarp();
    float q[HDIM];
    size_t qoff = ((size_t)b * LCTX + t) * DIM + h * HDIM;
#pragma unroll
    for (int d = 0; d < HDIM; d++) q[d] = g_qh[qoff + d];
    float lg[LKV], mx = -1e30f;
    for (int k = 0; k < LKV; k++) {
        float s = 0.f;
#pragma unroll
        for (int d = 0; d < HDIM; d++) s += q[d] * ks[k][d];
        s *= 0.25f; lg[k] = s; mx = fmaxf(mx, s);
    }
    float sum = 0.f;
    for (int k = 0; k < LKV; k++) { lg[k] = expf(lg[k] - mx); sum += lg[k]; }
    float inv = 1.f / sum;
    float acc[HDIM];
#pragma unroll
    for (int d = 0; d < HDIM; d++) acc[d] = 0.f;
    for (int k = 0; k < LKV; k++) {
        float w = lg[k];
#pragma unroll
        for (int d = 0; d < HDIM; d++) acc[d] += w * vs[k][d];
    }
#pragma unroll
    for (int d = 0; d < HDIM; d++) g_o[qoff + d] = acc[d] * inv;
}

__global__ void k_selfattn(const float* __restrict__ h, const float* __restrict__ t1,
                           const float* __restrict__ bvec, float* __restrict__ out, int L) {
    int b = blockIdx.x, t = threadIdx.x;
    __shared__ float w[40];
    if (t < L) {
        float e = 0.f;
        const float* tp = t1 + ((size_t)b * L + t) * DIM;
        for (int d = 0; d < DIM; d++) e += tanhf(tp[d]) * bvec[d];
        w[t] = e;
    }
    __syncthreads();
    float mx = -1e30f;
    for (int l = 0; l < L; l++) mx = fmaxf(mx, w[l]);
    float sum = 0.f;
    for (int l = 0; l < L; l++) sum += expf(w[l] - mx);
    float inv = 1.f / sum, acc = 0.f;
    for (int l = 0; l < L; l++) acc += expf(w[l] - mx) * h[((size_t)b * L + l) * DIM + t];
    out[(size_t)b * DIM + t] = acc * inv;
}

__global__ void k_ucat() {
    int i = blockIdx.x * blockDim.x + threadIdx.x;
    if (i >= NB * 33 * DIM) return;
    int d = i & 127, l = (i >> 7) % 33, b = i / (33 * DIM);
    g_ucat[i] = (l < 32) ? g_context[((size_t)b * 32 + l) * DIM + d] : g_his[(size_t)b * DIM + d];
}

// ------------- scores via tensor cores: out[u, n] = kg[n] . user[u] + rb[n] -------------
__global__ void __launch_bounds__(128) k_scores_mma(const float* __restrict__ rb,
                                                    float* __restrict__ out) {
    __shared__ unsigned Ah[128][20], Al[128][20], Bh[64][20], Bl[64][20];
    const int t = threadIdx.x, lane = t & 31, warp = t >> 5;
    const int m0w = warp * 32;
    const int blkM = blockIdx.x * 128;
    const unsigned* Bhg = g_Bh + 21 * MATW;
    const unsigned* Blg = g_Bl + 21 * MATW;
    float acc[2][8][4];
#pragma unroll
    for (int i = 0; i < 2; i++)
#pragma unroll
        for (int j = 0; j < 8; j++)
#pragma unroll
            for (int q = 0; q < 4; q++) acc[i][j][q] = 0.f;

    for (int k0 = 0; k0 < 128; k0 += 32) {
        int gm = blkM + t;
        if (gm < NN) {
            const float4* ap = reinterpret_cast<const float4*>(g_kg + (size_t)gm * DIM + k0);
            conv_store_row(ap, 1.0f, &Ah[t][0], &Al[t][0]);
            conv_store_row(ap + 4, 1.0f, &Ah[t][8], &Al[t][8]);
        } else {
            uint4 z = make_uint4(0, 0, 0, 0);
#pragma unroll
            for (int q = 0; q < 4; q++) {
                *reinterpret_cast<uint4*>(&Ah[t][4 * q]) = z;
                *reinterpret_cast<uint4*>(&Al[t][4 * q]) = z;
            }
        }
        {
            int nB = t & 63, hB = (t >> 6) * 8;
            const unsigned* sh = Bhg + nB * 64 + k0 / 2 + hB;
            const unsigned* sl = Blg + nB * 64 + k0 / 2 + hB;
            *reinterpret_cast<uint4*>(&Bh[nB][hB])     = *reinterpret_cast<const uint4*>(sh);
            *reinterpret_cast<uint4*>(&Bh[nB][hB + 4]) = *reinterpret_cast<const uint4*>(sh + 4);
            *reinterpret_cast<uint4*>(&Bl[nB][hB])     = *reinterpret_cast<const uint4*>(sl);
            *reinterpret_cast<uint4*>(&Bl[nB][hB + 4]) = *reinterpret_cast<const uint4*>(sl + 4);
        }
        __syncthreads();
        bf_chunk(Ah, Al, Bh, Bl, acc, lane, m0w, 0);
        __syncthreads();
    }
    const int gr = lane >> 2, tg = lane & 3;
#pragma unroll
    for (int ms = 0; ms < 2; ms++) {
#pragma unroll
        for (int hf = 0; hf < 2; hf++) {
            int gm = blkM + m0w + ms * 16 + gr + hf * 8;
            if (gm < NN) {
                float rv = rb[gm];
#pragma unroll
                for (int ns = 0; ns < 8; ns++) {
                    int col = ns * 8 + 2 * tg;
                    out[(size_t)col * NN + gm]       = acc[ms][ns][hf * 2] + rv;
                    out[(size_t)(col + 1) * NN + gm] = acc[ms][ns][hf * 2 + 1] + rv;
                }
            }
        }
    }
}

// ---------------- host ----------------
static void* sym(const void* s) { void* p = nullptr; cudaGetSymbolAddress(&p, s); return p; }

extern "C" void kernel_launch(void* const* d_in, const int* in_sizes, int n_in,
                              void* d_out, int out_size) {
    const float* emb   = (const float*)d_in[0];
    const float* bases = (const float*)d_in[1];
    const float* comp  = (const float*)d_in[2];
    const float* root  = (const float*)d_in[3];
    const float* rbias = (const float*)d_in[4];
    const float* sth   = (const float*)d_in[5];
    const float* sbi   = (const float*)d_in[6];
    const float* kth   = (const float*)d_in[7];
    const float* kbi   = (const float*)d_in[8];
    const float* ipw   = (const float*)d_in[9];
    const float* ipb   = (const float*)d_in[10];
    const float* opw   = (const float*)d_in[11];
    const float* opb   = (const float*)d_in[12];
    const float* aha   = (const float*)d_in[13];
    const float* ahb   = (const float*)d_in[14];
    const float* aa    = (const float*)d_in[15];
    const float* ab    = (const float*)d_in[16];
    const float* recb  = (const float*)d_in[17];
    const int* esrc = (const int*)d_in[18];
    const int* edst = (const int*)d_in[19];
    const int* ety  = (const int*)d_in[20];
    const int* snod = (const int*)d_in[21];
    const int* sedg = (const int*)d_in[22];
    const int* knod = (const int*)d_in[23];
    const int* kedg = (const int*)d_in[24];
    const int* sri  = (const int*)d_in[25];
    const int* kri  = (const int*)d_in[26];
    const int* cxi  = (const int*)d_in[27];
    float* out = (float*)d_out;

    cudaMemsetAsync(sym(g_cnt), 0, (size_t)NN * NREL * 4, 0);
    cudaMemsetAsync(sym(g_typeCnt), 0, NREL * 4, 0);
    cudaMemsetAsync(sym(g_cursor), 0, NREL * 4, 0);
    cudaMemsetAsync(sym(g_bdegS), 0, NHYP * 4, 0);
    cudaMemsetAsync(sym(g_bdegK), 0, NHYP * 4, 0);
    cudaMemsetAsync(sym(g_ddegS), 0, (size_t)NN * 4, 0);
    cudaMemsetAsync(sym(g_ddegK), 0, (size_t)NN * 4, 0);
    cudaMemsetAsync(sym(g_accS), 0, (size_t)NHYP * DIM * 4, 0);
    cudaMemsetAsync(sym(g_accK), 0, (size_t)NHYP * DIM * 4, 0);
    cudaMemsetAsync(sym(g_flagS), 0, (size_t)NN * 4, 0);
    cudaMemsetAsync(sym(g_flagK), 0, (size_t)NN * 4, 0);

    k_W<<<(NREL * DIM * DIM + 255) / 256, 256>>>(bases, comp);
    k_prep<<<(21 * MATW + 255) / 256, 256>>>(root, sth, kth, ipw, opw, aha, aa);

    // F1: root GEMM || edge count || hyper counts || flags || pack X
    k_fuse1<<<ROOTB + COUNTB + 2 * HCB + 2 * FLAGB + PACKB, 256>>>(
        emb, rbias, edst, ety, snod, sedg, knod, kedg, sri, kri);
    k_sort<<<(NEDGE + 255) / 256, 256>>>(ety);
    k_edge_gemm<<<EDGE_TILES, 256>>>(esrc, edst);

    // hypergraphs (linearity: scatter kg, then small GEMM with 1/b_deg)
    k_scatter_acc2<<<(2 * NP * 32) / 256, 256>>>(snod, sedg, knod, kedg);
    k_gemm_ef2<<<2 * EFB, 256>>>();
    k_scatter_node2<<<(2 * NP * 32) / 256, 256>>>(snod, sedg, knod, kedg);

    k_gather<<<(NB * LKV * DIM + NB * LCTX * DIM + 255) / 256, 256>>>(sri, kri, sbi, kbi, cxi);

    // MHA
    k_qkv<<<144, 256>>>(ipb);
    k_mha<<<NB * NHEAD, 32>>>();
    k_gemm128b<<<16, 256>>>((float*)sym(g_o), 18, opb, (float*)sym(g_attrel), NB * LCTX);

    // his self-attn
    k_gemm128b<<<16, 256>>>((float*)sym(g_attrel), 19, nullptr, (float*)sym(g_t1), NB * LCTX);
    k_selfattn<<<NB, 128>>>((float*)sym(g_attrel), (float*)sym(g_t1), ahb,
                            (float*)sym(g_his), LCTX);

    // user self-attn over [context, his]
    k_ucat<<<(NB * 33 * DIM + 255) / 256, 256>>>();
    k_gemm128b<<<17, 256>>>((float*)sym(g_ucat), 20, nullptr, (float*)sym(g_t2), NB * 33);
    k_selfattn<<<NB, 128>>>((float*)sym(g_ucat), (float*)sym(g_t2), ab,
                            (float*)sym(g_user), 33);

    // scores on tensor cores
    k_packU<<<(MATW + 255) / 256, 256>>>();
    k_scores_mma<<<(NN + 127) / 128, 128>>>(recb, out);
}

// round 10
// speedup vs baseline: 1.6592x; 1.0014x over previous
#include <cuda_runtime.h>
#include <cuda_bf16.h>
#include <math.h>

#define NN 100000
#define DIM 128
#define NREL 12
#define NBASES 8
#define NEDGE 1000000
#define NP 400000
#define NHYP 20000
#define NB 64
#define LREL 64
#define LKV 128
#define LCTX 32
#define NHEAD 8
#define HDIM 16
#define EDGE_TILES 7830
#define NMAT 22
#define MATW 8192   // 128 rows x 64 packed words per matrix

#define ROOTB 782
#define COUNTB 3907
#define HCB 1563
#define FLAGB 16
#define PACKB 3125
#define EFB 157

__device__ __forceinline__ void red_add_v4(float* p, float x, float y, float z, float w) {
    asm volatile("red.global.add.v4.f32 [%0], {%1,%2,%3,%4};"
                 :: "l"(p), "f"(x), "f"(y), "f"(z), "f"(w) : "memory");
}

// split two fp32 into packed bf16x2 hi word + lo word
__device__ __forceinline__ unsigned pack_split(float x0, float x1, unsigned& lo) {
    __nv_bfloat16 h0 = __float2bfloat16(x0), h1 = __float2bfloat16(x1);
    float r0 = x0 - __bfloat162float(h0), r1 = x1 - __bfloat162float(h1);
    __nv_bfloat16 l0 = __float2bfloat16(r0), l1 = __float2bfloat16(r1);
    lo = (unsigned)__bfloat16_as_ushort(l0) | ((unsigned)__bfloat16_as_ushort(l1) << 16);
    return (unsigned)__bfloat16_as_ushort(h0) | ((unsigned)__bfloat16_as_ushort(h1) << 16);
}

__device__ __forceinline__ void mma16(float* c, const unsigned* a, const unsigned* b) {
    asm("mma.sync.aligned.m16n8k16.row.col.f32.bf16.bf16.f32 "
        "{%0,%1,%2,%3}, {%4,%5,%6,%7}, {%8,%9}, {%0,%1,%2,%3};"
        : "+f"(c[0]), "+f"(c[1]), "+f"(c[2]), "+f"(c[3])
        : "r"(a[0]), "r"(a[1]), "r"(a[2]), "r"(a[3]), "r"(b[0]), "r"(b[1]));
}

__device__ __forceinline__ void ldsm4(unsigned* r, const unsigned* p) {
    unsigned addr = (unsigned)__cvta_generic_to_shared(const_cast<unsigned*>(p));
    asm volatile("ldmatrix.sync.aligned.m8n8.x4.shared.b16 {%0,%1,%2,%3}, [%4];"
                 : "=r"(r[0]), "=r"(r[1]), "=r"(r[2]), "=r"(r[3]) : "r"(addr));
}

// ---------------- device scratch ----------------
__device__ unsigned g_Bh[NMAT * MATW];
__device__ unsigned g_Bl[NMAT * MATW];
__device__ unsigned g_Xh[NN * 64];
__device__ unsigned g_Xl[NN * 64];
__device__ float g_kg[NN * DIM];
__device__ int   g_cnt[NN * NREL];
__device__ int   g_typeCnt[NREL];
__device__ int   g_cursor[NREL];
__device__ int   g_sorted[NEDGE];
__device__ int   g_bdegS[NHYP], g_bdegK[NHYP];
__device__ int   g_ddegS[NN], g_ddegK[NN];
__device__ float g_accS[NHYP * DIM], g_accK[NHYP * DIM];
__device__ float g_efS[NHYP * DIM], g_efK[NHYP * DIM];
__device__ int   g_flagS[NN], g_flagK[NN];
__device__ float g_noS[NN * DIM], g_noK[NN * DIM];
__device__ float g_related[NB * LKV * DIM];
__device__ float g_context[NB * LCTX * DIM];
__device__ float g_qh[NB * LCTX * DIM];
__device__ float g_kh[NB * LKV * DIM];
__device__ float g_vh[NB * LKV * DIM];
__device__ float g_o[NB * LCTX * DIM];
__device__ float g_attrel[NB * LCTX * DIM];
__device__ float g_t1[NB * LCTX * DIM];
__device__ float g_ucat[NB * 33 * DIM];
__device__ float g_t2[NB * 33 * DIM];
__device__ float g_his[NB * DIM];
__device__ float g_user[NB * DIM];

// ---------------- prep: pack 21 static B-matrices (W computed inline) ----------------
__global__ void k_prep(const float* __restrict__ bases, const float* __restrict__ comp,
                       const float* __restrict__ root, const float* __restrict__ sth,
                       const float* __restrict__ kth, const float* __restrict__ ipw,
                       const float* __restrict__ opw, const float* __restrict__ aha,
                       const float* __restrict__ aa) {
    int idx = blockIdx.x * blockDim.x + threadIdx.x;
    if (idx >= 21 * MATW) return;
    int m = idx >> 13, rem = idx & (MATW - 1), n = rem >> 6, k2 = rem & 63;
    float s0, s1;
    if (m < 12) {
        const float* cp = comp + m * NBASES;
        s0 = 0.f; s1 = 0.f;
#pragma unroll
        for (int b = 0; b < NBASES; b++) {
            const float* bp = bases + (size_t)b * DIM * DIM + (2 * k2) * DIM + n;
            s0 = fmaf(cp[b], bp[0], s0);
            s1 = fmaf(cp[b], bp[DIM], s1);
        }
    } else {
        const float* b; int tr = 0;
        switch (m) {
            case 12: b = root; break;
            case 13: b = sth; break;
            case 14: b = kth; break;
            case 15: b = ipw; tr = 1; break;
            case 16: b = ipw + DIM * DIM; tr = 1; break;
            case 17: b = ipw + 2 * DIM * DIM; tr = 1; break;
            case 18: b = opw; tr = 1; break;
            case 19: b = aha; break;
            default: b = aa; break;
        }
        if (tr) { s0 = b[n * DIM + 2 * k2]; s1 = b[n * DIM + 2 * k2 + 1]; }
        else    { s0 = b[(2 * k2) * DIM + n]; s1 = b[(2 * k2 + 1) * DIM + n]; }
    }
    unsigned lo, hi = pack_split(s0, s1, lo);
    g_Bh[idx] = hi; g_Bl[idx] = lo;
}

__global__ void k_packU() {
    int idx = blockIdx.x * blockDim.x + threadIdx.x;
    if (idx >= MATW) return;
    int n = idx >> 6, k2 = idx & 63;
    float s0 = 0.f, s1 = 0.f;
    if (n < NB) { s0 = g_user[n * DIM + 2 * k2]; s1 = g_user[n * DIM + 2 * k2 + 1]; }
    unsigned lo, hi = pack_split(s0, s1, lo);
    g_Bh[21 * MATW + idx] = hi; g_Bl[21 * MATW + idx] = lo;
}

// counting sort with block aggregation; per-block prefix from g_typeCnt
__global__ void k_sort(const int* __restrict__ ty) {
    __shared__ int h[NREL], base[NREL];
    int t = threadIdx.x;
    if (t < NREL) h[t] = 0;
    __syncthreads();
    int e = blockIdx.x * blockDim.x + t;
    int tt = -1, loc = 0;
    if (e < NEDGE) { tt = ty[e]; loc = atomicAdd(&h[tt], 1); }
    __syncthreads();
    if (t < NREL) {
        int off = 0;
        for (int i = 0; i < t; i++) off += g_typeCnt[i];
        base[t] = off + (h[t] ? atomicAdd(&g_cursor[t], h[t]) : 0);
    }
    __syncthreads();
    if (e < NEDGE) g_sorted[base[tt] + loc] = e;
}

// bf16x2 3-term compute over one K32 chunk (ldmatrix fragment loads)
__device__ __forceinline__ void bf_chunk(
    const unsigned (*Ah)[20], const unsigned (*Al)[20],
    const unsigned (*Bh)[20], const unsigned (*Bl)[20],
    float acc[2][8][4], int lane, int m0, int n0) {
    const int ar = lane & 15, ac = (lane >> 4) * 4;
    const int br = (lane & 7) | ((lane >> 4) << 3), bc = ((lane >> 3) & 1) * 4;
#pragma unroll
    for (int s = 0; s < 2; s++) {
        const int kb = s * 8;
        unsigned bh[8][2], bl[8][2];
#pragma unroll
        for (int np = 0; np < 4; np++) {
            unsigned r4[4];
            ldsm4(r4, &Bh[n0 + np * 16 + br][kb + bc]);
            bh[2*np][0] = r4[0]; bh[2*np][1] = r4[1];
            bh[2*np+1][0] = r4[2]; bh[2*np+1][1] = r4[3];
            ldsm4(r4, &Bl[n0 + np * 16 + br][kb + bc]);
            bl[2*np][0] = r4[0]; bl[2*np][1] = r4[1];
            bl[2*np+1][0] = r4[2]; bl[2*np+1][1] = r4[3];
        }
#pragma unroll
        for (int ms = 0; ms < 2; ms++) {
            unsigned ah[4], al[4];
            ldsm4(ah, &Ah[m0 + ms * 16 + ar][kb + ac]);
            ldsm4(al, &Al[m0 + ms * 16 + ar][kb + ac]);
#pragma unroll
            for (int ns = 0; ns < 8; ns++) {
                mma16(acc[ms][ns], ah, bh[ns]);
                mma16(acc[ms][ns], ah, bl[ns]);
                mma16(acc[ms][ns], al, bh[ns]);
            }
        }
    }
}

// convert 16 fp32 (scaled) -> 8 hi + 8 lo packed words
__device__ __forceinline__ void conv_store_row(const float4* ap, float scale,
                                               unsigned* dh, unsigned* dl) {
    unsigned hw[8], lw[8];
#pragma unroll
    for (int q = 0; q < 4; q++) {
        float4 v = ap[q];
        v.x *= scale; v.y *= scale; v.z *= scale; v.w *= scale;
        hw[2*q]   = pack_split(v.x, v.y, lw[2*q]);
        hw[2*q+1] = pack_split(v.z, v.w, lw[2*q+1]);
    }
    *reinterpret_cast<uint4*>(dh)     = make_uint4(hw[0], hw[1], hw[2], hw[3]);
    *reinterpret_cast<uint4*>(dh + 4) = make_uint4(hw[4], hw[5], hw[6], hw[7]);
    *reinterpret_cast<uint4*>(dl)     = make_uint4(lw[0], lw[1], lw[2], lw[3]);
    *reinterpret_cast<uint4*>(dl + 4) = make_uint4(lw[4], lw[5], lw[6], lw[7]);
}

// ------------- generic GEMM body: C[M,128] = A[M,128] @ B(mat) (+bias, row scale 1/deg) ----
__device__ __forceinline__ void gemm_body(
    unsigned (*Ah)[20], unsigned (*Al)[20], unsigned (*Bh)[20], unsigned (*Bl)[20],
    const float* __restrict__ A, int mat, const float* __restrict__ bias,
    float* __restrict__ C, int M, const int* __restrict__ rowdeg, int blk) {
    const int t = threadIdx.x, lane = t & 31, warp = t >> 5;
    const int m0w = (warp & 3) * 32, n0w = (warp >> 2) * 64;
    const int blkM = blk * 128;
    const unsigned* Bhg = g_Bh + mat * MATW;
    const unsigned* Blg = g_Bl + mat * MATW;
    float acc[2][8][4];
#pragma unroll
    for (int i = 0; i < 2; i++)
#pragma unroll
        for (int j = 0; j < 8; j++)
#pragma unroll
            for (int q = 0; q < 4; q++) acc[i][j][q] = 0.f;
    const int mA = t >> 1, half = t & 1;
    const int nB = t >> 1, hB = (t & 1) * 8;

    for (int k0 = 0; k0 < 128; k0 += 32) {
        int gm = blkM + mA;
        if (gm < M) {
            const float4* ap = reinterpret_cast<const float4*>(A + (size_t)gm * DIM + k0 + half * 16);
            conv_store_row(ap, 1.0f, &Ah[mA][half * 8], &Al[mA][half * 8]);
        } else {
            uint4 z = make_uint4(0, 0, 0, 0);
            *reinterpret_cast<uint4*>(&Ah[mA][half*8]) = z;
            *reinterpret_cast<uint4*>(&Ah[mA][half*8+4]) = z;
            *reinterpret_cast<uint4*>(&Al[mA][half*8]) = z;
            *reinterpret_cast<uint4*>(&Al[mA][half*8+4]) = z;
        }
        {
            const unsigned* sh = Bhg + nB * 64 + k0 / 2 + hB;
            const unsigned* sl = Blg + nB * 64 + k0 / 2 + hB;
            *reinterpret_cast<uint4*>(&Bh[nB][hB])     = *reinterpret_cast<const uint4*>(sh);
            *reinterpret_cast<uint4*>(&Bh[nB][hB + 4]) = *reinterpret_cast<const uint4*>(sh + 4);
            *reinterpret_cast<uint4*>(&Bl[nB][hB])     = *reinterpret_cast<const uint4*>(sl);
            *reinterpret_cast<uint4*>(&Bl[nB][hB + 4]) = *reinterpret_cast<const uint4*>(sl + 4);
        }
        __syncthreads();
        bf_chunk(Ah, Al, Bh, Bl, acc, lane, m0w, n0w);
        __syncthreads();
    }
    const int gr = lane >> 2, tg = lane & 3;
#pragma unroll
    for (int ms = 0; ms < 2; ms++) {
#pragma unroll
        for (int hf = 0; hf < 2; hf++) {
            int gm = blkM + m0w + ms * 16 + gr + hf * 8;
            if (gm < M) {
                float scale = 1.f;
                if (rowdeg) { int dg = rowdeg[gm]; scale = dg > 0 ? 1.f / (float)dg : 0.f; }
                float* cp = C + (size_t)gm * DIM;
#pragma unroll
                for (int ns = 0; ns < 8; ns++) {
                    int col = n0w + ns * 8 + 2 * tg;
                    float b0 = bias ? bias[col] : 0.f;
                    float b1 = bias ? bias[col + 1] : 0.f;
                    float2 v = make_float2(acc[ms][ns][hf * 2] * scale + b0,
                                           acc[ms][ns][hf * 2 + 1] * scale + b1);
                    *reinterpret_cast<float2*>(cp + col) = v;
                }
            }
        }
    }
}

__global__ void __launch_bounds__(256) k_gemm128b(
    const float* __restrict__ A, int mat, const float* __restrict__ bias,
    float* __restrict__ C, int M) {
    __shared__ unsigned Ah[128][20], Al[128][20], Bh[128][20], Bl[128][20];
    gemm_body(Ah, Al, Bh, Bl, A, mat, bias, C, M, nullptr, blockIdx.x);
}

// ------------- F1: root GEMM || edge count || hyper counts || flags || pack X -------------
__global__ void __launch_bounds__(256) k_fuse1(
    const float* __restrict__ emb, const float* __restrict__ rbias,
    const int* __restrict__ edst, const int* __restrict__ ety,
    const int* __restrict__ snod, const int* __restrict__ sedg,
    const int* __restrict__ knod, const int* __restrict__ kedg,
    const int* __restrict__ sri, const int* __restrict__ kri) {
    __shared__ unsigned Ah[128][20], Al[128][20], Bh[128][20], Bl[128][20];
    __shared__ int fh[NREL];
    int b = blockIdx.x;
    int t = threadIdx.x;
    if (b < ROOTB) {
        gemm_body(Ah, Al, Bh, Bl, emb, 12, rbias, g_kg, NN, nullptr, b);
        return;
    }
    b -= ROOTB;
    if (b < COUNTB) {
        if (t < NREL) fh[t] = 0;
        __syncthreads();
        int e = b * 256 + t;
        if (e < NEDGE) {
            int tt = ety[e];
            atomicAdd(&g_cnt[edst[e] * NREL + tt], 1);
            atomicAdd(&fh[tt], 1);
        }
        __syncthreads();
        if (t < NREL && fh[t]) atomicAdd(&g_typeCnt[t], fh[t]);
        return;
    }
    b -= COUNTB;
    if (b < 2 * HCB) {
        const int* nodes; const int* edges; int* bdeg; int* ddeg;
        int lb = b;
        if (lb < HCB) { nodes = snod; edges = sedg; bdeg = g_bdegS; ddeg = g_ddegS; }
        else { lb -= HCB; nodes = knod; edges = kedg; bdeg = g_bdegK; ddeg = g_ddegK; }
        int p = lb * 256 + t;
        if (p < NP) {
            atomicAdd(&bdeg[edges[p]], 1);
            atomicAdd(&ddeg[nodes[p]], 1);
        }
        return;
    }
    b -= 2 * HCB;
    if (b < 2 * FLAGB) {
        const int* idx; int* flag; float* no;
        int lb = b;
        if (lb < FLAGB) { idx = sri; flag = g_flagS; no = g_noS; }
        else { lb -= FLAGB; idx = kri; flag = g_flagK; no = g_noK; }
        int i = lb * 256 + t;
        if (i < NB * LREL) {
            int n = idx[i];
            flag[n] = 1;
            float4 z = make_float4(0.f, 0.f, 0.f, 0.f);
            float4* p = reinterpret_cast<float4*>(no + (size_t)n * DIM);
#pragma unroll
            for (int d = 0; d < DIM / 4; d++) p[d] = z;
        }
        return;
    }
    b -= 2 * FLAGB;
    {
        int i = b * 256 + t;
        if (i < NN * 8) {
            int n = i >> 3, part = i & 7;
            const float4* ap = reinterpret_cast<const float4*>(emb + (size_t)n * DIM + part * 16);
            conv_store_row(ap, 1.0f, &g_Xh[(size_t)n * 64 + part * 8],
                           &g_Xl[(size_t)n * 64 + part * 8]);
        }
    }
}

// ------------- RGCN edge GEMM (pre-packed A): kg[dst] += norm * x[src] @ W[type] -------------
__global__ void __launch_bounds__(256) k_edge_gemm(
    const int* __restrict__ esrc, const int* __restrict__ edst) {
    __shared__ unsigned Ah[128][20], Al[128][20], Bh[128][20], Bl[128][20];
    __shared__ int   sSrc[128], sDst[128];
    __shared__ float sNorm[128];
    const int bid = blockIdx.x;
    int r = -1, base = 0, cnt = 0;
    {
        int off = 0, toff = 0;
#pragma unroll
        for (int i = 0; i < NREL; i++) {
            int c = g_typeCnt[i];
            int nt = (c + 127) >> 7;
            if (r < 0 && bid < toff + nt) {
                int local = bid - toff;
                r = i; base = off + local * 128;
                cnt = c - local * 128; if (cnt > 128) cnt = 128;
            }
            off += c; toff += nt;
        }
    }
    if (r < 0) return;
    const int t = threadIdx.x, lane = t & 31, warp = t >> 5;
    const int m0w = (warp & 3) * 32, n0w = (warp >> 2) * 64;
    if (t < 128) {
        if (t < cnt) {
            int e = g_sorted[base + t];
            int d = edst[e];
            sSrc[t] = esrc[e]; sDst[t] = d;
            sNorm[t] = 1.0f / fmaxf((float)g_cnt[d * NREL + r], 1.0f);
        } else { sSrc[t] = 0; sDst[t] = -1; sNorm[t] = 0.f; }
    }
    __syncthreads();
    float acc[2][8][4];
#pragma unroll
    for (int i = 0; i < 2; i++)
#pragma unroll
        for (int j = 0; j < 8; j++)
#pragma unroll
            for (int q = 0; q < 4; q++) acc[i][j][q] = 0.f;
    const int mA = t >> 1, half = t & 1;
    const int nB = t >> 1, hB = (t & 1) * 8;
    const unsigned* Bhg = g_Bh + r * MATW;
    const unsigned* Blg = g_Bl + r * MATW;

    for (int k0 = 0; k0 < 128; k0 += 32) {
        {
            size_t xoff = (size_t)sSrc[mA] * 64 + k0 / 2 + half * 8;
            const unsigned* xh = g_Xh + xoff;
            const unsigned* xl = g_Xl + xoff;
            *reinterpret_cast<uint4*>(&Ah[mA][half*8])     = *reinterpret_cast<const uint4*>(xh);
            *reinterpret_cast<uint4*>(&Ah[mA][half*8 + 4]) = *reinterpret_cast<const uint4*>(xh + 4);
            *reinterpret_cast<uint4*>(&Al[mA][half*8])     = *reinterpret_cast<const uint4*>(xl);
            *reinterpret_cast<uint4*>(&Al[mA][half*8 + 4]) = *reinterpret_cast<const uint4*>(xl + 4);
        }
        {
            const unsigned* sh = Bhg + nB * 64 + k0 / 2 + hB;
            const unsigned* sl = Blg + nB * 64 + k0 / 2 + hB;
            *reinterpret_cast<uint4*>(&Bh[nB][hB])     = *reinterpret_cast<const uint4*>(sh);
            *reinterpret_cast<uint4*>(&Bh[nB][hB + 4]) = *reinterpret_cast<const uint4*>(sh + 4);
            *reinterpret_cast<uint4*>(&Bl[nB][hB])     = *reinterpret_cast<const uint4*>(sl);
            *reinterpret_cast<uint4*>(&Bl[nB][hB + 4]) = *reinterpret_cast<const uint4*>(sl + 4);
        }
        __syncthreads();
        bf_chunk(Ah, Al, Bh, Bl, acc, lane, m0w, n0w);
        __syncthreads();
    }
    const int gr = lane >> 2, tg = lane & 3;
#pragma unroll
    for (int ms = 0; ms < 2; ms++) {
#pragma unroll
        for (int hf = 0; hf < 2; hf++) {
            int rr = m0w + ms * 16 + gr + hf * 8;
            int dn = sDst[rr];
            float nrm = sNorm[rr];
#pragma unroll
            for (int ns = 0; ns < 8; ns++) {
                float v0 = acc[ms][ns][hf * 2] * nrm;
                float v1 = acc[ms][ns][hf * 2 + 1] * nrm;
                float p0 = __shfl_xor_sync(0xffffffffu, v0, 1);
                float p1 = __shfl_xor_sync(0xffffffffu, v1, 1);
                if (((tg & 1) == 0) && dn >= 0)
                    red_add_v4(g_kg + (size_t)dn * DIM + n0w + ns * 8 + 2 * tg, v0, v1, p0, p1);
            }
        }
    }
}

// ------------- fused S/K hyperedge accumulation: acc[he] += kg[node] -------------
__global__ void k_scatter_acc2(const int* __restrict__ snod, const int* __restrict__ sedg,
                               const int* __restrict__ knod, const int* __restrict__ kedg) {
    int w = (blockIdx.x * blockDim.x + threadIdx.x) >> 5;
    int lane = threadIdx.x & 31;
    const int* nodes; const int* edges; float* accum;
    if (w < NP) { nodes = snod; edges = sedg; accum = g_accS; }
    else { w -= NP; if (w >= NP) return; nodes = knod; edges = kedg; accum = g_accK; }
    float4 v = *reinterpret_cast<const float4*>(&g_kg[(size_t)nodes[w] * DIM + lane * 4]);
    red_add_v4(accum + (size_t)edges[w] * DIM + lane * 4, v.x, v.y, v.z, v.w);
}

// fused S/K edge-feature GEMMs: ef = (acc @ theta) / b_deg
__global__ void __launch_bounds__(256) k_gemm_ef2() {
    __shared__ unsigned Ah[128][20], Al[128][20], Bh[128][20], Bl[128][20];
    int b = blockIdx.x;
    if (b < EFB) gemm_body(Ah, Al, Bh, Bl, g_accS, 13, nullptr, g_efS, NHYP, g_bdegS, b);
    else gemm_body(Ah, Al, Bh, Bl, g_accK, 14, nullptr, g_efK, NHYP, g_bdegK, b - EFB);
}

// fused S/K node scatter (flag-masked)
__global__ void k_scatter_node2(const int* __restrict__ snod, const int* __restrict__ sedg,
                                const int* __restrict__ knod, const int* __restrict__ kedg) {
    int w = (blockIdx.x * blockDim.x + threadIdx.x) >> 5;
    int lane = threadIdx.x & 31;
    const int* nodes; const int* edges; const int* flag; const float* ef; float* no;
    if (w < NP) { nodes = snod; edges = sedg; flag = g_flagS; ef = g_efS; no = g_noS; }
    else { w -= NP; if (w >= NP) return; nodes = knod; edges = kedg; flag = g_flagK; ef = g_efK; no = g_noK; }
    int n = nodes[w];
    if (!flag[n]) return;
    float4 v = *reinterpret_cast<const float4*>(ef + (size_t)edges[w] * DIM + lane * 4);
    red_add_v4(no + (size_t)n * DIM + lane * 4, v.x, v.y, v.z, v.w);
}

// fused gathers: related + context
__global__ void k_gather(const int* __restrict__ sidx, const int* __restrict__ kidx,
                         const float* __restrict__ biasS, const float* __restrict__ biasK,
                         const int* __restrict__ cidx) {
    int i = blockIdx.x * blockDim.x + threadIdx.x;
    if (i < NB * LKV * DIM) {
        int d = i & 127, l = (i >> 7) & 127, b = i >> 14;
        float v;
        if (l < LREL) {
            int n = sidx[b * LREL + l]; int dd = g_ddegS[n];
            v = g_noS[(size_t)n * DIM + d] * (dd > 0 ? 1.f / dd : 0.f) + biasS[d];
        } else {
            int n = kidx[b * LREL + l - LREL]; int dd = g_ddegK[n];
            v = g_noK[(size_t)n * DIM + d] * (dd > 0 ? 1.f / dd : 0.f) + biasK[d];
        }
        g_related[i] = v;
        return;
    }
    int j = i - NB * LKV * DIM;
    if (j < NB * LCTX * DIM)
        g_context[j] = g_kg[(size_t)cidx[j >> 7] * DIM + (j & 127)];
}

// fused Q/K/V projections
__global__ void __launch_bounds__(256) k_qkv(const float* __restrict__ ipb) {
    __shared__ unsigned Ah[128][20], Al[128][20], Bh[128][20], Bl[128][20];
    int b = blockIdx.x;
    if (b < 16) gemm_body(Ah, Al, Bh, Bl, g_context, 15, ipb, g_qh, NB * LCTX, nullptr, b);
    else if (b < 80) gemm_body(Ah, Al, Bh, Bl, g_related, 16, ipb + DIM, g_kh, NB * LKV, nullptr, b - 16);
    else gemm_body(Ah, Al, Bh, Bl, g_related, 17, ipb + 2 * DIM, g_vh, NB * LKV, nullptr, b - 80);
}

// ---------------- attention ----------------
__global__ void k_mha() {
    int b = blockIdx.x / NHEAD, h = blockIdx.x % NHEAD;
    __shared__ float ks[LKV][HDIM], vs[LKV][HDIM];
    int t = threadIdx.x;
    for (int i = t; i < LKV * HDIM; i += 32) {
        int k = i / HDIM, d = i % HDIM;
        size_t off = ((size_t)b * LKV + k) * DIM + h * HDIM + d;
        ks[k][d] = g_kh[off]; vs[k][d] = g_vh[off];
    }
    __syncwarp();
    float q[HDIM];
    size_t qoff = ((size_t)b * LCTX + t) * DIM + h * HDIM;
#pragma unroll
    for (int d = 0; d < HDIM; d++) q[d] = g_qh[qoff + d];
    float lg[LKV], mx = -1e30f;
    for (int k = 0; k < LKV; k++) {
        float s = 0.f;
#pragma unroll
        for (int d = 0; d < HDIM; d++) s += q[d] * ks[k][d];
        s *= 0.25f; lg[k] = s; mx = fmaxf(mx, s);
    }
    float sum = 0.f;
    for (int k = 0; k < LKV; k++) { lg[k] = expf(lg[k] - mx); sum += lg[k]; }
    float inv = 1.f / sum;
    float acc[HDIM];
#pragma unroll
    for (int d = 0; d < HDIM; d++) acc[d] = 0.f;
    for (int k = 0; k < LKV; k++) {
        float w = lg[k];
#pragma unroll
        for (int d = 0; d < HDIM; d++) acc[d] += w * vs[k][d];
    }
#pragma unroll
    for (int d = 0; d < HDIM; d++) g_o[qoff + d] = acc[d] * inv;
}

__global__ void k_selfattn(const float* __restrict__ h, const float* __restrict__ t1,
                           const float* __restrict__ bvec, float* __restrict__ out, int L) {
    int b = blockIdx.x, t = threadIdx.x;
    __shared__ float w[40];
    if (t < L) {
        float e = 0.f;
        const float* tp = t1 + ((size_t)b * L + t) * DIM;
        for (int d = 0; d < DIM; d++) e += tanhf(tp[d]) * bvec[d];
        w[t] = e;
    }
    __syncthreads();
    float mx = -1e30f;
    for (int l = 0; l < L; l++) mx = fmaxf(mx, w[l]);
    float sum = 0.f;
    for (int l = 0; l < L; l++) sum += expf(w[l] - mx);
    float inv = 1.f / sum, acc = 0.f;
    for (int l = 0; l < L; l++) acc += expf(w[l] - mx) * h[((size_t)b * L + l) * DIM + t];
    out[(size_t)b * DIM + t] = acc * inv;
}

__global__ void k_ucat() {
    int i = blockIdx.x * blockDim.x + threadIdx.x;
    if (i >= NB * 33 * DIM) return;
    int d = i & 127, l = (i >> 7) % 33, b = i / (33 * DIM);
    g_ucat[i] = (l < 32) ? g_context[((size_t)b * 32 + l) * DIM + d] : g_his[(size_t)b * DIM + d];
}

// ------------- scores via tensor cores, coalesced epilogue -------------
__global__ void __launch_bounds__(128) k_scores_mma(const float* __restrict__ rb,
                                                    float* __restrict__ out) {
    __shared__ unsigned Ah[128][20], Al[128][20], Bh[64][20], Bl[64][20];
    __shared__ float st[128][33];
    const int t = threadIdx.x, lane = t & 31, warp = t >> 5;
    const int m0w = warp * 32;
    const int blkM = blockIdx.x * 128;
    const unsigned* Bhg = g_Bh + 21 * MATW;
    const unsigned* Blg = g_Bl + 21 * MATW;
    float acc[2][8][4];
#pragma unroll
    for (int i = 0; i < 2; i++)
#pragma unroll
        for (int j = 0; j < 8; j++)
#pragma unroll
            for (int q = 0; q < 4; q++) acc[i][j][q] = 0.f;

    for (int k0 = 0; k0 < 128; k0 += 32) {
        int gm = blkM + t;
        if (gm < NN) {
            const float4* ap = reinterpret_cast<const float4*>(g_kg + (size_t)gm * DIM + k0);
            conv_store_row(ap, 1.0f, &Ah[t][0], &Al[t][0]);
            conv_store_row(ap + 4, 1.0f, &Ah[t][8], &Al[t][8]);
        } else {
            uint4 z = make_uint4(0, 0, 0, 0);
#pragma unroll
            for (int q = 0; q < 4; q++) {
                *reinterpret_cast<uint4*>(&Ah[t][4 * q]) = z;
                *reinterpret_cast<uint4*>(&Al[t][4 * q]) = z;
            }
        }
        {
            int nB = t & 63, hB = (t >> 6) * 8;
            const unsigned* sh = Bhg + nB * 64 + k0 / 2 + hB;
            const unsigned* sl = Blg + nB * 64 + k0 / 2 + hB;
            *reinterpret_cast<uint4*>(&Bh[nB][hB])     = *reinterpret_cast<const uint4*>(sh);
            *reinterpret_cast<uint4*>(&Bh[nB][hB + 4]) = *reinterpret_cast<const uint4*>(sh + 4);
            *reinterpret_cast<uint4*>(&Bl[nB][hB])     = *reinterpret_cast<const uint4*>(sl);
            *reinterpret_cast<uint4*>(&Bl[nB][hB + 4]) = *reinterpret_cast<const uint4*>(sl + 4);
        }
        __syncthreads();
        bf_chunk(Ah, Al, Bh, Bl, acc, lane, m0w, 0);
        __syncthreads();
    }
    const int gr = lane >> 2, tg = lane & 3;
    int gmn = blkM + t;
    float rv = (gmn < NN) ? rb[gmn] : 0.f;
#pragma unroll
    for (int halfc = 0; halfc < 2; halfc++) {
        __syncthreads();
#pragma unroll
        for (int ms = 0; ms < 2; ms++) {
#pragma unroll
            for (int hf = 0; hf < 2; hf++) {
                int row = m0w + ms * 16 + gr + hf * 8;
#pragma unroll
                for (int ns = 0; ns < 4; ns++) {
                    int nsg = halfc * 4 + ns;
                    st[row][ns * 8 + 2 * tg]     = acc[ms][nsg][hf * 2];
                    st[row][ns * 8 + 2 * tg + 1] = acc[ms][nsg][hf * 2 + 1];
                }
            }
        }
        __syncthreads();
        if (gmn < NN) {
#pragma unroll
            for (int c = 0; c < 32; c++)
                out[(size_t)(halfc * 32 + c) * NN + gmn] = st[t][c] + rv;
        }
    }
}

// ---------------- host ----------------
static void* sym(const void* s) { void* p = nullptr; cudaGetSymbolAddress(&p, s); return p; }

extern "C" void kernel_launch(void* const* d_in, const int* in_sizes, int n_in,
                              void* d_out, int out_size) {
    const float* emb   = (const float*)d_in[0];
    const float* bases = (const float*)d_in[1];
    const float* comp  = (const float*)d_in[2];
    const float* root  = (const float*)d_in[3];
    const float* rbias = (const float*)d_in[4];
    const float* sth   = (const float*)d_in[5];
    const float* sbi   = (const float*)d_in[6];
    const float* kth   = (const float*)d_in[7];
    const float* kbi   = (const float*)d_in[8];
    const float* ipw   = (const float*)d_in[9];
    const float* ipb   = (const float*)d_in[10];
    const float* opw   = (const float*)d_in[11];
    const float* opb   = (const float*)d_in[12];
    const float* aha   = (const float*)d_in[13];
    const float* ahb   = (const float*)d_in[14];
    const float* aa    = (const float*)d_in[15];
    const float* ab    = (const float*)d_in[16];
    const float* recb  = (const float*)d_in[17];
    const int* esrc = (const int*)d_in[18];
    const int* edst = (const int*)d_in[19];
    const int* ety  = (const int*)d_in[20];
    const int* snod = (const int*)d_in[21];
    const int* sedg = (const int*)d_in[22];
    const int* knod = (const int*)d_in[23];
    const int* kedg = (const int*)d_in[24];
    const int* sri  = (const int*)d_in[25];
    const int* kri  = (const int*)d_in[26];
    const int* cxi  = (const int*)d_in[27];
    float* out = (float*)d_out;

    cudaMemsetAsync(sym(g_cnt), 0, (size_t)NN * NREL * 4, 0);
    cudaMemsetAsync(sym(g_typeCnt), 0, NREL * 4, 0);
    cudaMemsetAsync(sym(g_cursor), 0, NREL * 4, 0);
    cudaMemsetAsync(sym(g_bdegS), 0, NHYP * 4, 0);
    cudaMemsetAsync(sym(g_bdegK), 0, NHYP * 4, 0);
    cudaMemsetAsync(sym(g_ddegS), 0, (size_t)NN * 4, 0);
    cudaMemsetAsync(sym(g_ddegK), 0, (size_t)NN * 4, 0);
    cudaMemsetAsync(sym(g_accS), 0, (size_t)NHYP * DIM * 4, 0);
    cudaMemsetAsync(sym(g_accK), 0, (size_t)NHYP * DIM * 4, 0);
    cudaMemsetAsync(sym(g_flagS), 0, (size_t)NN * 4, 0);
    cudaMemsetAsync(sym(g_flagK), 0, (size_t)NN * 4, 0);

    k_prep<<<(21 * MATW + 255) / 256, 256>>>(bases, comp, root, sth, kth, ipw, opw, aha, aa);

    // F1: root GEMM || edge count || hyper counts || flags || pack X
    k_fuse1<<<ROOTB + COUNTB + 2 * HCB + 2 * FLAGB + PACKB, 256>>>(
        emb, rbias, edst, ety, snod, sedg, knod, kedg, sri, kri);
    k_sort<<<(NEDGE + 255) / 256, 256>>>(ety);
    k_edge_gemm<<<EDGE_TILES, 256>>>(esrc, edst);

    // hypergraphs (linearity: scatter kg, then small GEMM with 1/b_deg)
    k_scatter_acc2<<<(2 * NP * 32) / 256, 256>>>(snod, sedg, knod, kedg);
    k_gemm_ef2<<<2 * EFB, 256>>>();
    k_scatter_node2<<<(2 * NP * 32) / 256, 256>>>(snod, sedg, knod, kedg);

    k_gather<<<(NB * LKV * DIM + NB * LCTX * DIM + 255) / 256, 256>>>(sri, kri, sbi, kbi, cxi);

    // MHA
    k_qkv<<<144, 256>>>(ipb);
    k_mha<<<NB * NHEAD, 32>>>();
    k_gemm128b<<<16, 256>>>((float*)sym(g_o), 18, opb, (float*)sym(g_attrel), NB * LCTX);

    // his self-attn
    k_gemm128b<<<16, 256>>>((float*)sym(g_attrel), 19, nullptr, (float*)sym(g_t1), NB * LCTX);
    k_selfattn<<<NB, 128>>>((float*)sym(g_attrel), (float*)sym(g_t1), ahb,
                            (float*)sym(g_his), LCTX);

    // user self-attn over [context, his]
    k_ucat<<<(NB * 33 * DIM + 255) / 256, 256>>>();
    k_gemm128b<<<17, 256>>>((float*)sym(g_ucat), 20, nullptr, (float*)sym(g_t2), NB * 33);
    k_selfattn<<<NB, 128>>>((float*)sym(g_ucat), (float*)sym(g_t2), ab,
                            (float*)sym(g_user), 33);

    // scores on tensor cores
    k_packU<<<(MATW + 255) / 256, 256>>>();
    k_scores_mma<<<(NN + 127) / 128, 128>>>(recb, out);
}

// round 12
// speedup vs baseline: 1.6831x; 1.0144x over previous
#include <cuda_runtime.h>
#include <cuda_bf16.h>
#include <math.h>

#define NN 100000
#define DIM 128
#define NREL 12
#define NBASES 8
#define NEDGE 1000000
#define NP 400000
#define NHYP 20000
#define NB 64
#define LREL 64
#define LKV 128
#define LCTX 32
#define NHEAD 8
#define HDIM 16
#define EDGE_TILES 7830
#define NMAT 22
#define MATW 8192   // 128 rows x 64 packed words per matrix

#define ROOTB 782
#define COUNTB 3907
#define HCB 1563
#define FLAGB 16
#define PACKB 3125
#define EFB 157

// edge kernel double-buffered smem: 8 x 128 x 20 words = 81920 bytes
#define EDGE_SMEM 81920

__device__ __forceinline__ void red_add_v4(float* p, float x, float y, float z, float w) {
    asm volatile("red.global.add.v4.f32 [%0], {%1,%2,%3,%4};"
                 :: "l"(p), "f"(x), "f"(y), "f"(z), "f"(w) : "memory");
}

// split two fp32 into packed bf16x2 hi word + lo word
__device__ __forceinline__ unsigned pack_split(float x0, float x1, unsigned& lo) {
    __nv_bfloat16 h0 = __float2bfloat16(x0), h1 = __float2bfloat16(x1);
    float r0 = x0 - __bfloat162float(h0), r1 = x1 - __bfloat162float(h1);
    __nv_bfloat16 l0 = __float2bfloat16(r0), l1 = __float2bfloat16(r1);
    lo = (unsigned)__bfloat16_as_ushort(l0) | ((unsigned)__bfloat16_as_ushort(l1) << 16);
    return (unsigned)__bfloat16_as_ushort(h0) | ((unsigned)__bfloat16_as_ushort(h1) << 16);
}

__device__ __forceinline__ void mma16(float* c, const unsigned* a, const unsigned* b) {
    asm("mma.sync.aligned.m16n8k16.row.col.f32.bf16.bf16.f32 "
        "{%0,%1,%2,%3}, {%4,%5,%6,%7}, {%8,%9}, {%0,%1,%2,%3};"
        : "+f"(c[0]), "+f"(c[1]), "+f"(c[2]), "+f"(c[3])
        : "r"(a[0]), "r"(a[1]), "r"(a[2]), "r"(a[3]), "r"(b[0]), "r"(b[1]));
}

__device__ __forceinline__ void ldsm4(unsigned* r, const unsigned* p) {
    unsigned addr = (unsigned)__cvta_generic_to_shared(const_cast<unsigned*>(p));
    asm volatile("ldmatrix.sync.aligned.m8n8.x4.shared.b16 {%0,%1,%2,%3}, [%4];"
                 : "=r"(r[0]), "=r"(r[1]), "=r"(r[2]), "=r"(r[3]) : "r"(addr));
}

// ---------------- device scratch ----------------
__device__ unsigned g_Bh[NMAT * MATW];
__device__ unsigned g_Bl[NMAT * MATW];
__device__ unsigned g_Xh[NN * 64];
__device__ unsigned g_Xl[NN * 64];
__device__ float g_kg[NN * DIM];
__device__ int   g_cnt[NN * NREL];
__device__ int   g_typeCnt[NREL];
__device__ int   g_cursor[NREL];
__device__ int   g_sorted[NEDGE];
__device__ int   g_bdegS[NHYP], g_bdegK[NHYP];
__device__ int   g_ddegS[NN], g_ddegK[NN];
__device__ float g_accS[NHYP * DIM], g_accK[NHYP * DIM];
__device__ float g_efS[NHYP * DIM], g_efK[NHYP * DIM];
__device__ int   g_flagS[NN], g_flagK[NN];
__device__ float g_noS[NN * DIM], g_noK[NN * DIM];
__device__ float g_related[NB * LKV * DIM];
__device__ float g_context[NB * LCTX * DIM];
__device__ float g_qh[NB * LCTX * DIM];
__device__ float g_kh[NB * LKV * DIM];
__device__ float g_vh[NB * LKV * DIM];
__device__ float g_o[NB * LCTX * DIM];
__device__ float g_attrel[NB * LCTX * DIM];
__device__ float g_t1[NB * LCTX * DIM];
__device__ float g_ucat[NB * 33 * DIM];
__device__ float g_t2[NB * 33 * DIM];
__device__ float g_his[NB * DIM];
__device__ float g_user[NB * DIM];

// ---------------- prep: pack 21 static B-matrices (W computed inline) ----------------
__global__ void k_prep(const float* __restrict__ bases, const float* __restrict__ comp,
                       const float* __restrict__ root, const float* __restrict__ sth,
                       const float* __restrict__ kth, const float* __restrict__ ipw,
                       const float* __restrict__ opw, const float* __restrict__ aha,
                       const float* __restrict__ aa) {
    int idx = blockIdx.x * blockDim.x + threadIdx.x;
    if (idx >= 21 * MATW) return;
    int m = idx >> 13, rem = idx & (MATW - 1), n = rem >> 6, k2 = rem & 63;
    float s0, s1;
    if (m < 12) {
        const float* cp = comp + m * NBASES;
        s0 = 0.f; s1 = 0.f;
#pragma unroll
        for (int b = 0; b < NBASES; b++) {
            const float* bp = bases + (size_t)b * DIM * DIM + (2 * k2) * DIM + n;
            s0 = fmaf(cp[b], bp[0], s0);
            s1 = fmaf(cp[b], bp[DIM], s1);
        }
    } else {
        const float* b; int tr = 0;
        switch (m) {
            case 12: b = root; break;
            case 13: b = sth; break;
            case 14: b = kth; break;
            case 15: b = ipw; tr = 1; break;
            case 16: b = ipw + DIM * DIM; tr = 1; break;
            case 17: b = ipw + 2 * DIM * DIM; tr = 1; break;
            case 18: b = opw; tr = 1; break;
            case 19: b = aha; break;
            default: b = aa; break;
        }
        if (tr) { s0 = b[n * DIM + 2 * k2]; s1 = b[n * DIM + 2 * k2 + 1]; }
        else    { s0 = b[(2 * k2) * DIM + n]; s1 = b[(2 * k2 + 1) * DIM + n]; }
    }
    unsigned lo, hi = pack_split(s0, s1, lo);
    g_Bh[idx] = hi; g_Bl[idx] = lo;
}

__global__ void k_packU() {
    int idx = blockIdx.x * blockDim.x + threadIdx.x;
    if (idx >= MATW) return;
    int n = idx >> 6, k2 = idx & 63;
    float s0 = 0.f, s1 = 0.f;
    if (n < NB) { s0 = g_user[n * DIM + 2 * k2]; s1 = g_user[n * DIM + 2 * k2 + 1]; }
    unsigned lo, hi = pack_split(s0, s1, lo);
    g_Bh[21 * MATW + idx] = hi; g_Bl[21 * MATW + idx] = lo;
}

// counting sort with block aggregation; per-block prefix from g_typeCnt
__global__ void k_sort(const int* __restrict__ ty) {
    __shared__ int h[NREL], base[NREL];
    int t = threadIdx.x;
    if (t < NREL) h[t] = 0;
    __syncthreads();
    int e = blockIdx.x * blockDim.x + t;
    int tt = -1, loc = 0;
    if (e < NEDGE) { tt = ty[e]; loc = atomicAdd(&h[tt], 1); }
    __syncthreads();
    if (t < NREL) {
        int off = 0;
        for (int i = 0; i < t; i++) off += g_typeCnt[i];
        base[t] = off + (h[t] ? atomicAdd(&g_cursor[t], h[t]) : 0);
    }
    __syncthreads();
    if (e < NEDGE) g_sorted[base[tt] + loc] = e;
}

// bf16x2 3-term compute over one K32 chunk (ldmatrix fragment loads)
__device__ __forceinline__ void bf_chunk(
    const unsigned (*Ah)[20], const unsigned (*Al)[20],
    const unsigned (*Bh)[20], const unsigned (*Bl)[20],
    float acc[2][8][4], int lane, int m0, int n0) {
    const int ar = lane & 15, ac = (lane >> 4) * 4;
    const int br = (lane & 7) | ((lane >> 4) << 3), bc = ((lane >> 3) & 1) * 4;
#pragma unroll
    for (int s = 0; s < 2; s++) {
        const int kb = s * 8;
        unsigned bh[8][2], bl[8][2];
#pragma unroll
        for (int np = 0; np < 4; np++) {
            unsigned r4[4];
            ldsm4(r4, &Bh[n0 + np * 16 + br][kb + bc]);
            bh[2*np][0] = r4[0]; bh[2*np][1] = r4[1];
            bh[2*np+1][0] = r4[2]; bh[2*np+1][1] = r4[3];
            ldsm4(r4, &Bl[n0 + np * 16 + br][kb + bc]);
            bl[2*np][0] = r4[0]; bl[2*np][1] = r4[1];
            bl[2*np+1][0] = r4[2]; bl[2*np+1][1] = r4[3];
        }
#pragma unroll
        for (int ms = 0; ms < 2; ms++) {
            unsigned ah[4], al[4];
            ldsm4(ah, &Ah[m0 + ms * 16 + ar][kb + ac]);
            ldsm4(al, &Al[m0 + ms * 16 + ar][kb + ac]);
#pragma unroll
            for (int ns = 0; ns < 8; ns++) {
                mma16(acc[ms][ns], ah, bh[ns]);
                mma16(acc[ms][ns], ah, bl[ns]);
                mma16(acc[ms][ns], al, bh[ns]);
            }
        }
    }
}

// convert 16 fp32 (scaled) -> 8 hi + 8 lo packed words
__device__ __forceinline__ void conv_store_row(const float4* ap, float scale,
                                               unsigned* dh, unsigned* dl) {
    unsigned hw[8], lw[8];
#pragma unroll
    for (int q = 0; q < 4; q++) {
        float4 v = ap[q];
        v.x *= scale; v.y *= scale; v.z *= scale; v.w *= scale;
        hw[2*q]   = pack_split(v.x, v.y, lw[2*q]);
        hw[2*q+1] = pack_split(v.z, v.w, lw[2*q+1]);
    }
    *reinterpret_cast<uint4*>(dh)     = make_uint4(hw[0], hw[1], hw[2], hw[3]);
    *reinterpret_cast<uint4*>(dh + 4) = make_uint4(hw[4], hw[5], hw[6], hw[7]);
    *reinterpret_cast<uint4*>(dl)     = make_uint4(lw[0], lw[1], lw[2], lw[3]);
    *reinterpret_cast<uint4*>(dl + 4) = make_uint4(lw[4], lw[5], lw[6], lw[7]);
}

// ------------- generic GEMM body: C[M,128] = A[M,128] @ B(mat) (+bias, row scale 1/deg) ----
__device__ __forceinline__ void gemm_body(
    unsigned (*Ah)[20], unsigned (*Al)[20], unsigned (*Bh)[20], unsigned (*Bl)[20],
    const float* __restrict__ A, int mat, const float* __restrict__ bias,
    float* __restrict__ C, int M, const int* __restrict__ rowdeg, int blk) {
    const int t = threadIdx.x, lane = t & 31, warp = t >> 5;
    const int m0w = (warp & 3) * 32, n0w = (warp >> 2) * 64;
    const int blkM = blk * 128;
    const unsigned* Bhg = g_Bh + mat * MATW;
    const unsigned* Blg = g_Bl + mat * MATW;
    float acc[2][8][4];
#pragma unroll
    for (int i = 0; i < 2; i++)
#pragma unroll
        for (int j = 0; j < 8; j++)
#pragma unroll
            for (int q = 0; q < 4; q++) acc[i][j][q] = 0.f;
    const int mA = t >> 1, half = t & 1;
    const int nB = t >> 1, hB = (t & 1) * 8;

    for (int k0 = 0; k0 < 128; k0 += 32) {
        int gm = blkM + mA;
        if (gm < M) {
            const float4* ap = reinterpret_cast<const float4*>(A + (size_t)gm * DIM + k0 + half * 16);
            conv_store_row(ap, 1.0f, &Ah[mA][half * 8], &Al[mA][half * 8]);
        } else {
            uint4 z = make_uint4(0, 0, 0, 0);
            *reinterpret_cast<uint4*>(&Ah[mA][half*8]) = z;
            *reinterpret_cast<uint4*>(&Ah[mA][half*8+4]) = z;
            *reinterpret_cast<uint4*>(&Al[mA][half*8]) = z;
            *reinterpret_cast<uint4*>(&Al[mA][half*8+4]) = z;
        }
        {
            const unsigned* sh = Bhg + nB * 64 + k0 / 2 + hB;
            const unsigned* sl = Blg + nB * 64 + k0 / 2 + hB;
            *reinterpret_cast<uint4*>(&Bh[nB][hB])     = *reinterpret_cast<const uint4*>(sh);
            *reinterpret_cast<uint4*>(&Bh[nB][hB + 4]) = *reinterpret_cast<const uint4*>(sh + 4);
            *reinterpret_cast<uint4*>(&Bl[nB][hB])     = *reinterpret_cast<const uint4*>(sl);
            *reinterpret_cast<uint4*>(&Bl[nB][hB + 4]) = *reinterpret_cast<const uint4*>(sl + 4);
        }
        __syncthreads();
        bf_chunk(Ah, Al, Bh, Bl, acc, lane, m0w, n0w);
        __syncthreads();
    }
    const int gr = lane >> 2, tg = lane & 3;
#pragma unroll
    for (int ms = 0; ms < 2; ms++) {
#pragma unroll
        for (int hf = 0; hf < 2; hf++) {
            int gm = blkM + m0w + ms * 16 + gr + hf * 8;
            if (gm < M) {
                float scale = 1.f;
                if (rowdeg) { int dg = rowdeg[gm]; scale = dg > 0 ? 1.f / (float)dg : 0.f; }
                float* cp = C + (size_t)gm * DIM;
#pragma unroll
                for (int ns = 0; ns < 8; ns++) {
                    int col = n0w + ns * 8 + 2 * tg;
                    float b0 = bias ? bias[col] : 0.f;
                    float b1 = bias ? bias[col + 1] : 0.f;
                    float2 v = make_float2(acc[ms][ns][hf * 2] * scale + b0,
                                           acc[ms][ns][hf * 2 + 1] * scale + b1);
                    *reinterpret_cast<float2*>(cp + col) = v;
                }
            }
        }
    }
}

__global__ void __launch_bounds__(256) k_gemm128b(
    const float* __restrict__ A, int mat, const float* __restrict__ bias,
    float* __restrict__ C, int M) {
    __shared__ unsigned Ah[128][20], Al[128][20], Bh[128][20], Bl[128][20];
    gemm_body(Ah, Al, Bh, Bl, A, mat, bias, C, M, nullptr, blockIdx.x);
}

// ------------- F1: root GEMM || edge count || hyper counts || flags || pack X -------------
__global__ void __launch_bounds__(256) k_fuse1(
    const float* __restrict__ emb, const float* __restrict__ rbias,
    const int* __restrict__ edst, const int* __restrict__ ety,
    const int* __restrict__ snod, const int* __restrict__ sedg,
    const int* __restrict__ knod, const int* __restrict__ kedg,
    const int* __restrict__ sri, const int* __restrict__ kri) {
    __shared__ unsigned Ah[128][20], Al[128][20], Bh[128][20], Bl[128][20];
    __shared__ int fh[NREL];
    int b = blockIdx.x;
    int t = threadIdx.x;
    if (b < ROOTB) {
        gemm_body(Ah, Al, Bh, Bl, emb, 12, rbias, g_kg, NN, nullptr, b);
        return;
    }
    b -= ROOTB;
    if (b < COUNTB) {
        if (t < NREL) fh[t] = 0;
        __syncthreads();
        int e = b * 256 + t;
        if (e < NEDGE) {
            int tt = ety[e];
            atomicAdd(&g_cnt[edst[e] * NREL + tt], 1);
            atomicAdd(&fh[tt], 1);
        }
        __syncthreads();
        if (t < NREL && fh[t]) atomicAdd(&g_typeCnt[t], fh[t]);
        return;
    }
    b -= COUNTB;
    if (b < 2 * HCB) {
        const int* nodes; const int* edges; int* bdeg; int* ddeg;
        int lb = b;
        if (lb < HCB) { nodes = snod; edges = sedg; bdeg = g_bdegS; ddeg = g_ddegS; }
        else { lb -= HCB; nodes = knod; edges = kedg; bdeg = g_bdegK; ddeg = g_ddegK; }
        int p = lb * 256 + t;
        if (p < NP) {
            atomicAdd(&bdeg[edges[p]], 1);
            atomicAdd(&ddeg[nodes[p]], 1);
        }
        return;
    }
    b -= 2 * HCB;
    if (b < 2 * FLAGB) {
        const int* idx; int* flag; float* no;
        int lb = b;
        if (lb < FLAGB) { idx = sri; flag = g_flagS; no = g_noS; }
        else { lb -= FLAGB; idx = kri; flag = g_flagK; no = g_noK; }
        int i = lb * 256 + t;
        if (i < NB * LREL) {
            int n = idx[i];
            flag[n] = 1;
            float4 z = make_float4(0.f, 0.f, 0.f, 0.f);
            float4* p = reinterpret_cast<float4*>(no + (size_t)n * DIM);
#pragma unroll
            for (int d = 0; d < DIM / 4; d++) p[d] = z;
        }
        return;
    }
    b -= 2 * FLAGB;
    {
        int i = b * 256 + t;
        if (i < NN * 8) {
            int n = i >> 3, part = i & 7;
            const float4* ap = reinterpret_cast<const float4*>(emb + (size_t)n * DIM + part * 16);
            conv_store_row(ap, 1.0f, &g_Xh[(size_t)n * 64 + part * 8],
                           &g_Xl[(size_t)n * 64 + part * 8]);
        }
    }
}

// ------------- RGCN edge GEMM (pre-packed A, double-buffered pipeline) -------------
__global__ void __launch_bounds__(256) k_edge_gemm(
    const int* __restrict__ esrc, const int* __restrict__ edst) {
    extern __shared__ unsigned dsm[];
    // [2][128][20] x4 arrays: Ah | Al | Bh | Bl
    unsigned (*Ah)[20] = (unsigned(*)[20])dsm;                 // rows 0..255 (2 bufs)
    unsigned (*Al)[20] = (unsigned(*)[20])(dsm + 2 * 128 * 20);
    unsigned (*Bh)[20] = (unsigned(*)[20])(dsm + 4 * 128 * 20);
    unsigned (*Bl)[20] = (unsigned(*)[20])(dsm + 6 * 128 * 20);
    __shared__ int   sSrc[128], sDst[128];
    __shared__ float sNorm[128];
    const int bid = blockIdx.x;
    int r = -1, base = 0, cnt = 0;
    {
        int off = 0, toff = 0;
#pragma unroll
        for (int i = 0; i < NREL; i++) {
            int c = g_typeCnt[i];
            int nt = (c + 127) >> 7;
            if (r < 0 && bid < toff + nt) {
                int local = bid - toff;
                r = i; base = off + local * 128;
                cnt = c - local * 128; if (cnt > 128) cnt = 128;
            }
            off += c; toff += nt;
        }
    }
    if (r < 0) return;
    const int t = threadIdx.x, lane = t & 31, warp = t >> 5;
    const int m0w = (warp & 3) * 32, n0w = (warp >> 2) * 64;
    if (t < 128) {
        if (t < cnt) {
            int e = g_sorted[base + t];
            int d = edst[e];
            sSrc[t] = esrc[e]; sDst[t] = d;
            sNorm[t] = 1.0f / fmaxf((float)g_cnt[d * NREL + r], 1.0f);
        } else { sSrc[t] = 0; sDst[t] = -1; sNorm[t] = 0.f; }
    }
    __syncthreads();

    const int mA = t >> 1, half = t & 1;
    const unsigned* Bhg = g_Bh + (size_t)r * MATW;
    const unsigned* Blg = g_Bl + (size_t)r * MATW;

    // stage chunk (k0) into buffer buf
    auto stage = [&](int buf, int k0) {
        int ro = buf * 128 + mA;
        size_t xoff = (size_t)sSrc[mA] * 64 + k0 / 2 + half * 8;
        const unsigned* xh = g_Xh + xoff;
        const unsigned* xl = g_Xl + xoff;
        *reinterpret_cast<uint4*>(&Ah[ro][half*8])     = *reinterpret_cast<const uint4*>(xh);
        *reinterpret_cast<uint4*>(&Ah[ro][half*8 + 4]) = *reinterpret_cast<const uint4*>(xh + 4);
        *reinterpret_cast<uint4*>(&Al[ro][half*8])     = *reinterpret_cast<const uint4*>(xl);
        *reinterpret_cast<uint4*>(&Al[ro][half*8 + 4]) = *reinterpret_cast<const uint4*>(xl + 4);
        size_t boff = (size_t)mA * 64 + k0 / 2 + half * 8;
        const unsigned* bh = Bhg + boff;
        const unsigned* bl = Blg + boff;
        *reinterpret_cast<uint4*>(&Bh[ro][half*8])     = *reinterpret_cast<const uint4*>(bh);
        *reinterpret_cast<uint4*>(&Bh[ro][half*8 + 4]) = *reinterpret_cast<const uint4*>(bh + 4);
        *reinterpret_cast<uint4*>(&Bl[ro][half*8])     = *reinterpret_cast<const uint4*>(bl);
        *reinterpret_cast<uint4*>(&Bl[ro][half*8 + 4]) = *reinterpret_cast<const uint4*>(bl + 4);
    };

    float acc[2][8][4];
#pragma unroll
    for (int i = 0; i < 2; i++)
#pragma unroll
        for (int j = 0; j < 8; j++)
#pragma unroll
            for (int q = 0; q < 4; q++) acc[i][j][q] = 0.f;

    stage(0, 0);
    __syncthreads();
#pragma unroll
    for (int c = 0; c < 4; c++) {
        if (c < 3) stage((c + 1) & 1, (c + 1) * 32);
        int rb = (c & 1) * 128;
        bf_chunk(&Ah[rb], &Al[rb], &Bh[rb], &Bl[rb], acc, lane, m0w, n0w);
        __syncthreads();
    }

    const int gr = lane >> 2, tg = lane & 3;
#pragma unroll
    for (int ms = 0; ms < 2; ms++) {
#pragma unroll
        for (int hf = 0; hf < 2; hf++) {
            int rr = m0w + ms * 16 + gr + hf * 8;
            int dn = sDst[rr];
            float nrm = sNorm[rr];
#pragma unroll
            for (int ns = 0; ns < 8; ns++) {
                float v0 = acc[ms][ns][hf * 2] * nrm;
                float v1 = acc[ms][ns][hf * 2 + 1] * nrm;
                float p0 = __shfl_xor_sync(0xffffffffu, v0, 1);
                float p1 = __shfl_xor_sync(0xffffffffu, v1, 1);
                if (((tg & 1) == 0) && dn >= 0)
                    red_add_v4(g_kg + (size_t)dn * DIM + n0w + ns * 8 + 2 * tg, v0, v1, p0, p1);
            }
        }
    }
}

// ------------- fused S/K hyperedge accumulation: acc[he] += kg[node] -------------
__global__ void k_scatter_acc2(const int* __restrict__ snod, const int* __restrict__ sedg,
                               const int* __restrict__ knod, const int* __restrict__ kedg) {
    int w = (blockIdx.x * blockDim.x + threadIdx.x) >> 5;
    int lane = threadIdx.x & 31;
    const int* nodes; const int* edges; float* accum;
    if (w < NP) { nodes = snod; edges = sedg; accum = g_accS; }
    else { w -= NP; if (w >= NP) return; nodes = knod; edges = kedg; accum = g_accK; }
    float4 v = *reinterpret_cast<const float4*>(&g_kg[(size_t)nodes[w] * DIM + lane * 4]);
    red_add_v4(accum + (size_t)edges[w] * DIM + lane * 4, v.x, v.y, v.z, v.w);
}

// fused S/K edge-feature GEMMs: ef = (acc @ theta) / b_deg
__global__ void __launch_bounds__(256) k_gemm_ef2() {
    __shared__ unsigned Ah[128][20], Al[128][20], Bh[128][20], Bl[128][20];
    int b = blockIdx.x;
    if (b < EFB) gemm_body(Ah, Al, Bh, Bl, g_accS, 13, nullptr, g_efS, NHYP, g_bdegS, b);
    else gemm_body(Ah, Al, Bh, Bl, g_accK, 14, nullptr, g_efK, NHYP, g_bdegK, b - EFB);
}

// fused S/K node scatter (flag-masked)
__global__ void k_scatter_node2(const int* __restrict__ snod, const int* __restrict__ sedg,
                                const int* __restrict__ knod, const int* __restrict__ kedg) {
    int w = (blockIdx.x * blockDim.x + threadIdx.x) >> 5;
    int lane = threadIdx.x & 31;
    const int* nodes; const int* edges; const int* flag; const float* ef; float* no;
    if (w < NP) { nodes = snod; edges = sedg; flag = g_flagS; ef = g_efS; no = g_noS; }
    else { w -= NP; if (w >= NP) return; nodes = knod; edges = kedg; flag = g_flagK; ef = g_efK; no = g_noK; }
    int n = nodes[w];
    if (!flag[n]) return;
    float4 v = *reinterpret_cast<const float4*>(ef + (size_t)edges[w] * DIM + lane * 4);
    red_add_v4(no + (size_t)n * DIM + lane * 4, v.x, v.y, v.z, v.w);
}

// fused gathers: related + context
__global__ void k_gather(const int* __restrict__ sidx, const int* __restrict__ kidx,
                         const float* __restrict__ biasS, const float* __restrict__ biasK,
                         const int* __restrict__ cidx) {
    int i = blockIdx.x * blockDim.x + threadIdx.x;
    if (i < NB * LKV * DIM) {
        int d = i & 127, l = (i >> 7) & 127, b = i >> 14;
        float v;
        if (l < LREL) {
            int n = sidx[b * LREL + l]; int dd = g_ddegS[n];
            v = g_noS[(size_t)n * DIM + d] * (dd > 0 ? 1.f / dd : 0.f) + biasS[d];
        } else {
            int n = kidx[b * LREL + l - LREL]; int dd = g_ddegK[n];
            v = g_noK[(size_t)n * DIM + d] * (dd > 0 ? 1.f / dd : 0.f) + biasK[d];
        }
        g_related[i] = v;
        return;
    }
    int j = i - NB * LKV * DIM;
    if (j < NB * LCTX * DIM)
        g_context[j] = g_kg[(size_t)cidx[j >> 7] * DIM + (j & 127)];
}

// fused Q/K/V projections
__global__ void __launch_bounds__(256) k_qkv(const float* __restrict__ ipb) {
    __shared__ unsigned Ah[128][20], Al[128][20], Bh[128][20], Bl[128][20];
    int b = blockIdx.x;
    if (b < 16) gemm_body(Ah, Al, Bh, Bl, g_context, 15, ipb, g_qh, NB * LCTX, nullptr, b);
    else if (b < 80) gemm_body(Ah, Al, Bh, Bl, g_related, 16, ipb + DIM, g_kh, NB * LKV, nullptr, b - 16);
    else gemm_body(Ah, Al, Bh, Bl, g_related, 17, ipb + 2 * DIM, g_vh, NB * LKV, nullptr, b - 80);
}

// ---------------- attention ----------------
__global__ void k_mha() {
    int b = blockIdx.x / NHEAD, h = blockIdx.x % NHEAD;
    __shared__ float ks[LKV][HDIM], vs[LKV][HDIM];
    int t = threadIdx.x;
    for (int i = t; i < LKV * HDIM; i += 32) {
        int k = i / HDIM, d = i % HDIM;
        size_t off = ((size_t)b * LKV + k) * DIM + h * HDIM + d;
        ks[k][d] = g_kh[off]; vs[k][d] = g_vh[off];
    }
    __syncwarp();
    float q[HDIM];
    size_t qoff = ((size_t)b * LCTX + t) * DIM + h * HDIM;
#pragma unroll
    for (int d = 0; d < HDIM; d++) q[d] = g_qh[qoff + d];
    float lg[LKV], mx = -1e30f;
    for (int k = 0; k < LKV; k++) {
        float s = 0.f;
#pragma unroll
        for (int d = 0; d < HDIM; d++) s += q[d] * ks[k][d];
        s *= 0.25f; lg[k] = s; mx = fmaxf(mx, s);
    }
    float sum = 0.f;
    for (int k = 0; k < LKV; k++) { lg[k] = expf(lg[k] - mx); sum += lg[k]; }
    float inv = 1.f / sum;
    float acc[HDIM];
#pragma unroll
    for (int d = 0; d < HDIM; d++) acc[d] = 0.f;
    for (int k = 0; k < LKV; k++) {
        float w = lg[k];
#pragma unroll
        for (int d = 0; d < HDIM; d++) acc[d] += w * vs[k][d];
    }
#pragma unroll
    for (int d = 0; d < HDIM; d++) g_o[qoff + d] = acc[d] * inv;
}

__global__ void k_selfattn(const float* __restrict__ h, const float* __restrict__ t1,
                           const float* __restrict__ bvec, float* __restrict__ out, int L) {
    int b = blockIdx.x, t = threadIdx.x;
    __shared__ float w[40];
    if (t < L) {
        float e = 0.f;
        const float* tp = t1 + ((size_t)b * L + t) * DIM;
        for (int d = 0; d < DIM; d++) e += tanhf(tp[d]) * bvec[d];
        w[t] = e;
    }
    __syncthreads();
    float mx = -1e30f;
    for (int l = 0; l < L; l++) mx = fmaxf(mx, w[l]);
    float sum = 0.f;
    for (int l = 0; l < L; l++) sum += expf(w[l] - mx);
    float inv = 1.f / sum, acc = 0.f;
    for (int l = 0; l < L; l++) acc += expf(w[l] - mx) * h[((size_t)b * L + l) * DIM + t];
    out[(size_t)b * DIM + t] = acc * inv;
}

__global__ void k_ucat() {
    int i = blockIdx.x * blockDim.x + threadIdx.x;
    if (i >= NB * 33 * DIM) return;
    int d = i & 127, l = (i >> 7) % 33, b = i / (33 * DIM);
    g_ucat[i] = (l < 32) ? g_context[((size_t)b * 32 + l) * DIM + d] : g_his[(size_t)b * DIM + d];
}

// ------------- scores via tensor cores, coalesced epilogue -------------
__global__ void __launch_bounds__(128) k_scores_mma(const float* __restrict__ rb,
                                                    float* __restrict__ out) {
    __shared__ unsigned Ah[128][20], Al[128][20], Bh[64][20], Bl[64][20];
    __shared__ float st[128][33];
    const int t = threadIdx.x, lane = t & 31, warp = t >> 5;
    const int m0w = warp * 32;
    const int blkM = blockIdx.x * 128;
    const unsigned* Bhg = g_Bh + 21 * MATW;
    const unsigned* Blg = g_Bl + 21 * MATW;
    float acc[2][8][4];
#pragma unroll
    for (int i = 0; i < 2; i++)
#pragma unroll
        for (int j = 0; j < 8; j++)
#pragma unroll
            for (int q = 0; q < 4; q++) acc[i][j][q] = 0.f;

    for (int k0 = 0; k0 < 128; k0 += 32) {
        int gm = blkM + t;
        if (gm < NN) {
            const float4* ap = reinterpret_cast<const float4*>(g_kg + (size_t)gm * DIM + k0);
            conv_store_row(ap, 1.0f, &Ah[t][0], &Al[t][0]);
            conv_store_row(ap + 4, 1.0f, &Ah[t][8], &Al[t][8]);
        } else {
            uint4 z = make_uint4(0, 0, 0, 0);
#pragma unroll
            for (int q = 0; q < 4; q++) {
                *reinterpret_cast<uint4*>(&Ah[t][4 * q]) = z;
                *reinterpret_cast<uint4*>(&Al[t][4 * q]) = z;
            }
        }
        {
            int nB = t & 63, hB = (t >> 6) * 8;
            const unsigned* sh = Bhg + nB * 64 + k0 / 2 + hB;
            const unsigned* sl = Blg + nB * 64 + k0 / 2 + hB;
            *reinterpret_cast<uint4*>(&Bh[nB][hB])     = *reinterpret_cast<const uint4*>(sh);
            *reinterpret_cast<uint4*>(&Bh[nB][hB + 4]) = *reinterpret_cast<const uint4*>(sh + 4);
            *reinterpret_cast<uint4*>(&Bl[nB][hB])     = *reinterpret_cast<const uint4*>(sl);
            *reinterpret_cast<uint4*>(&Bl[nB][hB + 4]) = *reinterpret_cast<const uint4*>(sl + 4);
        }
        __syncthreads();
        bf_chunk(Ah, Al, Bh, Bl, acc, lane, m0w, 0);
        __syncthreads();
    }
    const int gr = lane >> 2, tg = lane & 3;
    int gmn = blkM + t;
    float rv = (gmn < NN) ? rb[gmn] : 0.f;
#pragma unroll
    for (int halfc = 0; halfc < 2; halfc++) {
        __syncthreads();
#pragma unroll
        for (int ms = 0; ms < 2; ms++) {
#pragma unroll
            for (int hf = 0; hf < 2; hf++) {
                int row = m0w + ms * 16 + gr + hf * 8;
#pragma unroll
                for (int ns = 0; ns < 4; ns++) {
                    int nsg = halfc * 4 + ns;
                    st[row][ns * 8 + 2 * tg]     = acc[ms][nsg][hf * 2];
                    st[row][ns * 8 + 2 * tg + 1] = acc[ms][nsg][hf * 2 + 1];
                }
            }
        }
        __syncthreads();
        if (gmn < NN) {
#pragma unroll
            for (int c = 0; c < 32; c++)
                out[(size_t)(halfc * 32 + c) * NN + gmn] = st[t][c] + rv;
        }
    }
}

// ---------------- host ----------------
static void* sym(const void* s) { void* p = nullptr; cudaGetSymbolAddress(&p, s); return p; }

extern "C" void kernel_launch(void* const* d_in, const int* in_sizes, int n_in,
                              void* d_out, int out_size) {
    const float* emb   = (const float*)d_in[0];
    const float* bases = (const float*)d_in[1];
    const float* comp  = (const float*)d_in[2];
    const float* root  = (const float*)d_in[3];
    const float* rbias = (const float*)d_in[4];
    const float* sth   = (const float*)d_in[5];
    const float* sbi   = (const float*)d_in[6];
    const float* kth   = (const float*)d_in[7];
    const float* kbi   = (const float*)d_in[8];
    const float* ipw   = (const float*)d_in[9];
    const float* ipb   = (const float*)d_in[10];
    const float* opw   = (const float*)d_in[11];
    const float* opb   = (const float*)d_in[12];
    const float* aha   = (const float*)d_in[13];
    const float* ahb   = (const float*)d_in[14];
    const float* aa    = (const float*)d_in[15];
    const float* ab    = (const float*)d_in[16];
    const float* recb  = (const float*)d_in[17];
    const int* esrc = (const int*)d_in[18];
    const int* edst = (const int*)d_in[19];
    const int* ety  = (const int*)d_in[20];
    const int* snod = (const int*)d_in[21];
    const int* sedg = (const int*)d_in[22];
    const int* knod = (const int*)d_in[23];
    const int* kedg = (const int*)d_in[24];
    const int* sri  = (const int*)d_in[25];
    const int* kri  = (const int*)d_in[26];
    const int* cxi  = (const int*)d_in[27];
    float* out = (float*)d_out;

    cudaFuncSetAttribute(k_edge_gemm, cudaFuncAttributeMaxDynamicSharedMemorySize, EDGE_SMEM);

    cudaMemsetAsync(sym(g_cnt), 0, (size_t)NN * NREL * 4, 0);
    cudaMemsetAsync(sym(g_typeCnt), 0, NREL * 4, 0);
    cudaMemsetAsync(sym(g_cursor), 0, NREL * 4, 0);
    cudaMemsetAsync(sym(g_bdegS), 0, NHYP * 4, 0);
    cudaMemsetAsync(sym(g_bdegK), 0, NHYP * 4, 0);
    cudaMemsetAsync(sym(g_ddegS), 0, (size_t)NN * 4, 0);
    cudaMemsetAsync(sym(g_ddegK), 0, (size_t)NN * 4, 0);
    cudaMemsetAsync(sym(g_accS), 0, (size_t)NHYP * DIM * 4, 0);
    cudaMemsetAsync(sym(g_accK), 0, (size_t)NHYP * DIM * 4, 0);
    cudaMemsetAsync(sym(g_flagS), 0, (size_t)NN * 4, 0);
    cudaMemsetAsync(sym(g_flagK), 0, (size_t)NN * 4, 0);

    k_prep<<<(21 * MATW + 255) / 256, 256>>>(bases, comp, root, sth, kth, ipw, opw, aha, aa);

    // F1: root GEMM || edge count || hyper counts || flags || pack X
    k_fuse1<<<ROOTB + COUNTB + 2 * HCB + 2 * FLAGB + PACKB, 256>>>(
        emb, rbias, edst, ety, snod, sedg, knod, kedg, sri, kri);
    k_sort<<<(NEDGE + 255) / 256, 256>>>(ety);
    k_edge_gemm<<<EDGE_TILES, 256, EDGE_SMEM>>>(esrc, edst);

    // hypergraphs (linearity: scatter kg, then small GEMM with 1/b_deg)
    k_scatter_acc2<<<(2 * NP * 32) / 256, 256>>>(snod, sedg, knod, kedg);
    k_gemm_ef2<<<2 * EFB, 256>>>();
    k_scatter_node2<<<(2 * NP * 32) / 256, 256>>>(snod, sedg, knod, kedg);

    k_gather<<<(NB * LKV * DIM + NB * LCTX * DIM + 255) / 256, 256>>>(sri, kri, sbi, kbi, cxi);

    // MHA
    k_qkv<<<144, 256>>>(ipb);
    k_mha<<<NB * NHEAD, 32>>>();
    k_gemm128b<<<16, 256>>>((float*)sym(g_o), 18, opb, (float*)sym(g_attrel), NB * LCTX);

    // his self-attn
    k_gemm128b<<<16, 256>>>((float*)sym(g_attrel), 19, nullptr, (float*)sym(g_t1), NB * LCTX);
    k_selfattn<<<NB, 128>>>((float*)sym(g_attrel), (float*)sym(g_t1), ahb,
                            (float*)sym(g_his), LCTX);

    // user self-attn over [context, his]
    k_ucat<<<(NB * 33 * DIM + 255) / 256, 256>>>();
    k_gemm128b<<<17, 256>>>((float*)sym(g_ucat), 20, nullptr, (float*)sym(g_t2), NB * 33);
    k_selfattn<<<NB, 128>>>((float*)sym(g_ucat), (float*)sym(g_t2), ab,
                            (float*)sym(g_user), 33);

    // scores on tensor cores
    k_packU<<<(MATW + 255) / 256, 256>>>();
    k_scores_mma<<<(NN + 127) / 128, 128>>>(recb, out);
}

// round 13
// speedup vs baseline: 1.7279x; 1.0266x over previous
#include <cuda_runtime.h>
#include <cuda_bf16.h>
#include <math.h>

#define NN 100000
#define DIM 128
#define NREL 12
#define NBASES 8
#define NEDGE 1000000
#define NP 400000
#define NHYP 20000
#define NB 64
#define LREL 64
#define LKV 128
#define LCTX 32
#define NHEAD 8
#define HDIM 16
#define EDGE_TILES 7830
#define NMAT 22
#define MATW 8192   // 128 rows x 64 packed words per matrix

#define ROOTB 782
#define COUNTB 3907
#define HCB 1563
#define FLAGB 16
#define PACKB 3125
#define EFB 157

// edge kernel double-buffered smem: 8 x 128 x 20 words = 81920 bytes
#define EDGE_SMEM 81920

// ---------------- single zeroed region ----------------
// words: cnt 1.2M | typeCnt 12 | cursor 12 | bdegS 20K | bdegK 20K |
//        ddegS 100K | ddegK 100K | flagS 100K | flagK 100K | accS 2.56M | accK 2.56M
#define ZW_TOTAL 6760024
__device__ __align__(16) int g_Z[ZW_TOTAL];
#define g_cnt     (g_Z)
#define g_typeCnt (g_Z + 1200000)
#define g_cursor  (g_Z + 1200012)
#define g_bdegS   (g_Z + 1200024)
#define g_bdegK   (g_Z + 1220024)
#define g_ddegS   (g_Z + 1240024)
#define g_ddegK   (g_Z + 1340024)
#define g_flagS   (g_Z + 1440024)
#define g_flagK   (g_Z + 1540024)
#define g_accS    ((float*)(g_Z + 1640024))
#define g_accK    ((float*)(g_Z + 4200024))

__device__ __forceinline__ void red_add_v4(float* p, float x, float y, float z, float w) {
    asm volatile("red.global.add.v4.f32 [%0], {%1,%2,%3,%4};"
                 :: "l"(p), "f"(x), "f"(y), "f"(z), "f"(w) : "memory");
}

// split two fp32 into packed bf16x2 hi word + lo word
__device__ __forceinline__ unsigned pack_split(float x0, float x1, unsigned& lo) {
    __nv_bfloat16 h0 = __float2bfloat16(x0), h1 = __float2bfloat16(x1);
    float r0 = x0 - __bfloat162float(h0), r1 = x1 - __bfloat162float(h1);
    __nv_bfloat16 l0 = __float2bfloat16(r0), l1 = __float2bfloat16(r1);
    lo = (unsigned)__bfloat16_as_ushort(l0) | ((unsigned)__bfloat16_as_ushort(l1) << 16);
    return (unsigned)__bfloat16_as_ushort(h0) | ((unsigned)__bfloat16_as_ushort(h1) << 16);
}

__device__ __forceinline__ void mma16(float* c, const unsigned* a, const unsigned* b) {
    asm("mma.sync.aligned.m16n8k16.row.col.f32.bf16.bf16.f32 "
        "{%0,%1,%2,%3}, {%4,%5,%6,%7}, {%8,%9}, {%0,%1,%2,%3};"
        : "+f"(c[0]), "+f"(c[1]), "+f"(c[2]), "+f"(c[3])
        : "r"(a[0]), "r"(a[1]), "r"(a[2]), "r"(a[3]), "r"(b[0]), "r"(b[1]));
}

__device__ __forceinline__ void ldsm4(unsigned* r, const unsigned* p) {
    unsigned addr = (unsigned)__cvta_generic_to_shared(const_cast<unsigned*>(p));
    asm volatile("ldmatrix.sync.aligned.m8n8.x4.shared.b16 {%0,%1,%2,%3}, [%4];"
                 : "=r"(r[0]), "=r"(r[1]), "=r"(r[2]), "=r"(r[3]) : "r"(addr));
}

// ---------------- device scratch ----------------
__device__ unsigned g_Bh[NMAT * MATW];
__device__ unsigned g_Bl[NMAT * MATW];
__device__ unsigned g_Xh[NN * 64];
__device__ unsigned g_Xl[NN * 64];
__device__ float g_kg[NN * DIM];
__device__ int   g_sorted[NEDGE];
__device__ float g_efS[NHYP * DIM], g_efK[NHYP * DIM];
__device__ float g_noS[NN * DIM], g_noK[NN * DIM];
__device__ float g_related[NB * LKV * DIM];
__device__ float g_context[NB * LCTX * DIM];
__device__ float g_qh[NB * LCTX * DIM];
__device__ float g_kh[NB * LKV * DIM];
__device__ float g_vh[NB * LKV * DIM];
__device__ float g_o[NB * LCTX * DIM];
__device__ float g_attrel[NB * LCTX * DIM];
__device__ float g_t1[NB * LCTX * DIM];
__device__ float g_t2ctx[NB * LCTX * DIM];
__device__ float g_his[NB * DIM];
__device__ float g_user[NB * DIM];
__device__ float g_v1[DIM];

// ---------------- prep: pack 21 static B-matrices (W and M1 computed inline) ----------------
__global__ void k_prep(const float* __restrict__ bases, const float* __restrict__ comp,
                       const float* __restrict__ root, const float* __restrict__ sth,
                       const float* __restrict__ kth, const float* __restrict__ ipw,
                       const float* __restrict__ opw, const float* __restrict__ aha,
                       const float* __restrict__ aa, const float* __restrict__ opb) {
    int idx = blockIdx.x * blockDim.x + threadIdx.x;
    if (idx >= 21 * MATW) {
        int n = idx - 21 * MATW;
        if (n < DIM) {
            float s = 0.f;
            for (int j = 0; j < DIM; j++) s = fmaf(opb[j], aha[j * DIM + n], s);
            g_v1[n] = s;
        }
        return;
    }
    int m = idx >> 13, rem = idx & (MATW - 1), n = rem >> 6, k2 = rem & 63;
    float s0, s1;
    if (m < 12) {
        const float* cp = comp + m * NBASES;
        s0 = 0.f; s1 = 0.f;
#pragma unroll
        for (int b = 0; b < NBASES; b++) {
            const float* bp = bases + (size_t)b * DIM * DIM + (2 * k2) * DIM + n;
            s0 = fmaf(cp[b], bp[0], s0);
            s1 = fmaf(cp[b], bp[DIM], s1);
        }
    } else if (m == 19) {
        // M1[k][n] = sum_j opw[j][k] * aha[j][n]  (t1 = o @ M1 + v1)
        s0 = 0.f; s1 = 0.f;
        for (int j = 0; j < DIM; j++) {
            float av = aha[j * DIM + n];
            s0 = fmaf(opw[j * DIM + 2 * k2],     av, s0);
            s1 = fmaf(opw[j * DIM + 2 * k2 + 1], av, s1);
        }
    } else {
        const float* b; int tr = 0;
        switch (m) {
            case 12: b = root; break;
            case 13: b = sth; break;
            case 14: b = kth; break;
            case 15: b = ipw; tr = 1; break;
            case 16: b = ipw + DIM * DIM; tr = 1; break;
            case 17: b = ipw + 2 * DIM * DIM; tr = 1; break;
            case 18: b = opw; tr = 1; break;
            default: b = aa; break;
        }
        if (tr) { s0 = b[n * DIM + 2 * k2]; s1 = b[n * DIM + 2 * k2 + 1]; }
        else    { s0 = b[(2 * k2) * DIM + n]; s1 = b[(2 * k2 + 1) * DIM + n]; }
    }
    unsigned lo, hi = pack_split(s0, s1, lo);
    g_Bh[idx] = hi; g_Bl[idx] = lo;
}

// counting sort with block aggregation; per-block prefix from g_typeCnt
__global__ void k_sort(const int* __restrict__ ty) {
    __shared__ int h[NREL], base[NREL];
    int t = threadIdx.x;
    if (t < NREL) h[t] = 0;
    __syncthreads();
    int e = blockIdx.x * blockDim.x + t;
    int tt = -1, loc = 0;
    if (e < NEDGE) { tt = ty[e]; loc = atomicAdd(&h[tt], 1); }
    __syncthreads();
    if (t < NREL) {
        int off = 0;
        for (int i = 0; i < t; i++) off += g_typeCnt[i];
        base[t] = off + (h[t] ? atomicAdd(&g_cursor[t], h[t]) : 0);
    }
    __syncthreads();
    if (e < NEDGE) g_sorted[base[tt] + loc] = e;
}

// bf16x2 3-term compute over one K32 chunk (ldmatrix fragment loads)
__device__ __forceinline__ void bf_chunk(
    const unsigned (*Ah)[20], const unsigned (*Al)[20],
    const unsigned (*Bh)[20], const unsigned (*Bl)[20],
    float acc[2][8][4], int lane, int m0, int n0) {
    const int ar = lane & 15, ac = (lane >> 4) * 4;
    const int br = (lane & 7) | ((lane >> 4) << 3), bc = ((lane >> 3) & 1) * 4;
#pragma unroll
    for (int s = 0; s < 2; s++) {
        const int kb = s * 8;
        unsigned bh[8][2], bl[8][2];
#pragma unroll
        for (int np = 0; np < 4; np++) {
            unsigned r4[4];
            ldsm4(r4, &Bh[n0 + np * 16 + br][kb + bc]);
            bh[2*np][0] = r4[0]; bh[2*np][1] = r4[1];
            bh[2*np+1][0] = r4[2]; bh[2*np+1][1] = r4[3];
            ldsm4(r4, &Bl[n0 + np * 16 + br][kb + bc]);
            bl[2*np][0] = r4[0]; bl[2*np][1] = r4[1];
            bl[2*np+1][0] = r4[2]; bl[2*np+1][1] = r4[3];
        }
#pragma unroll
        for (int ms = 0; ms < 2; ms++) {
            unsigned ah[4], al[4];
            ldsm4(ah, &Ah[m0 + ms * 16 + ar][kb + ac]);
            ldsm4(al, &Al[m0 + ms * 16 + ar][kb + ac]);
#pragma unroll
            for (int ns = 0; ns < 8; ns++) {
                mma16(acc[ms][ns], ah, bh[ns]);
                mma16(acc[ms][ns], ah, bl[ns]);
                mma16(acc[ms][ns], al, bh[ns]);
            }
        }
    }
}

// convert 16 fp32 (scaled) -> 8 hi + 8 lo packed words
__device__ __forceinline__ void conv_store_row(const float4* ap, float scale,
                                               unsigned* dh, unsigned* dl) {
    unsigned hw[8], lw[8];
#pragma unroll
    for (int q = 0; q < 4; q++) {
        float4 v = ap[q];
        v.x *= scale; v.y *= scale; v.z *= scale; v.w *= scale;
        hw[2*q]   = pack_split(v.x, v.y, lw[2*q]);
        hw[2*q+1] = pack_split(v.z, v.w, lw[2*q+1]);
    }
    *reinterpret_cast<uint4*>(dh)     = make_uint4(hw[0], hw[1], hw[2], hw[3]);
    *reinterpret_cast<uint4*>(dh + 4) = make_uint4(hw[4], hw[5], hw[6], hw[7]);
    *reinterpret_cast<uint4*>(dl)     = make_uint4(lw[0], lw[1], lw[2], lw[3]);
    *reinterpret_cast<uint4*>(dl + 4) = make_uint4(lw[4], lw[5], lw[6], lw[7]);
}

// ------------- generic GEMM body: C[M,128] = A[M,128] @ B(mat) (+bias, row scale 1/deg) ----
__device__ __forceinline__ void gemm_body(
    unsigned (*Ah)[20], unsigned (*Al)[20], unsigned (*Bh)[20], unsigned (*Bl)[20],
    const float* __restrict__ A, int mat, const float* __restrict__ bias,
    float* __restrict__ C, int M, const int* __restrict__ rowdeg, int blk) {
    const int t = threadIdx.x, lane = t & 31, warp = t >> 5;
    const int m0w = (warp & 3) * 32, n0w = (warp >> 2) * 64;
    const int blkM = blk * 128;
    const unsigned* Bhg = g_Bh + mat * MATW;
    const unsigned* Blg = g_Bl + mat * MATW;
    float acc[2][8][4];
#pragma unroll
    for (int i = 0; i < 2; i++)
#pragma unroll
        for (int j = 0; j < 8; j++)
#pragma unroll
            for (int q = 0; q < 4; q++) acc[i][j][q] = 0.f;
    const int mA = t >> 1, half = t & 1;
    const int nB = t >> 1, hB = (t & 1) * 8;

    for (int k0 = 0; k0 < 128; k0 += 32) {
        int gm = blkM + mA;
        if (gm < M) {
            const float4* ap = reinterpret_cast<const float4*>(A + (size_t)gm * DIM + k0 + half * 16);
            conv_store_row(ap, 1.0f, &Ah[mA][half * 8], &Al[mA][half * 8]);
        } else {
            uint4 z = make_uint4(0, 0, 0, 0);
            *reinterpret_cast<uint4*>(&Ah[mA][half*8]) = z;
            *reinterpret_cast<uint4*>(&Ah[mA][half*8+4]) = z;
            *reinterpret_cast<uint4*>(&Al[mA][half*8]) = z;
            *reinterpret_cast<uint4*>(&Al[mA][half*8+4]) = z;
        }
        {
            const unsigned* sh = Bhg + nB * 64 + k0 / 2 + hB;
            const unsigned* sl = Blg + nB * 64 + k0 / 2 + hB;
            *reinterpret_cast<uint4*>(&Bh[nB][hB])     = *reinterpret_cast<const uint4*>(sh);
            *reinterpret_cast<uint4*>(&Bh[nB][hB + 4]) = *reinterpret_cast<const uint4*>(sh + 4);
            *reinterpret_cast<uint4*>(&Bl[nB][hB])     = *reinterpret_cast<const uint4*>(sl);
            *reinterpret_cast<uint4*>(&Bl[nB][hB + 4]) = *reinterpret_cast<const uint4*>(sl + 4);
        }
        __syncthreads();
        bf_chunk(Ah, Al, Bh, Bl, acc, lane, m0w, n0w);
        __syncthreads();
    }
    const int gr = lane >> 2, tg = lane & 3;
#pragma unroll
    for (int ms = 0; ms < 2; ms++) {
#pragma unroll
        for (int hf = 0; hf < 2; hf++) {
            int gm = blkM + m0w + ms * 16 + gr + hf * 8;
            if (gm < M) {
                float scale = 1.f;
                if (rowdeg) { int dg = rowdeg[gm]; scale = dg > 0 ? 1.f / (float)dg : 0.f; }
                float* cp = C + (size_t)gm * DIM;
#pragma unroll
                for (int ns = 0; ns < 8; ns++) {
                    int col = n0w + ns * 8 + 2 * tg;
                    float b0 = bias ? bias[col] : 0.f;
                    float b1 = bias ? bias[col + 1] : 0.f;
                    float2 v = make_float2(acc[ms][ns][hf * 2] * scale + b0,
                                           acc[ms][ns][hf * 2 + 1] * scale + b1);
                    *reinterpret_cast<float2*>(cp + col) = v;
                }
            }
        }
    }
}

// ------------- F1: root GEMM || edge count || hyper counts || flags || pack X -------------
__global__ void __launch_bounds__(256) k_fuse1(
    const float* __restrict__ emb, const float* __restrict__ rbias,
    const int* __restrict__ edst, const int* __restrict__ ety,
    const int* __restrict__ snod, const int* __restrict__ sedg,
    const int* __restrict__ knod, const int* __restrict__ kedg,
    const int* __restrict__ sri, const int* __restrict__ kri) {
    __shared__ unsigned Ah[128][20], Al[128][20], Bh[128][20], Bl[128][20];
    __shared__ int fh[NREL];
    int b = blockIdx.x;
    int t = threadIdx.x;
    if (b < ROOTB) {
        gemm_body(Ah, Al, Bh, Bl, emb, 12, rbias, g_kg, NN, nullptr, b);
        return;
    }
    b -= ROOTB;
    if (b < COUNTB) {
        if (t < NREL) fh[t] = 0;
        __syncthreads();
        int e = b * 256 + t;
        if (e < NEDGE) {
            int tt = ety[e];
            atomicAdd(&g_cnt[edst[e] * NREL + tt], 1);
            atomicAdd(&fh[tt], 1);
        }
        __syncthreads();
        if (t < NREL && fh[t]) atomicAdd(&g_typeCnt[t], fh[t]);
        return;
    }
    b -= COUNTB;
    if (b < 2 * HCB) {
        const int* nodes; const int* edges; int* bdeg; int* ddeg;
        int lb = b;
        if (lb < HCB) { nodes = snod; edges = sedg; bdeg = g_bdegS; ddeg = g_ddegS; }
        else { lb -= HCB; nodes = knod; edges = kedg; bdeg = g_bdegK; ddeg = g_ddegK; }
        int p = lb * 256 + t;
        if (p < NP) {
            atomicAdd(&bdeg[edges[p]], 1);
            atomicAdd(&ddeg[nodes[p]], 1);
        }
        return;
    }
    b -= 2 * HCB;
    if (b < 2 * FLAGB) {
        const int* idx; int* flag; float* no;
        int lb = b;
        if (lb < FLAGB) { idx = sri; flag = g_flagS; no = g_noS; }
        else { lb -= FLAGB; idx = kri; flag = g_flagK; no = g_noK; }
        int i = lb * 256 + t;
        if (i < NB * LREL) {
            int n = idx[i];
            flag[n] = 1;
            float4 z = make_float4(0.f, 0.f, 0.f, 0.f);
            float4* p = reinterpret_cast<float4*>(no + (size_t)n * DIM);
#pragma unroll
            for (int d = 0; d < DIM / 4; d++) p[d] = z;
        }
        return;
    }
    b -= 2 * FLAGB;
    {
        int i = b * 256 + t;
        if (i < NN * 8) {
            int n = i >> 3, part = i & 7;
            const float4* ap = reinterpret_cast<const float4*>(emb + (size_t)n * DIM + part * 16);
            conv_store_row(ap, 1.0f, &g_Xh[(size_t)n * 64 + part * 8],
                           &g_Xl[(size_t)n * 64 + part * 8]);
        }
    }
}

// ------------- RGCN edge GEMM (pre-packed A, double-buffered pipeline) -------------
__global__ void __launch_bounds__(256) k_edge_gemm(
    const int* __restrict__ esrc, const int* __restrict__ edst) {
    extern __shared__ unsigned dsm[];
    unsigned (*Ah)[20] = (unsigned(*)[20])dsm;
    unsigned (*Al)[20] = (unsigned(*)[20])(dsm + 2 * 128 * 20);
    unsigned (*Bh)[20] = (unsigned(*)[20])(dsm + 4 * 128 * 20);
    unsigned (*Bl)[20] = (unsigned(*)[20])(dsm + 6 * 128 * 20);
    __shared__ int   sSrc[128], sDst[128];
    __shared__ float sNorm[128];
    const int bid = blockIdx.x;
    int r = -1, base = 0, cnt = 0;
    {
        int off = 0, toff = 0;
#pragma unroll
        for (int i = 0; i < NREL; i++) {
            int c = g_typeCnt[i];
            int nt = (c + 127) >> 7;
            if (r < 0 && bid < toff + nt) {
                int local = bid - toff;
                r = i; base = off + local * 128;
                cnt = c - local * 128; if (cnt > 128) cnt = 128;
            }
            off += c; toff += nt;
        }
    }
    if (r < 0) return;
    const int t = threadIdx.x, lane = t & 31, warp = t >> 5;
    const int m0w = (warp & 3) * 32, n0w = (warp >> 2) * 64;
    if (t < 128) {
        if (t < cnt) {
            int e = g_sorted[base + t];
            int d = edst[e];
            sSrc[t] = esrc[e]; sDst[t] = d;
            sNorm[t] = 1.0f / fmaxf((float)g_cnt[d * NREL + r], 1.0f);
        } else { sSrc[t] = 0; sDst[t] = -1; sNorm[t] = 0.f; }
    }
    __syncthreads();

    const int mA = t >> 1, half = t & 1;
    const unsigned* Bhg = g_Bh + (size_t)r * MATW;
    const unsigned* Blg = g_Bl + (size_t)r * MATW;

    auto stage = [&](int buf, int k0) {
        int ro = buf * 128 + mA;
        size_t xoff = (size_t)sSrc[mA] * 64 + k0 / 2 + half * 8;
        const unsigned* xh = g_Xh + xoff;
        const unsigned* xl = g_Xl + xoff;
        *reinterpret_cast<uint4*>(&Ah[ro][half*8])     = *reinterpret_cast<const uint4*>(xh);
        *reinterpret_cast<uint4*>(&Ah[ro][half*8 + 4]) = *reinterpret_cast<const uint4*>(xh + 4);
        *reinterpret_cast<uint4*>(&Al[ro][half*8])     = *reinterpret_cast<const uint4*>(xl);
        *reinterpret_cast<uint4*>(&Al[ro][half*8 + 4]) = *reinterpret_cast<const uint4*>(xl + 4);
        size_t boff = (size_t)mA * 64 + k0 / 2 + half * 8;
        const unsigned* bh = Bhg + boff;
        const unsigned* bl = Blg + boff;
        *reinterpret_cast<uint4*>(&Bh[ro][half*8])     = *reinterpret_cast<const uint4*>(bh);
        *reinterpret_cast<uint4*>(&Bh[ro][half*8 + 4]) = *reinterpret_cast<const uint4*>(bh + 4);
        *reinterpret_cast<uint4*>(&Bl[ro][half*8])     = *reinterpret_cast<const uint4*>(bl);
        *reinterpret_cast<uint4*>(&Bl[ro][half*8 + 4]) = *reinterpret_cast<const uint4*>(bl + 4);
    };

    float acc[2][8][4];
#pragma unroll
    for (int i = 0; i < 2; i++)
#pragma unroll
        for (int j = 0; j < 8; j++)
#pragma unroll
            for (int q = 0; q < 4; q++) acc[i][j][q] = 0.f;

    stage(0, 0);
    __syncthreads();
#pragma unroll
    for (int c = 0; c < 4; c++) {
        if (c < 3) stage((c + 1) & 1, (c + 1) * 32);
        int rb = (c & 1) * 128;
        bf_chunk(&Ah[rb], &Al[rb], &Bh[rb], &Bl[rb], acc, lane, m0w, n0w);
        __syncthreads();
    }

    const int gr = lane >> 2, tg = lane & 3;
#pragma unroll
    for (int ms = 0; ms < 2; ms++) {
#pragma unroll
        for (int hf = 0; hf < 2; hf++) {
            int rr = m0w + ms * 16 + gr + hf * 8;
            int dn = sDst[rr];
            float nrm = sNorm[rr];
#pragma unroll
            for (int ns = 0; ns < 8; ns++) {
                float v0 = acc[ms][ns][hf * 2] * nrm;
                float v1 = acc[ms][ns][hf * 2 + 1] * nrm;
                float p0 = __shfl_xor_sync(0xffffffffu, v0, 1);
                float p1 = __shfl_xor_sync(0xffffffffu, v1, 1);
                if (((tg & 1) == 0) && dn >= 0)
                    red_add_v4(g_kg + (size_t)dn * DIM + n0w + ns * 8 + 2 * tg, v0, v1, p0, p1);
            }
        }
    }
}

// ------------- fused S/K hyperedge accumulation: acc[he] += kg[node] -------------
__global__ void k_scatter_acc2(const int* __restrict__ snod, const int* __restrict__ sedg,
                               const int* __restrict__ knod, const int* __restrict__ kedg) {
    int w = (blockIdx.x * blockDim.x + threadIdx.x) >> 5;
    int lane = threadIdx.x & 31;
    const int* nodes; const int* edges; float* accum;
    if (w < NP) { nodes = snod; edges = sedg; accum = g_accS; }
    else { w -= NP; if (w >= NP) return; nodes = knod; edges = kedg; accum = g_accK; }
    float4 v = *reinterpret_cast<const float4*>(&g_kg[(size_t)nodes[w] * DIM + lane * 4]);
    red_add_v4(accum + (size_t)edges[w] * DIM + lane * 4, v.x, v.y, v.z, v.w);
}

// fused S/K edge-feature GEMMs: ef = (acc @ theta) / b_deg
__global__ void __launch_bounds__(256) k_gemm_ef2() {
    __shared__ unsigned Ah[128][20], Al[128][20], Bh[128][20], Bl[128][20];
    int b = blockIdx.x;
    if (b < EFB) gemm_body(Ah, Al, Bh, Bl, g_accS, 13, nullptr, g_efS, NHYP, g_bdegS, b);
    else gemm_body(Ah, Al, Bh, Bl, g_accK, 14, nullptr, g_efK, NHYP, g_bdegK, b - EFB);
}

// fused S/K node scatter (flag-masked)
__global__ void k_scatter_node2(const int* __restrict__ snod, const int* __restrict__ sedg,
                                const int* __restrict__ knod, const int* __restrict__ kedg) {
    int w = (blockIdx.x * blockDim.x + threadIdx.x) >> 5;
    int lane = threadIdx.x & 31;
    const int* nodes; const int* edges; const int* flag; const float* ef; float* no;
    if (w < NP) { nodes = snod; edges = sedg; flag = g_flagS; ef = g_efS; no = g_noS; }
    else { w -= NP; if (w >= NP) return; nodes = knod; edges = kedg; flag = g_flagK; ef = g_efK; no = g_noK; }
    int n = nodes[w];
    if (!flag[n]) return;
    float4 v = *reinterpret_cast<const float4*>(ef + (size_t)edges[w] * DIM + lane * 4);
    red_add_v4(no + (size_t)n * DIM + lane * 4, v.x, v.y, v.z, v.w);
}

// fused gathers: related + context
__global__ void k_gather(const int* __restrict__ sidx, const int* __restrict__ kidx,
                         const float* __restrict__ biasS, const float* __restrict__ biasK,
                         const int* __restrict__ cidx) {
    int i = blockIdx.x * blockDim.x + threadIdx.x;
    if (i < NB * LKV * DIM) {
        int d = i & 127, l = (i >> 7) & 127, b = i >> 14;
        float v;
        if (l < LREL) {
            int n = sidx[b * LREL + l]; int dd = g_ddegS[n];
            v = g_noS[(size_t)n * DIM + d] * (dd > 0 ? 1.f / dd : 0.f) + biasS[d];
        } else {
            int n = kidx[b * LREL + l - LREL]; int dd = g_ddegK[n];
            v = g_noK[(size_t)n * DIM + d] * (dd > 0 ? 1.f / dd : 0.f) + biasK[d];
        }
        g_related[i] = v;
        return;
    }
    int j = i - NB * LKV * DIM;
    if (j < NB * LCTX * DIM)
        g_context[j] = g_kg[(size_t)cidx[j >> 7] * DIM + (j & 127)];
}

// fused Q/K/V projections + context@aa
__global__ void __launch_bounds__(256) k_qkv(const float* __restrict__ ipb) {
    __shared__ unsigned Ah[128][20], Al[128][20], Bh[128][20], Bl[128][20];
    int b = blockIdx.x;
    if (b < 16) gemm_body(Ah, Al, Bh, Bl, g_context, 15, ipb, g_qh, NB * LCTX, nullptr, b);
    else if (b < 80) gemm_body(Ah, Al, Bh, Bl, g_related, 16, ipb + DIM, g_kh, NB * LKV, nullptr, b - 16);
    else if (b < 144) gemm_body(Ah, Al, Bh, Bl, g_related, 17, ipb + 2 * DIM, g_vh, NB * LKV, nullptr, b - 80);
    else gemm_body(Ah, Al, Bh, Bl, g_context, 20, nullptr, g_t2ctx, NB * LCTX, nullptr, b - 144);
}

// fused attrel-proj + t1 (independent given M1 precombination)
__global__ void __launch_bounds__(256) k_att2(const float* __restrict__ opb) {
    __shared__ unsigned Ah[128][20], Al[128][20], Bh[128][20], Bl[128][20];
    int b = blockIdx.x;
    if (b < 16) gemm_body(Ah, Al, Bh, Bl, g_o, 18, opb, g_attrel, NB * LCTX, nullptr, b);
    else gemm_body(Ah, Al, Bh, Bl, g_o, 19, g_v1, g_t1, NB * LCTX, nullptr, b - 16);
}

// ---------------- attention ----------------
__global__ void k_mha() {
    int b = blockIdx.x / NHEAD, h = blockIdx.x % NHEAD;
    __shared__ float ks[LKV][HDIM], vs[LKV][HDIM];
    int t = threadIdx.x;
    for (int i = t; i < LKV * HDIM; i += 32) {
        int k = i / HDIM, d = i % HDIM;
        size_t off = ((size_t)b * LKV + k) * DIM + h * HDIM + d;
        ks[k][d] = g_kh[off]; vs[k][d] = g_vh[off];
    }
    __syncwarp();
    float q[HDIM];
    size_t qoff = ((size_t)b * LCTX + t) * DIM + h * HDIM;
#pragma unroll
    for (int d = 0; d < HDIM; d++) q[d] = g_qh[qoff + d];
    float lg[LKV], mx = -1e30f;
    for (int k = 0; k < LKV; k++) {
        float s = 0.f;
#pragma unroll
        for (int d = 0; d < HDIM; d++) s += q[d] * ks[k][d];
        s *= 0.25f; lg[k] = s; mx = fmaxf(mx, s);
    }
    float sum = 0.f;
    for (int k = 0; k < LKV; k++) { lg[k] = expf(lg[k] - mx); sum += lg[k]; }
    float inv = 1.f / sum;
    float acc[HDIM];
#pragma unroll
    for (int d = 0; d < HDIM; d++) acc[d] = 0.f;
    for (int k = 0; k < LKV; k++) {
        float w = lg[k];
#pragma unroll
        for (int d = 0; d < HDIM; d++) acc[d] += w * vs[k][d];
    }
#pragma unroll
    for (int d = 0; d < HDIM; d++) g_o[qoff + d] = acc[d] * inv;
}

// his self-attn over attrel (L=32)
__global__ void k_selfattn_his(const float* __restrict__ ahb) {
    int b = blockIdx.x, t = threadIdx.x;
    __shared__ float w[LCTX];
    if (t < LCTX) {
        float e = 0.f;
        const float* tp = g_t1 + ((size_t)b * LCTX + t) * DIM;
        for (int d = 0; d < DIM; d++) e += tanhf(tp[d]) * ahb[d];
        w[t] = e;
    }
    __syncthreads();
    float mx = -1e30f;
    for (int l = 0; l < LCTX; l++) mx = fmaxf(mx, w[l]);
    float sum = 0.f;
    for (int l = 0; l < LCTX; l++) sum += expf(w[l] - mx);
    float inv = 1.f / sum, acc = 0.f;
    for (int l = 0; l < LCTX; l++)
        acc += expf(w[l] - mx) * g_attrel[((size_t)b * LCTX + l) * DIM + t];
    g_his[(size_t)b * DIM + t] = acc * inv;
}

// user self-attn over [context, his] (L=33) + inline his@aa + pack user row
__global__ void k_user(const float* __restrict__ aa, const float* __restrict__ ab) {
    int b = blockIdx.x, t = threadIdx.x;
    __shared__ float hs[DIM], t32[DIM], w[33], outv[DIM];
    hs[t] = g_his[(size_t)b * DIM + t];
    __syncthreads();
    // t2 row for l=32: his @ aa (column t)
    {
        float s = 0.f;
        for (int k = 0; k < DIM; k++) s = fmaf(hs[k], aa[k * DIM + t], s);
        t32[t] = s;
    }
    __syncthreads();
    if (t < 32) {
        float e = 0.f;
        const float* tp = g_t2ctx + ((size_t)b * LCTX + t) * DIM;
        for (int d = 0; d < DIM; d++) e += tanhf(tp[d]) * ab[d];
        w[t] = e;
    } else if (t == 32) {
        float e = 0.f;
        for (int d = 0; d < DIM; d++) e += tanhf(t32[d]) * ab[d];
        w[32] = e;
    }
    __syncthreads();
    float mx = -1e30f;
    for (int l = 0; l < 33; l++) mx = fmaxf(mx, w[l]);
    float sum = 0.f;
    for (int l = 0; l < 33; l++) sum += expf(w[l] - mx);
    float inv = 1.f / sum, acc = 0.f;
    for (int l = 0; l < 32; l++)
        acc += expf(w[l] - mx) * g_context[((size_t)b * LCTX + l) * DIM + t];
    acc += expf(w[32] - mx) * hs[t];
    float uv = acc * inv;
    outv[t] = uv;
    g_user[(size_t)b * DIM + t] = uv;
    __syncthreads();
    if (t < 64) {
        unsigned lo, hi = pack_split(outv[2 * t], outv[2 * t + 1], lo);
        g_Bh[21 * MATW + b * 64 + t] = hi;
        g_Bl[21 * MATW + b * 64 + t] = lo;
    }
}

// ------------- scores via tensor cores, coalesced epilogue -------------
__global__ void __launch_bounds__(128) k_scores_mma(const float* __restrict__ rb,
                                                    float* __restrict__ out) {
    __shared__ unsigned Ah[128][20], Al[128][20], Bh[64][20], Bl[64][20];
    __shared__ float st[128][33];
    const int t = threadIdx.x, lane = t & 31, warp = t >> 5;
    const int m0w = warp * 32;
    const int blkM = blockIdx.x * 128;
    const unsigned* Bhg = g_Bh + 21 * MATW;
    const unsigned* Blg = g_Bl + 21 * MATW;
    float acc[2][8][4];
#pragma unroll
    for (int i = 0; i < 2; i++)
#pragma unroll
        for (int j = 0; j < 8; j++)
#pragma unroll
            for (int q = 0; q < 4; q++) acc[i][j][q] = 0.f;

    for (int k0 = 0; k0 < 128; k0 += 32) {
        int gm = blkM + t;
        if (gm < NN) {
            const float4* ap = reinterpret_cast<const float4*>(g_kg + (size_t)gm * DIM + k0);
            conv_store_row(ap, 1.0f, &Ah[t][0], &Al[t][0]);
            conv_store_row(ap + 4, 1.0f, &Ah[t][8], &Al[t][8]);
        } else {
            uint4 z = make_uint4(0, 0, 0, 0);
#pragma unroll
            for (int q = 0; q < 4; q++) {
                *reinterpret_cast<uint4*>(&Ah[t][4 * q]) = z;
                *reinterpret_cast<uint4*>(&Al[t][4 * q]) = z;
            }
        }
        {
            int nB = t & 63, hB = (t >> 6) * 8;
            const unsigned* sh = Bhg + nB * 64 + k0 / 2 + hB;
            const unsigned* sl = Blg + nB * 64 + k0 / 2 + hB;
            *reinterpret_cast<uint4*>(&Bh[nB][hB])     = *reinterpret_cast<const uint4*>(sh);
            *reinterpret_cast<uint4*>(&Bh[nB][hB + 4]) = *reinterpret_cast<const uint4*>(sh + 4);
            *reinterpret_cast<uint4*>(&Bl[nB][hB])     = *reinterpret_cast<const uint4*>(sl);
            *reinterpret_cast<uint4*>(&Bl[nB][hB + 4]) = *reinterpret_cast<const uint4*>(sl + 4);
        }
        __syncthreads();
        bf_chunk(Ah, Al, Bh, Bl, acc, lane, m0w, 0);
        __syncthreads();
    }
    const int gr = lane >> 2, tg = lane & 3;
    int gmn = blkM + t;
    float rv = (gmn < NN) ? rb[gmn] : 0.f;
#pragma unroll
    for (int halfc = 0; halfc < 2; halfc++) {
        __syncthreads();
#pragma unroll
        for (int ms = 0; ms < 2; ms++) {
#pragma unroll
            for (int hf = 0; hf < 2; hf++) {
                int row = m0w + ms * 16 + gr + hf * 8;
#pragma unroll
                for (int ns = 0; ns < 4; ns++) {
                    int nsg = halfc * 4 + ns;
                    st[row][ns * 8 + 2 * tg]     = acc[ms][nsg][hf * 2];
                    st[row][ns * 8 + 2 * tg + 1] = acc[ms][nsg][hf * 2 + 1];
                }
            }
        }
        __syncthreads();
        if (gmn < NN) {
#pragma unroll
            for (int c = 0; c < 32; c++)
                out[(size_t)(halfc * 32 + c) * NN + gmn] = st[t][c] + rv;
        }
    }
}

// ---------------- host ----------------
static void* sym(const void* s) { void* p = nullptr; cudaGetSymbolAddress(&p, s); return p; }

extern "C" void kernel_launch(void* const* d_in, const int* in_sizes, int n_in,
                              void* d_out, int out_size) {
    const float* emb   = (const float*)d_in[0];
    const float* bases = (const float*)d_in[1];
    const float* comp  = (const float*)d_in[2];
    const float* root  = (const float*)d_in[3];
    const float* rbias = (const float*)d_in[4];
    const float* sth   = (const float*)d_in[5];
    const float* sbi   = (const float*)d_in[6];
    const float* kth   = (const float*)d_in[7];
    const float* kbi   = (const float*)d_in[8];
    const float* ipw   = (const float*)d_in[9];
    const float* ipb   = (const float*)d_in[10];
    const float* opw   = (const float*)d_in[11];
    const float* opb   = (const float*)d_in[12];
    const float* aha   = (const float*)d_in[13];
    const float* ahb   = (const float*)d_in[14];
    const float* aa    = (const float*)d_in[15];
    const float* ab    = (const float*)d_in[16];
    const float* recb  = (const float*)d_in[17];
    const int* esrc = (const int*)d_in[18];
    const int* edst = (const int*)d_in[19];
    const int* ety  = (const int*)d_in[20];
    const int* snod = (const int*)d_in[21];
    const int* sedg = (const int*)d_in[22];
    const int* knod = (const int*)d_in[23];
    const int* kedg = (const int*)d_in[24];
    const int* sri  = (const int*)d_in[25];
    const int* kri  = (const int*)d_in[26];
    const int* cxi  = (const int*)d_in[27];
    float* out = (float*)d_out;

    cudaFuncSetAttribute(k_edge_gemm, cudaFuncAttributeMaxDynamicSharedMemorySize, EDGE_SMEM);

    // single fused memset of all zeroed scratch
    cudaMemsetAsync(sym(g_Z), 0, (size_t)ZW_TOTAL * 4, 0);

    k_prep<<<(21 * MATW + 128 + 255) / 256, 256>>>(bases, comp, root, sth, kth, ipw, opw,
                                                   aha, aa, opb);

    // F1: root GEMM || edge count || hyper counts || flags || pack X
    k_fuse1<<<ROOTB + COUNTB + 2 * HCB + 2 * FLAGB + PACKB, 256>>>(
        emb, rbias, edst, ety, snod, sedg, knod, kedg, sri, kri);
    k_sort<<<(NEDGE + 255) / 256, 256>>>(ety);
    k_edge_gemm<<<EDGE_TILES, 256, EDGE_SMEM>>>(esrc, edst);

    // hypergraphs (linearity: scatter kg, then small GEMM with 1/b_deg)
    k_scatter_acc2<<<(2 * NP * 32) / 256, 256>>>(snod, sedg, knod, kedg);
    k_gemm_ef2<<<2 * EFB, 256>>>();
    k_scatter_node2<<<(2 * NP * 32) / 256, 256>>>(snod, sedg, knod, kedg);

    k_gather<<<(NB * LKV * DIM + NB * LCTX * DIM + 255) / 256, 256>>>(sri, kri, sbi, kbi, cxi);

    // MHA: Q/K/V + context@aa in one launch; then attention; then attrel+t1 in one launch
    k_qkv<<<160, 256>>>(ipb);
    k_mha<<<NB * NHEAD, 32>>>();
    k_att2<<<32, 256>>>(opb);

    k_selfattn_his<<<NB, 128>>>(ahb);
    k_user<<<NB, 128>>>(aa, ab);

    // scores on tensor cores
    k_scores_mma<<<(NN + 127) / 128, 128>>>(recb, out);
}

// round 14
// speedup vs baseline: 1.8925x; 1.0952x over previous
#include <cuda_runtime.h>
#include <cuda_bf16.h>
#include <cuda_fp16.h>
#include <math.h>

#define NN 100000
#define DIM 128
#define NREL 12
#define NBASES 8
#define NEDGE 1000000
#define NP 400000
#define NHYP 20000
#define NB 64
#define LREL 64
#define LKV 128
#define LCTX 32
#define NHEAD 8
#define HDIM 16
#define EDGE_TILES 7830
#define NMAT 22
#define MATW 8192   // 128 rows x 64 packed words per matrix

#define ROOTB 782
#define COUNTB 3907
#define HCB 1563
#define FLAGB 16
#define PACKB 3125
#define EFB 157

// edge kernel double-buffered smem: 6 x 128 x 20 words = 61440 bytes (Ah2 Al2 Bh2)
#define EDGE_SMEM 61440

// ---------------- single zeroed region ----------------
#define ZW_TOTAL 6760024
__device__ __align__(16) int g_Z[ZW_TOTAL];
#define g_cnt     (g_Z)
#define g_typeCnt (g_Z + 1200000)
#define g_cursor  (g_Z + 1200012)
#define g_bdegS   (g_Z + 1200024)
#define g_bdegK   (g_Z + 1220024)
#define g_ddegS   (g_Z + 1240024)
#define g_ddegK   (g_Z + 1340024)
#define g_flagS   (g_Z + 1440024)
#define g_flagK   (g_Z + 1540024)
#define g_accS    ((float*)(g_Z + 1640024))
#define g_accK    ((float*)(g_Z + 4200024))

__device__ __forceinline__ void red_add_v4(float* p, float x, float y, float z, float w) {
    asm volatile("red.global.add.v4.f32 [%0], {%1,%2,%3,%4};"
                 :: "l"(p), "f"(x), "f"(y), "f"(z), "f"(w) : "memory");
}

// split two fp32 into packed bf16x2 hi word + lo word
__device__ __forceinline__ unsigned pack_split(float x0, float x1, unsigned& lo) {
    __nv_bfloat16 h0 = __float2bfloat16(x0), h1 = __float2bfloat16(x1);
    float r0 = x0 - __bfloat162float(h0), r1 = x1 - __bfloat162float(h1);
    __nv_bfloat16 l0 = __float2bfloat16(r0), l1 = __float2bfloat16(r1);
    lo = (unsigned)__bfloat16_as_ushort(l0) | ((unsigned)__bfloat16_as_ushort(l1) << 16);
    return (unsigned)__bfloat16_as_ushort(h0) | ((unsigned)__bfloat16_as_ushort(h1) << 16);
}

// split two fp32 into packed fp16x2 hi word + lo word
__device__ __forceinline__ unsigned pack_split_f16(float x0, float x1, unsigned& lo) {
    __half h0 = __float2half_rn(x0), h1 = __float2half_rn(x1);
    float r0 = x0 - __half2float(h0), r1 = x1 - __half2float(h1);
    __half l0 = __float2half_rn(r0), l1 = __float2half_rn(r1);
    lo = (unsigned)__half_as_ushort(l0) | ((unsigned)__half_as_ushort(l1) << 16);
    return (unsigned)__half_as_ushort(h0) | ((unsigned)__half_as_ushort(h1) << 16);
}

__device__ __forceinline__ void mma16(float* c, const unsigned* a, const unsigned* b) {
    asm("mma.sync.aligned.m16n8k16.row.col.f32.bf16.bf16.f32 "
        "{%0,%1,%2,%3}, {%4,%5,%6,%7}, {%8,%9}, {%0,%1,%2,%3};"
        : "+f"(c[0]), "+f"(c[1]), "+f"(c[2]), "+f"(c[3])
        : "r"(a[0]), "r"(a[1]), "r"(a[2]), "r"(a[3]), "r"(b[0]), "r"(b[1]));
}

__device__ __forceinline__ void mma16f(float* c, const unsigned* a, const unsigned* b) {
    asm("mma.sync.aligned.m16n8k16.row.col.f32.f16.f16.f32 "
        "{%0,%1,%2,%3}, {%4,%5,%6,%7}, {%8,%9}, {%0,%1,%2,%3};"
        : "+f"(c[0]), "+f"(c[1]), "+f"(c[2]), "+f"(c[3])
        : "r"(a[0]), "r"(a[1]), "r"(a[2]), "r"(a[3]), "r"(b[0]), "r"(b[1]));
}

__device__ __forceinline__ void ldsm4(unsigned* r, const unsigned* p) {
    unsigned addr = (unsigned)__cvta_generic_to_shared(const_cast<unsigned*>(p));
    asm volatile("ldmatrix.sync.aligned.m8n8.x4.shared.b16 {%0,%1,%2,%3}, [%4];"
                 : "=r"(r[0]), "=r"(r[1]), "=r"(r[2]), "=r"(r[3]) : "r"(addr));
}

// ---------------- device scratch ----------------
__device__ unsigned g_Bh[NMAT * MATW];
__device__ unsigned g_Bl[NMAT * MATW];
__device__ unsigned g_Xh[NN * 64];
__device__ unsigned g_Xl[NN * 64];
__device__ float g_kg[NN * DIM];
__device__ int   g_sorted[NEDGE];
__device__ float g_efS[NHYP * DIM], g_efK[NHYP * DIM];
__device__ float g_noS[NN * DIM], g_noK[NN * DIM];
__device__ float g_related[NB * LKV * DIM];
__device__ float g_context[NB * LCTX * DIM];
__device__ float g_qh[NB * LCTX * DIM];
__device__ float g_kh[NB * LKV * DIM];
__device__ float g_vh[NB * LKV * DIM];
__device__ float g_o[NB * LCTX * DIM];
__device__ float g_attrel[NB * LCTX * DIM];
__device__ float g_t1[NB * LCTX * DIM];
__device__ float g_t2ctx[NB * LCTX * DIM];
__device__ float g_his[NB * DIM];
__device__ float g_user[NB * DIM];
__device__ float g_v1[DIM];

// ---------------- prep: pack B-matrices (W fp16 for edge; rest bf16 split) ----------------
__global__ void k_prep(const float* __restrict__ bases, const float* __restrict__ comp,
                       const float* __restrict__ root, const float* __restrict__ sth,
                       const float* __restrict__ kth, const float* __restrict__ ipw,
                       const float* __restrict__ opw, const float* __restrict__ aha,
                       const float* __restrict__ aa, const float* __restrict__ opb) {
    int idx = blockIdx.x * blockDim.x + threadIdx.x;
    if (idx >= 21 * MATW) {
        int n = idx - 21 * MATW;
        if (n < DIM) {
            float s = 0.f;
            for (int j = 0; j < DIM; j++) s = fmaf(opb[j], aha[j * DIM + n], s);
            g_v1[n] = s;
        }
        return;
    }
    int m = idx >> 13, rem = idx & (MATW - 1), n = rem >> 6, k2 = rem & 63;
    float s0, s1;
    if (m < 12) {
        const float* cp = comp + m * NBASES;
        s0 = 0.f; s1 = 0.f;
#pragma unroll
        for (int b = 0; b < NBASES; b++) {
            const float* bp = bases + (size_t)b * DIM * DIM + (2 * k2) * DIM + n;
            s0 = fmaf(cp[b], bp[0], s0);
            s1 = fmaf(cp[b], bp[DIM], s1);
        }
        // fp16 pack (edge kernel uses hi only)
        unsigned lo, hi = pack_split_f16(s0, s1, lo);
        g_Bh[idx] = hi; g_Bl[idx] = lo;
        return;
    } else if (m == 19) {
        // M1[k][n] = sum_j opw[j][k] * aha[j][n]  (t1 = o @ M1 + v1)
        s0 = 0.f; s1 = 0.f;
        for (int j = 0; j < DIM; j++) {
            float av = aha[j * DIM + n];
            s0 = fmaf(opw[j * DIM + 2 * k2],     av, s0);
            s1 = fmaf(opw[j * DIM + 2 * k2 + 1], av, s1);
        }
    } else {
        const float* b; int tr = 0;
        switch (m) {
            case 12: b = root; break;
            case 13: b = sth; break;
            case 14: b = kth; break;
            case 15: b = ipw; tr = 1; break;
            case 16: b = ipw + DIM * DIM; tr = 1; break;
            case 17: b = ipw + 2 * DIM * DIM; tr = 1; break;
            case 18: b = opw; tr = 1; break;
            default: b = aa; break;
        }
        if (tr) { s0 = b[n * DIM + 2 * k2]; s1 = b[n * DIM + 2 * k2 + 1]; }
        else    { s0 = b[(2 * k2) * DIM + n]; s1 = b[(2 * k2 + 1) * DIM + n]; }
    }
    unsigned lo, hi = pack_split(s0, s1, lo);
    g_Bh[idx] = hi; g_Bl[idx] = lo;
}

// counting sort with block aggregation; per-block prefix from g_typeCnt
__global__ void k_sort(const int* __restrict__ ty) {
    __shared__ int h[NREL], base[NREL];
    int t = threadIdx.x;
    if (t < NREL) h[t] = 0;
    __syncthreads();
    int e = blockIdx.x * blockDim.x + t;
    int tt = -1, loc = 0;
    if (e < NEDGE) { tt = ty[e]; loc = atomicAdd(&h[tt], 1); }
    __syncthreads();
    if (t < NREL) {
        int off = 0;
        for (int i = 0; i < t; i++) off += g_typeCnt[i];
        base[t] = off + (h[t] ? atomicAdd(&g_cursor[t], h[t]) : 0);
    }
    __syncthreads();
    if (e < NEDGE) g_sorted[base[tt] + loc] = e;
}

// bf16x2 3-term compute over one K32 chunk (ldmatrix fragment loads)
__device__ __forceinline__ void bf_chunk(
    const unsigned (*Ah)[20], const unsigned (*Al)[20],
    const unsigned (*Bh)[20], const unsigned (*Bl)[20],
    float acc[2][8][4], int lane, int m0, int n0) {
    const int ar = lane & 15, ac = (lane >> 4) * 4;
    const int br = (lane & 7) | ((lane >> 4) << 3), bc = ((lane >> 3) & 1) * 4;
#pragma unroll
    for (int s = 0; s < 2; s++) {
        const int kb = s * 8;
        unsigned bh[8][2], bl[8][2];
#pragma unroll
        for (int np = 0; np < 4; np++) {
            unsigned r4[4];
            ldsm4(r4, &Bh[n0 + np * 16 + br][kb + bc]);
            bh[2*np][0] = r4[0]; bh[2*np][1] = r4[1];
            bh[2*np+1][0] = r4[2]; bh[2*np+1][1] = r4[3];
            ldsm4(r4, &Bl[n0 + np * 16 + br][kb + bc]);
            bl[2*np][0] = r4[0]; bl[2*np][1] = r4[1];
            bl[2*np+1][0] = r4[2]; bl[2*np+1][1] = r4[3];
        }
#pragma unroll
        for (int ms = 0; ms < 2; ms++) {
            unsigned ah[4], al[4];
            ldsm4(ah, &Ah[m0 + ms * 16 + ar][kb + ac]);
            ldsm4(al, &Al[m0 + ms * 16 + ar][kb + ac]);
#pragma unroll
            for (int ns = 0; ns < 8; ns++) {
                mma16(acc[ms][ns], ah, bh[ns]);
                mma16(acc[ms][ns], ah, bl[ns]);
                mma16(acc[ms][ns], al, bh[ns]);
            }
        }
    }
}

// fp16 2-term compute over one K32 chunk: acc += (Ah + Al) @ Bh
__device__ __forceinline__ void fp_chunk(
    const unsigned (*Ah)[20], const unsigned (*Al)[20], const unsigned (*Bh)[20],
    float acc[2][8][4], int lane, int m0, int n0) {
    const int ar = lane & 15, ac = (lane >> 4) * 4;
    const int br = (lane & 7) | ((lane >> 4) << 3), bc = ((lane >> 3) & 1) * 4;
#pragma unroll
    for (int s = 0; s < 2; s++) {
        const int kb = s * 8;
        unsigned bh[8][2];
#pragma unroll
        for (int np = 0; np < 4; np++) {
            unsigned r4[4];
            ldsm4(r4, &Bh[n0 + np * 16 + br][kb + bc]);
            bh[2*np][0] = r4[0]; bh[2*np][1] = r4[1];
            bh[2*np+1][0] = r4[2]; bh[2*np+1][1] = r4[3];
        }
#pragma unroll
        for (int ms = 0; ms < 2; ms++) {
            unsigned ah[4], al[4];
            ldsm4(ah, &Ah[m0 + ms * 16 + ar][kb + ac]);
            ldsm4(al, &Al[m0 + ms * 16 + ar][kb + ac]);
#pragma unroll
            for (int ns = 0; ns < 8; ns++) {
                mma16f(acc[ms][ns], ah, bh[ns]);
                mma16f(acc[ms][ns], al, bh[ns]);
            }
        }
    }
}

// convert 16 fp32 (scaled) -> 8 hi + 8 lo packed words (bf16)
__device__ __forceinline__ void conv_store_row(const float4* ap, float scale,
                                               unsigned* dh, unsigned* dl) {
    unsigned hw[8], lw[8];
#pragma unroll
    for (int q = 0; q < 4; q++) {
        float4 v = ap[q];
        v.x *= scale; v.y *= scale; v.z *= scale; v.w *= scale;
        hw[2*q]   = pack_split(v.x, v.y, lw[2*q]);
        hw[2*q+1] = pack_split(v.z, v.w, lw[2*q+1]);
    }
    *reinterpret_cast<uint4*>(dh)     = make_uint4(hw[0], hw[1], hw[2], hw[3]);
    *reinterpret_cast<uint4*>(dh + 4) = make_uint4(hw[4], hw[5], hw[6], hw[7]);
    *reinterpret_cast<uint4*>(dl)     = make_uint4(lw[0], lw[1], lw[2], lw[3]);
    *reinterpret_cast<uint4*>(dl + 4) = make_uint4(lw[4], lw[5], lw[6], lw[7]);
}

// fp16 variant
__device__ __forceinline__ void conv_store_row_f16(const float4* ap,
                                                   unsigned* dh, unsigned* dl) {
    unsigned hw[8], lw[8];
#pragma unroll
    for (int q = 0; q < 4; q++) {
        float4 v = ap[q];
        hw[2*q]   = pack_split_f16(v.x, v.y, lw[2*q]);
        hw[2*q+1] = pack_split_f16(v.z, v.w, lw[2*q+1]);
    }
    *reinterpret_cast<uint4*>(dh)     = make_uint4(hw[0], hw[1], hw[2], hw[3]);
    *reinterpret_cast<uint4*>(dh + 4) = make_uint4(hw[4], hw[5], hw[6], hw[7]);
    *reinterpret_cast<uint4*>(dl)     = make_uint4(lw[0], lw[1], lw[2], lw[3]);
    *reinterpret_cast<uint4*>(dl + 4) = make_uint4(lw[4], lw[5], lw[6], lw[7]);
}

// ------------- generic GEMM body: C[M,128] = A[M,128] @ B(mat) (+bias, row scale 1/deg) ----
__device__ __forceinline__ void gemm_body(
    unsigned (*Ah)[20], unsigned (*Al)[20], unsigned (*Bh)[20], unsigned (*Bl)[20],
    const float* __restrict__ A, int mat, const float* __restrict__ bias,
    float* __restrict__ C, int M, const int* __restrict__ rowdeg, int blk) {
    const int t = threadIdx.x, lane = t & 31, warp = t >> 5;
    const int m0w = (warp & 3) * 32, n0w = (warp >> 2) * 64;
    const int blkM = blk * 128;
    const unsigned* Bhg = g_Bh + mat * MATW;
    const unsigned* Blg = g_Bl + mat * MATW;
    float acc[2][8][4];
#pragma unroll
    for (int i = 0; i < 2; i++)
#pragma unroll
        for (int j = 0; j < 8; j++)
#pragma unroll
            for (int q = 0; q < 4; q++) acc[i][j][q] = 0.f;
    const int mA = t >> 1, half = t & 1;
    const int nB = t >> 1, hB = (t & 1) * 8;

    for (int k0 = 0; k0 < 128; k0 += 32) {
        int gm = blkM + mA;
        if (gm < M) {
            const float4* ap = reinterpret_cast<const float4*>(A + (size_t)gm * DIM + k0 + half * 16);
            conv_store_row(ap, 1.0f, &Ah[mA][half * 8], &Al[mA][half * 8]);
        } else {
            uint4 z = make_uint4(0, 0, 0, 0);
            *reinterpret_cast<uint4*>(&Ah[mA][half*8]) = z;
            *reinterpret_cast<uint4*>(&Ah[mA][half*8+4]) = z;
            *reinterpret_cast<uint4*>(&Al[mA][half*8]) = z;
            *reinterpret_cast<uint4*>(&Al[mA][half*8+4]) = z;
        }
        {
            const unsigned* sh = Bhg + nB * 64 + k0 / 2 + hB;
            const unsigned* sl = Blg + nB * 64 + k0 / 2 + hB;
            *reinterpret_cast<uint4*>(&Bh[nB][hB])     = *reinterpret_cast<const uint4*>(sh);
            *reinterpret_cast<uint4*>(&Bh[nB][hB + 4]) = *reinterpret_cast<const uint4*>(sh + 4);
            *reinterpret_cast<uint4*>(&Bl[nB][hB])     = *reinterpret_cast<const uint4*>(sl);
            *reinterpret_cast<uint4*>(&Bl[nB][hB + 4]) = *reinterpret_cast<const uint4*>(sl + 4);
        }
        __syncthreads();
        bf_chunk(Ah, Al, Bh, Bl, acc, lane, m0w, n0w);
        __syncthreads();
    }
    const int gr = lane >> 2, tg = lane & 3;
#pragma unroll
    for (int ms = 0; ms < 2; ms++) {
#pragma unroll
        for (int hf = 0; hf < 2; hf++) {
            int gm = blkM + m0w + ms * 16 + gr + hf * 8;
            if (gm < M) {
                float scale = 1.f;
                if (rowdeg) { int dg = rowdeg[gm]; scale = dg > 0 ? 1.f / (float)dg : 0.f; }
                float* cp = C + (size_t)gm * DIM;
#pragma unroll
                for (int ns = 0; ns < 8; ns++) {
                    int col = n0w + ns * 8 + 2 * tg;
                    float b0 = bias ? bias[col] : 0.f;
                    float b1 = bias ? bias[col + 1] : 0.f;
                    float2 v = make_float2(acc[ms][ns][hf * 2] * scale + b0,
                                           acc[ms][ns][hf * 2 + 1] * scale + b1);
                    *reinterpret_cast<float2*>(cp + col) = v;
                }
            }
        }
    }
}

// ------------- F1: root GEMM || edge count || hyper counts || flags || pack X -------------
__global__ void __launch_bounds__(256) k_fuse1(
    const float* __restrict__ emb, const float* __restrict__ rbias,
    const int* __restrict__ edst, const int* __restrict__ ety,
    const int* __restrict__ snod, const int* __restrict__ sedg,
    const int* __restrict__ knod, const int* __restrict__ kedg,
    const int* __restrict__ sri, const int* __restrict__ kri) {
    __shared__ unsigned Ah[128][20], Al[128][20], Bh[128][20], Bl[128][20];
    __shared__ int fh[NREL];
    int b = blockIdx.x;
    int t = threadIdx.x;
    if (b < ROOTB) {
        gemm_body(Ah, Al, Bh, Bl, emb, 12, rbias, g_kg, NN, nullptr, b);
        return;
    }
    b -= ROOTB;
    if (b < COUNTB) {
        if (t < NREL) fh[t] = 0;
        __syncthreads();
        int e = b * 256 + t;
        if (e < NEDGE) {
            int tt = ety[e];
            atomicAdd(&g_cnt[edst[e] * NREL + tt], 1);
            atomicAdd(&fh[tt], 1);
        }
        __syncthreads();
        if (t < NREL && fh[t]) atomicAdd(&g_typeCnt[t], fh[t]);
        return;
    }
    b -= COUNTB;
    if (b < 2 * HCB) {
        const int* nodes; const int* edges; int* bdeg; int* ddeg;
        int lb = b;
        if (lb < HCB) { nodes = snod; edges = sedg; bdeg = g_bdegS; ddeg = g_ddegS; }
        else { lb -= HCB; nodes = knod; edges = kedg; bdeg = g_bdegK; ddeg = g_ddegK; }
        int p = lb * 256 + t;
        if (p < NP) {
            atomicAdd(&bdeg[edges[p]], 1);
            atomicAdd(&ddeg[nodes[p]], 1);
        }
        return;
    }
    b -= 2 * HCB;
    if (b < 2 * FLAGB) {
        const int* idx; int* flag; float* no;
        int lb = b;
        if (lb < FLAGB) { idx = sri; flag = g_flagS; no = g_noS; }
        else { lb -= FLAGB; idx = kri; flag = g_flagK; no = g_noK; }
        int i = lb * 256 + t;
        if (i < NB * LREL) {
            int n = idx[i];
            flag[n] = 1;
            float4 z = make_float4(0.f, 0.f, 0.f, 0.f);
            float4* p = reinterpret_cast<float4*>(no + (size_t)n * DIM);
#pragma unroll
            for (int d = 0; d < DIM / 4; d++) p[d] = z;
        }
        return;
    }
    b -= 2 * FLAGB;
    {
        int i = b * 256 + t;
        if (i < NN * 8) {
            int n = i >> 3, part = i & 7;
            const float4* ap = reinterpret_cast<const float4*>(emb + (size_t)n * DIM + part * 16);
            conv_store_row_f16(ap, &g_Xh[(size_t)n * 64 + part * 8],
                               &g_Xl[(size_t)n * 64 + part * 8]);
        }
    }
}

// ------------- RGCN edge GEMM (fp16 2-term, double-buffered) -------------
__global__ void __launch_bounds__(256) k_edge_gemm(
    const int* __restrict__ esrc, const int* __restrict__ edst) {
    extern __shared__ unsigned dsm[];
    unsigned (*Ah)[20] = (unsigned(*)[20])dsm;                   // 2 bufs
    unsigned (*Al)[20] = (unsigned(*)[20])(dsm + 2 * 128 * 20);  // 2 bufs
    unsigned (*Bh)[20] = (unsigned(*)[20])(dsm + 4 * 128 * 20);  // 2 bufs
    __shared__ int   sSrc[128], sDst[128];
    __shared__ float sNorm[128];
    const int bid = blockIdx.x;
    int r = -1, base = 0, cnt = 0;
    {
        int off = 0, toff = 0;
#pragma unroll
        for (int i = 0; i < NREL; i++) {
            int c = g_typeCnt[i];
            int nt = (c + 127) >> 7;
            if (r < 0 && bid < toff + nt) {
                int local = bid - toff;
                r = i; base = off + local * 128;
                cnt = c - local * 128; if (cnt > 128) cnt = 128;
            }
            off += c; toff += nt;
        }
    }
    if (r < 0) return;
    const int t = threadIdx.x, lane = t & 31, warp = t >> 5;
    const int m0w = (warp & 3) * 32, n0w = (warp >> 2) * 64;
    if (t < 128) {
        if (t < cnt) {
            int e = g_sorted[base + t];
            int d = edst[e];
            sSrc[t] = esrc[e]; sDst[t] = d;
            sNorm[t] = 1.0f / fmaxf((float)g_cnt[d * NREL + r], 1.0f);
        } else { sSrc[t] = 0; sDst[t] = -1; sNorm[t] = 0.f; }
    }
    __syncthreads();

    const int mA = t >> 1, half = t & 1;
    const unsigned* Bhg = g_Bh + (size_t)r * MATW;

    auto stage = [&](int buf, int k0) {
        int ro = buf * 128 + mA;
        size_t xoff = (size_t)sSrc[mA] * 64 + k0 / 2 + half * 8;
        const unsigned* xh = g_Xh + xoff;
        const unsigned* xl = g_Xl + xoff;
        *reinterpret_cast<uint4*>(&Ah[ro][half*8])     = *reinterpret_cast<const uint4*>(xh);
        *reinterpret_cast<uint4*>(&Ah[ro][half*8 + 4]) = *reinterpret_cast<const uint4*>(xh + 4);
        *reinterpret_cast<uint4*>(&Al[ro][half*8])     = *reinterpret_cast<const uint4*>(xl);
        *reinterpret_cast<uint4*>(&Al[ro][half*8 + 4]) = *reinterpret_cast<const uint4*>(xl + 4);
        size_t boff = (size_t)mA * 64 + k0 / 2 + half * 8;
        const unsigned* bh = Bhg + boff;
        *reinterpret_cast<uint4*>(&Bh[ro][half*8])     = *reinterpret_cast<const uint4*>(bh);
        *reinterpret_cast<uint4*>(&Bh[ro][half*8 + 4]) = *reinterpret_cast<const uint4*>(bh + 4);
    };

    float acc[2][8][4];
#pragma unroll
    for (int i = 0; i < 2; i++)
#pragma unroll
        for (int j = 0; j < 8; j++)
#pragma unroll
            for (int q = 0; q < 4; q++) acc[i][j][q] = 0.f;

    stage(0, 0);
    __syncthreads();
#pragma unroll
    for (int c = 0; c < 4; c++) {
        if (c < 3) stage((c + 1) & 1, (c + 1) * 32);
        int rb = (c & 1) * 128;
        fp_chunk(&Ah[rb], &Al[rb], &Bh[rb], acc, lane, m0w, n0w);
        __syncthreads();
    }

    const int gr = lane >> 2, tg = lane & 3;
#pragma unroll
    for (int ms = 0; ms < 2; ms++) {
#pragma unroll
        for (int hf = 0; hf < 2; hf++) {
            int rr = m0w + ms * 16 + gr + hf * 8;
            int dn = sDst[rr];
            float nrm = sNorm[rr];
#pragma unroll
            for (int ns = 0; ns < 8; ns++) {
                float v0 = acc[ms][ns][hf * 2] * nrm;
                float v1 = acc[ms][ns][hf * 2 + 1] * nrm;
                float p0 = __shfl_xor_sync(0xffffffffu, v0, 1);
                float p1 = __shfl_xor_sync(0xffffffffu, v1, 1);
                if (((tg & 1) == 0) && dn >= 0)
                    red_add_v4(g_kg + (size_t)dn * DIM + n0w + ns * 8 + 2 * tg, v0, v1, p0, p1);
            }
        }
    }
}

// ------------- fused S/K hyperedge accumulation: acc[he] += kg[node] -------------
__global__ void k_scatter_acc2(const int* __restrict__ snod, const int* __restrict__ sedg,
                               const int* __restrict__ knod, const int* __restrict__ kedg) {
    int w = (blockIdx.x * blockDim.x + threadIdx.x) >> 5;
    int lane = threadIdx.x & 31;
    const int* nodes; const int* edges; float* accum;
    if (w < NP) { nodes = snod; edges = sedg; accum = g_accS; }
    else { w -= NP; if (w >= NP) return; nodes = knod; edges = kedg; accum = g_accK; }
    float4 v = *reinterpret_cast<const float4*>(&g_kg[(size_t)nodes[w] * DIM + lane * 4]);
    red_add_v4(accum + (size_t)edges[w] * DIM + lane * 4, v.x, v.y, v.z, v.w);
}

// fused S/K edge-feature GEMMs: ef = (acc @ theta) / b_deg
__global__ void __launch_bounds__(256) k_gemm_ef2() {
    __shared__ unsigned Ah[128][20], Al[128][20], Bh[128][20], Bl[128][20];
    int b = blockIdx.x;
    if (b < EFB) gemm_body(Ah, Al, Bh, Bl, g_accS, 13, nullptr, g_efS, NHYP, g_bdegS, b);
    else gemm_body(Ah, Al, Bh, Bl, g_accK, 14, nullptr, g_efK, NHYP, g_bdegK, b - EFB);
}

// fused S/K node scatter (flag-masked)
__global__ void k_scatter_node2(const int* __restrict__ snod, const int* __restrict__ sedg,
                                const int* __restrict__ knod, const int* __restrict__ kedg) {
    int w = (blockIdx.x * blockDim.x + threadIdx.x) >> 5;
    int lane = threadIdx.x & 31;
    const int* nodes; const int* edges; const int* flag; const float* ef; float* no;
    if (w < NP) { nodes = snod; edges = sedg; flag = g_flagS; ef = g_efS; no = g_noS; }
    else { w -= NP; if (w >= NP) return; nodes = knod; edges = kedg; flag = g_flagK; ef = g_efK; no = g_noK; }
    int n = nodes[w];
    if (!flag[n]) return;
    float4 v = *reinterpret_cast<const float4*>(ef + (size_t)edges[w] * DIM + lane * 4);
    red_add_v4(no + (size_t)n * DIM + lane * 4, v.x, v.y, v.z, v.w);
}

// fused gathers: related + context
__global__ void k_gather(const int* __restrict__ sidx, const int* __restrict__ kidx,
                         const float* __restrict__ biasS, const float* __restrict__ biasK,
                         const int* __restrict__ cidx) {
    int i = blockIdx.x * blockDim.x + threadIdx.x;
    if (i < NB * LKV * DIM) {
        int d = i & 127, l = (i >> 7) & 127, b = i >> 14;
        float v;
        if (l < LREL) {
            int n = sidx[b * LREL + l]; int dd = g_ddegS[n];
            v = g_noS[(size_t)n * DIM + d] * (dd > 0 ? 1.f / dd : 0.f) + biasS[d];
        } else {
            int n = kidx[b * LREL + l - LREL]; int dd = g_ddegK[n];
            v = g_noK[(size_t)n * DIM + d] * (dd > 0 ? 1.f / dd : 0.f) + biasK[d];
        }
        g_related[i] = v;
        return;
    }
    int j = i - NB * LKV * DIM;
    if (j < NB * LCTX * DIM)
        g_context[j] = g_kg[(size_t)cidx[j >> 7] * DIM + (j & 127)];
}

// fused Q/K/V projections + context@aa
__global__ void __launch_bounds__(256) k_qkv(const float* __restrict__ ipb) {
    __shared__ unsigned Ah[128][20], Al[128][20], Bh[128][20], Bl[128][20];
    int b = blockIdx.x;
    if (b < 16) gemm_body(Ah, Al, Bh, Bl, g_context, 15, ipb, g_qh, NB * LCTX, nullptr, b);
    else if (b < 80) gemm_body(Ah, Al, Bh, Bl, g_related, 16, ipb + DIM, g_kh, NB * LKV, nullptr, b - 16);
    else if (b < 144) gemm_body(Ah, Al, Bh, Bl, g_related, 17, ipb + 2 * DIM, g_vh, NB * LKV, nullptr, b - 80);
    else gemm_body(Ah, Al, Bh, Bl, g_context, 20, nullptr, g_t2ctx, NB * LCTX, nullptr, b - 144);
}

// fused attrel-proj + t1 (independent given M1 precombination)
__global__ void __launch_bounds__(256) k_att2(const float* __restrict__ opb) {
    __shared__ unsigned Ah[128][20], Al[128][20], Bh[128][20], Bl[128][20];
    int b = blockIdx.x;
    if (b < 16) gemm_body(Ah, Al, Bh, Bl, g_o, 18, opb, g_attrel, NB * LCTX, nullptr, b);
    else gemm_body(Ah, Al, Bh, Bl, g_o, 19, g_v1, g_t1, NB * LCTX, nullptr, b - 16);
}

// ---------------- attention ----------------
__global__ void k_mha() {
    int b = blockIdx.x / NHEAD, h = blockIdx.x % NHEAD;
    __shared__ float ks[LKV][HDIM], vs[LKV][HDIM];
    int t = threadIdx.x;
    for (int i = t; i < LKV * HDIM; i += 32) {
        int k = i / HDIM, d = i % HDIM;
        size_t off = ((size_t)b * LKV + k) * DIM + h * HDIM + d;
        ks[k][d] = g_kh[off]; vs[k][d] = g_vh[off];
    }
    __syncwarp();
    float q[HDIM];
    size_t qoff = ((size_t)b * LCTX + t) * DIM + h * HDIM;
#pragma unroll
    for (int d = 0; d < HDIM; d++) q[d] = g_qh[qoff + d];
    float lg[LKV], mx = -1e30f;
    for (int k = 0; k < LKV; k++) {
        float s = 0.f;
#pragma unroll
        for (int d = 0; d < HDIM; d++) s += q[d] * ks[k][d];
        s *= 0.25f; lg[k] = s; mx = fmaxf(mx, s);
    }
    float sum = 0.f;
    for (int k = 0; k < LKV; k++) { lg[k] = expf(lg[k] - mx); sum += lg[k]; }
    float inv = 1.f / sum;
    float acc[HDIM];
#pragma unroll
    for (int d = 0; d < HDIM; d++) acc[d] = 0.f;
    for (int k = 0; k < LKV; k++) {
        float w = lg[k];
#pragma unroll
        for (int d = 0; d < HDIM; d++) acc[d] += w * vs[k][d];
    }
#pragma unroll
    for (int d = 0; d < HDIM; d++) g_o[qoff + d] = acc[d] * inv;
}

// his self-attn over attrel (L=32)
__global__ void k_selfattn_his(const float* __restrict__ ahb) {
    int b = blockIdx.x, t = threadIdx.x;
    __shared__ float w[LCTX];
    if (t < LCTX) {
        float e = 0.f;
        const float* tp = g_t1 + ((size_t)b * LCTX + t) * DIM;
        for (int d = 0; d < DIM; d++) e += tanhf(tp[d]) * ahb[d];
        w[t] = e;
    }
    __syncthreads();
    float mx = -1e30f;
    for (int l = 0; l < LCTX; l++) mx = fmaxf(mx, w[l]);
    float sum = 0.f;
    for (int l = 0; l < LCTX; l++) sum += expf(w[l] - mx);
    float inv = 1.f / sum, acc = 0.f;
    for (int l = 0; l < LCTX; l++)
        acc += expf(w[l] - mx) * g_attrel[((size_t)b * LCTX + l) * DIM + t];
    g_his[(size_t)b * DIM + t] = acc * inv;
}

// user self-attn over [context, his] (L=33) + inline his@aa + pack user row
__global__ void k_user(const float* __restrict__ aa, const float* __restrict__ ab) {
    int b = blockIdx.x, t = threadIdx.x;
    __shared__ float hs[DIM], t32[DIM], w[33], outv[DIM];
    hs[t] = g_his[(size_t)b * DIM + t];
    __syncthreads();
    {
        float s = 0.f;
        for (int k = 0; k < DIM; k++) s = fmaf(hs[k], aa[k * DIM + t], s);
        t32[t] = s;
    }
    __syncthreads();
    if (t < 32) {
        float e = 0.f;
        const float* tp = g_t2ctx + ((size_t)b * LCTX + t) * DIM;
        for (int d = 0; d < DIM; d++) e += tanhf(tp[d]) * ab[d];
        w[t] = e;
    } else if (t == 32) {
        float e = 0.f;
        for (int d = 0; d < DIM; d++) e += tanhf(t32[d]) * ab[d];
        w[32] = e;
    }
    __syncthreads();
    float mx = -1e30f;
    for (int l = 0; l < 33; l++) mx = fmaxf(mx, w[l]);
    float sum = 0.f;
    for (int l = 0; l < 33; l++) sum += expf(w[l] - mx);
    float inv = 1.f / sum, acc = 0.f;
    for (int l = 0; l < 32; l++)
        acc += expf(w[l] - mx) * g_context[((size_t)b * LCTX + l) * DIM + t];
    acc += expf(w[32] - mx) * hs[t];
    float uv = acc * inv;
    outv[t] = uv;
    g_user[(size_t)b * DIM + t] = uv;
    __syncthreads();
    if (t < 64) {
        unsigned lo, hi = pack_split(outv[2 * t], outv[2 * t + 1], lo);
        g_Bh[21 * MATW + b * 64 + t] = hi;
        g_Bl[21 * MATW + b * 64 + t] = lo;
    }
}

// ------------- scores via tensor cores, coalesced epilogue -------------
__global__ void __launch_bounds__(128) k_scores_mma(const float* __restrict__ rb,
                                                    float* __restrict__ out) {
    __shared__ unsigned Ah[128][20], Al[128][20], Bh[64][20], Bl[64][20];
    __shared__ float st[128][33];
    const int t = threadIdx.x, lane = t & 31, warp = t >> 5;
    const int m0w = warp * 32;
    const int blkM = blockIdx.x * 128;
    const unsigned* Bhg = g_Bh + 21 * MATW;
    const unsigned* Blg = g_Bl + 21 * MATW;
    float acc[2][8][4];
#pragma unroll
    for (int i = 0; i < 2; i++)
#pragma unroll
        for (int j = 0; j < 8; j++)
#pragma unroll
            for (int q = 0; q < 4; q++) acc[i][j][q] = 0.f;

    for (int k0 = 0; k0 < 128; k0 += 32) {
        int gm = blkM + t;
        if (gm < NN) {
            const float4* ap = reinterpret_cast<const float4*>(g_kg + (size_t)gm * DIM + k0);
            conv_store_row(ap, 1.0f, &Ah[t][0], &Al[t][0]);
            conv_store_row(ap + 4, 1.0f, &Ah[t][8], &Al[t][8]);
        } else {
            uint4 z = make_uint4(0, 0, 0, 0);
#pragma unroll
            for (int q = 0; q < 4; q++) {
                *reinterpret_cast<uint4*>(&Ah[t][4 * q]) = z;
                *reinterpret_cast<uint4*>(&Al[t][4 * q]) = z;
            }
        }
        {
            int nB = t & 63, hB = (t >> 6) * 8;
            const unsigned* sh = Bhg + nB * 64 + k0 / 2 + hB;
            const unsigned* sl = Blg + nB * 64 + k0 / 2 + hB;
            *reinterpret_cast<uint4*>(&Bh[nB][hB])     = *reinterpret_cast<const uint4*>(sh);
            *reinterpret_cast<uint4*>(&Bh[nB][hB + 4]) = *reinterpret_cast<const uint4*>(sh + 4);
            *reinterpret_cast<uint4*>(&Bl[nB][hB])     = *reinterpret_cast<const uint4*>(sl);
            *reinterpret_cast<uint4*>(&Bl[nB][hB + 4]) = *reinterpret_cast<const uint4*>(sl + 4);
        }
        __syncthreads();
        bf_chunk(Ah, Al, Bh, Bl, acc, lane, m0w, 0);
        __syncthreads();
    }
    const int gr = lane >> 2, tg = lane & 3;
    int gmn = blkM + t;
    float rv = (gmn < NN) ? rb[gmn] : 0.f;
#pragma unroll
    for (int halfc = 0; halfc < 2; halfc++) {
        __syncthreads();
#pragma unroll
        for (int ms = 0; ms < 2; ms++) {
#pragma unroll
            for (int hf = 0; hf < 2; hf++) {
                int row = m0w + ms * 16 + gr + hf * 8;
#pragma unroll
                for (int ns = 0; ns < 4; ns++) {
                    int nsg = halfc * 4 + ns;
                    st[row][ns * 8 + 2 * tg]     = acc[ms][nsg][hf * 2];
                    st[row][ns * 8 + 2 * tg + 1] = acc[ms][nsg][hf * 2 + 1];
                }
            }
        }
        __syncthreads();
        if (gmn < NN) {
#pragma unroll
            for (int c = 0; c < 32; c++)
                out[(size_t)(halfc * 32 + c) * NN + gmn] = st[t][c] + rv;
        }
    }
}

// ---------------- host ----------------
static void* sym(const void* s) { void* p = nullptr; cudaGetSymbolAddress(&p, s); return p; }

extern "C" void kernel_launch(void* const* d_in, const int* in_sizes, int n_in,
                              void* d_out, int out_size) {
    const float* emb   = (const float*)d_in[0];
    const float* bases = (const float*)d_in[1];
    const float* comp  = (const float*)d_in[2];
    const float* root  = (const float*)d_in[3];
    const float* rbias = (const float*)d_in[4];
    const float* sth   = (const float*)d_in[5];
    const float* sbi   = (const float*)d_in[6];
    const float* kth   = (const float*)d_in[7];
    const float* kbi   = (const float*)d_in[8];
    const float* ipw   = (const float*)d_in[9];
    const float* ipb   = (const float*)d_in[10];
    const float* opw   = (const float*)d_in[11];
    const float* opb   = (const float*)d_in[12];
    const float* aha   = (const float*)d_in[13];
    const float* ahb   = (const float*)d_in[14];
    const float* aa    = (const float*)d_in[15];
    const float* ab    = (const float*)d_in[16];
    const float* recb  = (const float*)d_in[17];
    const int* esrc = (const int*)d_in[18];
    const int* edst = (const int*)d_in[19];
    const int* ety  = (const int*)d_in[20];
    const int* snod = (const int*)d_in[21];
    const int* sedg = (const int*)d_in[22];
    const int* knod = (const int*)d_in[23];
    const int* kedg = (const int*)d_in[24];
    const int* sri  = (const int*)d_in[25];
    const int* kri  = (const int*)d_in[26];
    const int* cxi  = (const int*)d_in[27];
    float* out = (float*)d_out;

    cudaFuncSetAttribute(k_edge_gemm, cudaFuncAttributeMaxDynamicSharedMemorySize, EDGE_SMEM);

    // single fused memset of all zeroed scratch
    cudaMemsetAsync(sym(g_Z), 0, (size_t)ZW_TOTAL * 4, 0);

    k_prep<<<(21 * MATW + 128 + 255) / 256, 256>>>(bases, comp, root, sth, kth, ipw, opw,
                                                   aha, aa, opb);

    // F1: root GEMM || edge count || hyper counts || flags || pack X (fp16)
    k_fuse1<<<ROOTB + COUNTB + 2 * HCB + 2 * FLAGB + PACKB, 256>>>(
        emb, rbias, edst, ety, snod, sedg, knod, kedg, sri, kri);
    k_sort<<<(NEDGE + 255) / 256, 256>>>(ety);
    k_edge_gemm<<<EDGE_TILES, 256, EDGE_SMEM>>>(esrc, edst);

    // hypergraphs (linearity: scatter kg, then small GEMM with 1/b_deg)
    k_scatter_acc2<<<(2 * NP * 32) / 256, 256>>>(snod, sedg, knod, kedg);
    k_gemm_ef2<<<2 * EFB, 256>>>();
    k_scatter_node2<<<(2 * NP * 32) / 256, 256>>>(snod, sedg, knod, kedg);

    k_gather<<<(NB * LKV * DIM + NB * LCTX * DIM + 255) / 256, 256>>>(sri, kri, sbi, kbi, cxi);

    // MHA
    k_qkv<<<160, 256>>>(ipb);
    k_mha<<<NB * NHEAD, 32>>>();
    k_att2<<<32, 256>>>(opb);

    k_selfattn_his<<<NB, 128>>>(ahb);
    k_user<<<NB, 128>>>(aa, ab);

    // scores on tensor cores
    k_scores_mma<<<(NN + 127) / 128, 128>>>(recb, out);
}

// round 15
// speedup vs baseline: 2.0716x; 1.0946x over previous
#include <cuda_runtime.h>
#include <cuda_bf16.h>
#include <cuda_fp16.h>
#include <math.h>

#define NN 100000
#define DIM 128
#define NREL 12
#define NBASES 8
#define NEDGE 1000000
#define NP 400000
#define NHYP 20000
#define NB 64
#define LREL 64
#define LKV 128
#define LCTX 32
#define NHEAD 8
#define HDIM 16
#define EDGE_TILES 7830
#define NMAT 22
#define MATW 8192   // 128 rows x 64 packed words per matrix

#define ROOTB 782
#define COUNTB 3907
#define HCB 1563
#define FLAGB 16
#define PACKB 3125
#define EFB 157

// edge kernel double-buffered smem: 4 x 128 x 20 words = 40960 bytes (Ah2 Bh2)
#define EDGE_SMEM 40960

// ---------------- single zeroed region ----------------
#define ZW_TOTAL 6760024
__device__ __align__(16) int g_Z[ZW_TOTAL];
#define g_cnt     (g_Z)
#define g_typeCnt (g_Z + 1200000)
#define g_cursor  (g_Z + 1200012)
#define g_bdegS   (g_Z + 1200024)
#define g_bdegK   (g_Z + 1220024)
#define g_ddegS   (g_Z + 1240024)
#define g_ddegK   (g_Z + 1340024)
#define g_flagS   (g_Z + 1440024)
#define g_flagK   (g_Z + 1540024)
#define g_accS    ((float*)(g_Z + 1640024))
#define g_accK    ((float*)(g_Z + 4200024))

__device__ __forceinline__ void red_add_v4(float* p, float x, float y, float z, float w) {
    asm volatile("red.global.add.v4.f32 [%0], {%1,%2,%3,%4};"
                 :: "l"(p), "f"(x), "f"(y), "f"(z), "f"(w) : "memory");
}

// split two fp32 into packed bf16x2 hi word + lo word
__device__ __forceinline__ unsigned pack_split(float x0, float x1, unsigned& lo) {
    __nv_bfloat16 h0 = __float2bfloat16(x0), h1 = __float2bfloat16(x1);
    float r0 = x0 - __bfloat162float(h0), r1 = x1 - __bfloat162float(h1);
    __nv_bfloat16 l0 = __float2bfloat16(r0), l1 = __float2bfloat16(r1);
    lo = (unsigned)__bfloat16_as_ushort(l0) | ((unsigned)__bfloat16_as_ushort(l1) << 16);
    return (unsigned)__bfloat16_as_ushort(h0) | ((unsigned)__bfloat16_as_ushort(h1) << 16);
}

// pack two fp32 into fp16x2 (round-nearest)
__device__ __forceinline__ unsigned pack_f16(float x0, float x1) {
    __half h0 = __float2half_rn(x0), h1 = __float2half_rn(x1);
    return (unsigned)__half_as_ushort(h0) | ((unsigned)__half_as_ushort(h1) << 16);
}

__device__ __forceinline__ void mma16(float* c, const unsigned* a, const unsigned* b) {
    asm("mma.sync.aligned.m16n8k16.row.col.f32.bf16.bf16.f32 "
        "{%0,%1,%2,%3}, {%4,%5,%6,%7}, {%8,%9}, {%0,%1,%2,%3};"
        : "+f"(c[0]), "+f"(c[1]), "+f"(c[2]), "+f"(c[3])
        : "r"(a[0]), "r"(a[1]), "r"(a[2]), "r"(a[3]), "r"(b[0]), "r"(b[1]));
}

__device__ __forceinline__ void mma16f(float* c, const unsigned* a, const unsigned* b) {
    asm("mma.sync.aligned.m16n8k16.row.col.f32.f16.f16.f32 "
        "{%0,%1,%2,%3}, {%4,%5,%6,%7}, {%8,%9}, {%0,%1,%2,%3};"
        : "+f"(c[0]), "+f"(c[1]), "+f"(c[2]), "+f"(c[3])
        : "r"(a[0]), "r"(a[1]), "r"(a[2]), "r"(a[3]), "r"(b[0]), "r"(b[1]));
}

__device__ __forceinline__ void ldsm4(unsigned* r, const unsigned* p) {
    unsigned addr = (unsigned)__cvta_generic_to_shared(const_cast<unsigned*>(p));
    asm volatile("ldmatrix.sync.aligned.m8n8.x4.shared.b16 {%0,%1,%2,%3}, [%4];"
                 : "=r"(r[0]), "=r"(r[1]), "=r"(r[2]), "=r"(r[3]) : "r"(addr));
}

// ---------------- device scratch ----------------
__device__ unsigned g_Bh[NMAT * MATW];
__device__ unsigned g_Bl[NMAT * MATW];
__device__ unsigned g_Xh[NN * 64];
__device__ float g_kg[NN * DIM];
__device__ int   g_sorted[NEDGE];
__device__ float g_efS[NHYP * DIM], g_efK[NHYP * DIM];
__device__ float g_noS[NN * DIM], g_noK[NN * DIM];
__device__ float g_related[NB * LKV * DIM];
__device__ float g_context[NB * LCTX * DIM];
__device__ float g_qh[NB * LCTX * DIM];
__device__ float g_kh[NB * LKV * DIM];
__device__ float g_vh[NB * LKV * DIM];
__device__ float g_o[NB * LCTX * DIM];
__device__ float g_attrel[NB * LCTX * DIM];
__device__ float g_t1[NB * LCTX * DIM];
__device__ float g_t2ctx[NB * LCTX * DIM];
__device__ float g_his[NB * DIM];
__device__ float g_user[NB * DIM];
__device__ float g_v1[DIM];

// ---------------- prep: pack B-matrices (W fp16 for edge; rest bf16 split) ----------------
__global__ void k_prep(const float* __restrict__ bases, const float* __restrict__ comp,
                       const float* __restrict__ root, const float* __restrict__ sth,
                       const float* __restrict__ kth, const float* __restrict__ ipw,
                       const float* __restrict__ opw, const float* __restrict__ aha,
                       const float* __restrict__ aa, const float* __restrict__ opb) {
    int idx = blockIdx.x * blockDim.x + threadIdx.x;
    if (idx >= 21 * MATW) {
        int n = idx - 21 * MATW;
        if (n < DIM) {
            float s = 0.f;
            for (int j = 0; j < DIM; j++) s = fmaf(opb[j], aha[j * DIM + n], s);
            g_v1[n] = s;
        }
        return;
    }
    int m = idx >> 13, rem = idx & (MATW - 1), n = rem >> 6, k2 = rem & 63;
    float s0, s1;
    if (m < 12) {
        const float* cp = comp + m * NBASES;
        s0 = 0.f; s1 = 0.f;
#pragma unroll
        for (int b = 0; b < NBASES; b++) {
            const float* bp = bases + (size_t)b * DIM * DIM + (2 * k2) * DIM + n;
            s0 = fmaf(cp[b], bp[0], s0);
            s1 = fmaf(cp[b], bp[DIM], s1);
        }
        g_Bh[idx] = pack_f16(s0, s1);   // fp16 single-word (edge uses hi only)
        return;
    } else if (m == 19) {
        // M1[k][n] = sum_j opw[j][k] * aha[j][n]  (t1 = o @ M1 + v1)
        s0 = 0.f; s1 = 0.f;
        for (int j = 0; j < DIM; j++) {
            float av = aha[j * DIM + n];
            s0 = fmaf(opw[j * DIM + 2 * k2],     av, s0);
            s1 = fmaf(opw[j * DIM + 2 * k2 + 1], av, s1);
        }
    } else {
        const float* b; int tr = 0;
        switch (m) {
            case 12: b = root; break;
            case 13: b = sth; break;
            case 14: b = kth; break;
            case 15: b = ipw; tr = 1; break;
            case 16: b = ipw + DIM * DIM; tr = 1; break;
            case 17: b = ipw + 2 * DIM * DIM; tr = 1; break;
            case 18: b = opw; tr = 1; break;
            default: b = aa; break;
        }
        if (tr) { s0 = b[n * DIM + 2 * k2]; s1 = b[n * DIM + 2 * k2 + 1]; }
        else    { s0 = b[(2 * k2) * DIM + n]; s1 = b[(2 * k2 + 1) * DIM + n]; }
    }
    unsigned lo, hi = pack_split(s0, s1, lo);
    g_Bh[idx] = hi; g_Bl[idx] = lo;
}

// counting sort with block aggregation; per-block prefix from g_typeCnt
__global__ void k_sort(const int* __restrict__ ty) {
    __shared__ int h[NREL], base[NREL];
    int t = threadIdx.x;
    if (t < NREL) h[t] = 0;
    __syncthreads();
    int e = blockIdx.x * blockDim.x + t;
    int tt = -1, loc = 0;
    if (e < NEDGE) { tt = ty[e]; loc = atomicAdd(&h[tt], 1); }
    __syncthreads();
    if (t < NREL) {
        int off = 0;
        for (int i = 0; i < t; i++) off += g_typeCnt[i];
        base[t] = off + (h[t] ? atomicAdd(&g_cursor[t], h[t]) : 0);
    }
    __syncthreads();
    if (e < NEDGE) g_sorted[base[tt] + loc] = e;
}

// bf16x2 3-term compute over one K32 chunk (ldmatrix fragment loads)
__device__ __forceinline__ void bf_chunk(
    const unsigned (*Ah)[20], const unsigned (*Al)[20],
    const unsigned (*Bh)[20], const unsigned (*Bl)[20],
    float acc[2][8][4], int lane, int m0, int n0) {
    const int ar = lane & 15, ac = (lane >> 4) * 4;
    const int br = (lane & 7) | ((lane >> 4) << 3), bc = ((lane >> 3) & 1) * 4;
#pragma unroll
    for (int s = 0; s < 2; s++) {
        const int kb = s * 8;
        unsigned bh[8][2], bl[8][2];
#pragma unroll
        for (int np = 0; np < 4; np++) {
            unsigned r4[4];
            ldsm4(r4, &Bh[n0 + np * 16 + br][kb + bc]);
            bh[2*np][0] = r4[0]; bh[2*np][1] = r4[1];
            bh[2*np+1][0] = r4[2]; bh[2*np+1][1] = r4[3];
            ldsm4(r4, &Bl[n0 + np * 16 + br][kb + bc]);
            bl[2*np][0] = r4[0]; bl[2*np][1] = r4[1];
            bl[2*np+1][0] = r4[2]; bl[2*np+1][1] = r4[3];
        }
#pragma unroll
        for (int ms = 0; ms < 2; ms++) {
            unsigned ah[4], al[4];
            ldsm4(ah, &Ah[m0 + ms * 16 + ar][kb + ac]);
            ldsm4(al, &Al[m0 + ms * 16 + ar][kb + ac]);
#pragma unroll
            for (int ns = 0; ns < 8; ns++) {
                mma16(acc[ms][ns], ah, bh[ns]);
                mma16(acc[ms][ns], ah, bl[ns]);
                mma16(acc[ms][ns], al, bh[ns]);
            }
        }
    }
}

// fp16 1-term compute over one K32 chunk: acc += Ah @ Bh
__device__ __forceinline__ void fp_chunk1(
    const unsigned (*Ah)[20], const unsigned (*Bh)[20],
    float acc[2][8][4], int lane, int m0, int n0) {
    const int ar = lane & 15, ac = (lane >> 4) * 4;
    const int br = (lane & 7) | ((lane >> 4) << 3), bc = ((lane >> 3) & 1) * 4;
#pragma unroll
    for (int s = 0; s < 2; s++) {
        const int kb = s * 8;
        unsigned bh[8][2];
#pragma unroll
        for (int np = 0; np < 4; np++) {
            unsigned r4[4];
            ldsm4(r4, &Bh[n0 + np * 16 + br][kb + bc]);
            bh[2*np][0] = r4[0]; bh[2*np][1] = r4[1];
            bh[2*np+1][0] = r4[2]; bh[2*np+1][1] = r4[3];
        }
#pragma unroll
        for (int ms = 0; ms < 2; ms++) {
            unsigned ah[4];
            ldsm4(ah, &Ah[m0 + ms * 16 + ar][kb + ac]);
#pragma unroll
            for (int ns = 0; ns < 8; ns++)
                mma16f(acc[ms][ns], ah, bh[ns]);
        }
    }
}

// convert 16 fp32 (scaled) -> 8 hi + 8 lo packed words (bf16)
__device__ __forceinline__ void conv_store_row(const float4* ap, float scale,
                                               unsigned* dh, unsigned* dl) {
    unsigned hw[8], lw[8];
#pragma unroll
    for (int q = 0; q < 4; q++) {
        float4 v = ap[q];
        v.x *= scale; v.y *= scale; v.z *= scale; v.w *= scale;
        hw[2*q]   = pack_split(v.x, v.y, lw[2*q]);
        hw[2*q+1] = pack_split(v.z, v.w, lw[2*q+1]);
    }
    *reinterpret_cast<uint4*>(dh)     = make_uint4(hw[0], hw[1], hw[2], hw[3]);
    *reinterpret_cast<uint4*>(dh + 4) = make_uint4(hw[4], hw[5], hw[6], hw[7]);
    *reinterpret_cast<uint4*>(dl)     = make_uint4(lw[0], lw[1], lw[2], lw[3]);
    *reinterpret_cast<uint4*>(dl + 4) = make_uint4(lw[4], lw[5], lw[6], lw[7]);
}

// fp16 single-precision variant (hi only)
__device__ __forceinline__ void conv_store_row_f16(const float4* ap, unsigned* dh) {
    unsigned hw[8];
#pragma unroll
    for (int q = 0; q < 4; q++) {
        float4 v = ap[q];
        hw[2*q]   = pack_f16(v.x, v.y);
        hw[2*q+1] = pack_f16(v.z, v.w);
    }
    *reinterpret_cast<uint4*>(dh)     = make_uint4(hw[0], hw[1], hw[2], hw[3]);
    *reinterpret_cast<uint4*>(dh + 4) = make_uint4(hw[4], hw[5], hw[6], hw[7]);
}

// ------------- generic GEMM body: C[M,128] = A[M,128] @ B(mat) (+bias, row scale 1/deg) ----
__device__ __forceinline__ void gemm_body(
    unsigned (*Ah)[20], unsigned (*Al)[20], unsigned (*Bh)[20], unsigned (*Bl)[20],
    const float* __restrict__ A, int mat, const float* __restrict__ bias,
    float* __restrict__ C, int M, const int* __restrict__ rowdeg, int blk) {
    const int t = threadIdx.x, lane = t & 31, warp = t >> 5;
    const int m0w = (warp & 3) * 32, n0w = (warp >> 2) * 64;
    const int blkM = blk * 128;
    const unsigned* Bhg = g_Bh + mat * MATW;
    const unsigned* Blg = g_Bl + mat * MATW;
    float acc[2][8][4];
#pragma unroll
    for (int i = 0; i < 2; i++)
#pragma unroll
        for (int j = 0; j < 8; j++)
#pragma unroll
            for (int q = 0; q < 4; q++) acc[i][j][q] = 0.f;
    const int mA = t >> 1, half = t & 1;
    const int nB = t >> 1, hB = (t & 1) * 8;

    for (int k0 = 0; k0 < 128; k0 += 32) {
        int gm = blkM + mA;
        if (gm < M) {
            const float4* ap = reinterpret_cast<const float4*>(A + (size_t)gm * DIM + k0 + half * 16);
            conv_store_row(ap, 1.0f, &Ah[mA][half * 8], &Al[mA][half * 8]);
        } else {
            uint4 z = make_uint4(0, 0, 0, 0);
            *reinterpret_cast<uint4*>(&Ah[mA][half*8]) = z;
            *reinterpret_cast<uint4*>(&Ah[mA][half*8+4]) = z;
            *reinterpret_cast<uint4*>(&Al[mA][half*8]) = z;
            *reinterpret_cast<uint4*>(&Al[mA][half*8+4]) = z;
        }
        {
            const unsigned* sh = Bhg + nB * 64 + k0 / 2 + hB;
            const unsigned* sl = Blg + nB * 64 + k0 / 2 + hB;
            *reinterpret_cast<uint4*>(&Bh[nB][hB])     = *reinterpret_cast<const uint4*>(sh);
            *reinterpret_cast<uint4*>(&Bh[nB][hB + 4]) = *reinterpret_cast<const uint4*>(sh + 4);
            *reinterpret_cast<uint4*>(&Bl[nB][hB])     = *reinterpret_cast<const uint4*>(sl);
            *reinterpret_cast<uint4*>(&Bl[nB][hB + 4]) = *reinterpret_cast<const uint4*>(sl + 4);
        }
        __syncthreads();
        bf_chunk(Ah, Al, Bh, Bl, acc, lane, m0w, n0w);
        __syncthreads();
    }
    const int gr = lane >> 2, tg = lane & 3;
#pragma unroll
    for (int ms = 0; ms < 2; ms++) {
#pragma unroll
        for (int hf = 0; hf < 2; hf++) {
            int gm = blkM + m0w + ms * 16 + gr + hf * 8;
            if (gm < M) {
                float scale = 1.f;
                if (rowdeg) { int dg = rowdeg[gm]; scale = dg > 0 ? 1.f / (float)dg : 0.f; }
                float* cp = C + (size_t)gm * DIM;
#pragma unroll
                for (int ns = 0; ns < 8; ns++) {
                    int col = n0w + ns * 8 + 2 * tg;
                    float b0 = bias ? bias[col] : 0.f;
                    float b1 = bias ? bias[col + 1] : 0.f;
                    float2 v = make_float2(acc[ms][ns][hf * 2] * scale + b0,
                                           acc[ms][ns][hf * 2 + 1] * scale + b1);
                    *reinterpret_cast<float2*>(cp + col) = v;
                }
            }
        }
    }
}

// ------------- F1: root GEMM || edge count || hyper counts || flags || pack X -------------
__global__ void __launch_bounds__(256) k_fuse1(
    const float* __restrict__ emb, const float* __restrict__ rbias,
    const int* __restrict__ edst, const int* __restrict__ ety,
    const int* __restrict__ snod, const int* __restrict__ sedg,
    const int* __restrict__ knod, const int* __restrict__ kedg,
    const int* __restrict__ sri, const int* __restrict__ kri) {
    __shared__ unsigned Ah[128][20], Al[128][20], Bh[128][20], Bl[128][20];
    __shared__ int fh[NREL];
    int b = blockIdx.x;
    int t = threadIdx.x;
    if (b < ROOTB) {
        gemm_body(Ah, Al, Bh, Bl, emb, 12 /*unused below*/, rbias, g_kg, NN, nullptr, b);
        return;
    }
    b -= ROOTB;
    if (b < COUNTB) {
        if (t < NREL) fh[t] = 0;
        __syncthreads();
        int e = b * 256 + t;
        if (e < NEDGE) {
            int tt = ety[e];
            atomicAdd(&g_cnt[edst[e] * NREL + tt], 1);
            atomicAdd(&fh[tt], 1);
        }
        __syncthreads();
        if (t < NREL && fh[t]) atomicAdd(&g_typeCnt[t], fh[t]);
        return;
    }
    b -= COUNTB;
    if (b < 2 * HCB) {
        const int* nodes; const int* edges; int* bdeg; int* ddeg;
        int lb = b;
        if (lb < HCB) { nodes = snod; edges = sedg; bdeg = g_bdegS; ddeg = g_ddegS; }
        else { lb -= HCB; nodes = knod; edges = kedg; bdeg = g_bdegK; ddeg = g_ddegK; }
        int p = lb * 256 + t;
        if (p < NP) {
            atomicAdd(&bdeg[edges[p]], 1);
            atomicAdd(&ddeg[nodes[p]], 1);
        }
        return;
    }
    b -= 2 * HCB;
    if (b < 2 * FLAGB) {
        const int* idx; int* flag; float* no;
        int lb = b;
        if (lb < FLAGB) { idx = sri; flag = g_flagS; no = g_noS; }
        else { lb -= FLAGB; idx = kri; flag = g_flagK; no = g_noK; }
        int i = lb * 256 + t;
        if (i < NB * LREL) {
            int n = idx[i];
            flag[n] = 1;
            float4 z = make_float4(0.f, 0.f, 0.f, 0.f);
            float4* p = reinterpret_cast<float4*>(no + (size_t)n * DIM);
#pragma unroll
            for (int d = 0; d < DIM / 4; d++) p[d] = z;
        }
        return;
    }
    b -= 2 * FLAGB;
    {
        int i = b * 256 + t;
        if (i < NN * 8) {
            int n = i >> 3, part = i & 7;
            const float4* ap = reinterpret_cast<const float4*>(emb + (size_t)n * DIM + part * 16);
            conv_store_row_f16(ap, &g_Xh[(size_t)n * 64 + part * 8]);
        }
    }
}

// ------------- RGCN edge GEMM (fp16 1-term, double-buffered) -------------
__global__ void __launch_bounds__(256) k_edge_gemm(
    const int* __restrict__ esrc, const int* __restrict__ edst) {
    extern __shared__ unsigned dsm[];
    unsigned (*Ah)[20] = (unsigned(*)[20])dsm;                   // 2 bufs
    unsigned (*Bh)[20] = (unsigned(*)[20])(dsm + 2 * 128 * 20);  // 2 bufs
    __shared__ int   sSrc[128], sDst[128];
    __shared__ float sNorm[128];
    const int bid = blockIdx.x;
    int r = -1, base = 0, cnt = 0;
    {
        int off = 0, toff = 0;
#pragma unroll
        for (int i = 0; i < NREL; i++) {
            int c = g_typeCnt[i];
            int nt = (c + 127) >> 7;
            if (r < 0 && bid < toff + nt) {
                int local = bid - toff;
                r = i; base = off + local * 128;
                cnt = c - local * 128; if (cnt > 128) cnt = 128;
            }
            off += c; toff += nt;
        }
    }
    if (r < 0) return;
    const int t = threadIdx.x, lane = t & 31, warp = t >> 5;
    const int m0w = (warp & 3) * 32, n0w = (warp >> 2) * 64;
    if (t < 128) {
        if (t < cnt) {
            int e = g_sorted[base + t];
            int d = edst[e];
            sSrc[t] = esrc[e]; sDst[t] = d;
            sNorm[t] = 1.0f / fmaxf((float)g_cnt[d * NREL + r], 1.0f);
        } else { sSrc[t] = 0; sDst[t] = -1; sNorm[t] = 0.f; }
    }
    __syncthreads();

    const int mA = t >> 1, half = t & 1;
    const unsigned* Bhg = g_Bh + (size_t)r * MATW;

    auto stage = [&](int buf, int k0) {
        int ro = buf * 128 + mA;
        size_t xoff = (size_t)sSrc[mA] * 64 + k0 / 2 + half * 8;
        const unsigned* xh = g_Xh + xoff;
        *reinterpret_cast<uint4*>(&Ah[ro][half*8])     = *reinterpret_cast<const uint4*>(xh);
        *reinterpret_cast<uint4*>(&Ah[ro][half*8 + 4]) = *reinterpret_cast<const uint4*>(xh + 4);
        size_t boff = (size_t)mA * 64 + k0 / 2 + half * 8;
        const unsigned* bh = Bhg + boff;
        *reinterpret_cast<uint4*>(&Bh[ro][half*8])     = *reinterpret_cast<const uint4*>(bh);
        *reinterpret_cast<uint4*>(&Bh[ro][half*8 + 4]) = *reinterpret_cast<const uint4*>(bh + 4);
    };

    float acc[2][8][4];
#pragma unroll
    for (int i = 0; i < 2; i++)
#pragma unroll
        for (int j = 0; j < 8; j++)
#pragma unroll
            for (int q = 0; q < 4; q++) acc[i][j][q] = 0.f;

    stage(0, 0);
    __syncthreads();
#pragma unroll
    for (int c = 0; c < 4; c++) {
        if (c < 3) stage((c + 1) & 1, (c + 1) * 32);
        int rb = (c & 1) * 128;
        fp_chunk1(&Ah[rb], &Bh[rb], acc, lane, m0w, n0w);
        __syncthreads();
    }

    const int gr = lane >> 2, tg = lane & 3;
#pragma unroll
    for (int ms = 0; ms < 2; ms++) {
#pragma unroll
        for (int hf = 0; hf < 2; hf++) {
            int rr = m0w + ms * 16 + gr + hf * 8;
            int dn = sDst[rr];
            float nrm = sNorm[rr];
#pragma unroll
            for (int ns = 0; ns < 8; ns++) {
                float v0 = acc[ms][ns][hf * 2] * nrm;
                float v1 = acc[ms][ns][hf * 2 + 1] * nrm;
                float p0 = __shfl_xor_sync(0xffffffffu, v0, 1);
                float p1 = __shfl_xor_sync(0xffffffffu, v1, 1);
                if (((tg & 1) == 0) && dn >= 0)
                    red_add_v4(g_kg + (size_t)dn * DIM + n0w + ns * 8 + 2 * tg, v0, v1, p0, p1);
            }
        }
    }
}

// ------------- fused S/K hyperedge accumulation: acc[he] += kg[node] -------------
__global__ void k_scatter_acc2(const int* __restrict__ snod, const int* __restrict__ sedg,
                               const int* __restrict__ knod, const int* __restrict__ kedg) {
    int w = (blockIdx.x * blockDim.x + threadIdx.x) >> 5;
    int lane = threadIdx.x & 31;
    const int* nodes; const int* edges; float* accum;
    if (w < NP) { nodes = snod; edges = sedg; accum = g_accS; }
    else { w -= NP; if (w >= NP) return; nodes = knod; edges = kedg; accum = g_accK; }
    float4 v = *reinterpret_cast<const float4*>(&g_kg[(size_t)nodes[w] * DIM + lane * 4]);
    red_add_v4(accum + (size_t)edges[w] * DIM + lane * 4, v.x, v.y, v.z, v.w);
}

// fused S/K edge-feature GEMMs: ef = (acc @ theta) / b_deg
__global__ void __launch_bounds__(256) k_gemm_ef2() {
    __shared__ unsigned Ah[128][20], Al[128][20], Bh[128][20], Bl[128][20];
    int b = blockIdx.x;
    if (b < EFB) gemm_body(Ah, Al, Bh, Bl, g_accS, 13, nullptr, g_efS, NHYP, g_bdegS, b);
    else gemm_body(Ah, Al, Bh, Bl, g_accK, 14, nullptr, g_efK, NHYP, g_bdegK, b - EFB);
}

// fused S/K node scatter (flag-masked)
__global__ void k_scatter_node2(const int* __restrict__ snod, const int* __restrict__ sedg,
                                const int* __restrict__ knod, const int* __restrict__ kedg) {
    int w = (blockIdx.x * blockDim.x + threadIdx.x) >> 5;
    int lane = threadIdx.x & 31;
    const int* nodes; const int* edges; const int* flag; const float* ef; float* no;
    if (w < NP) { nodes = snod; edges = sedg; flag = g_flagS; ef = g_efS; no = g_noS; }
    else { w -= NP; if (w >= NP) return; nodes = knod; edges = kedg; flag = g_flagK; ef = g_efK; no = g_noK; }
    int n = nodes[w];
    if (!flag[n]) return;
    float4 v = *reinterpret_cast<const float4*>(ef + (size_t)edges[w] * DIM + lane * 4);
    red_add_v4(no + (size_t)n * DIM + lane * 4, v.x, v.y, v.z, v.w);
}

// fused gathers: related + context
__global__ void k_gather(const int* __restrict__ sidx, const int* __restrict__ kidx,
                         const float* __restrict__ biasS, const float* __restrict__ biasK,
                         const int* __restrict__ cidx) {
    int i = blockIdx.x * blockDim.x + threadIdx.x;
    if (i < NB * LKV * DIM) {
        int d = i & 127, l = (i >> 7) & 127, b = i >> 14;
        float v;
        if (l < LREL) {
            int n = sidx[b * LREL + l]; int dd = g_ddegS[n];
            v = g_noS[(size_t)n * DIM + d] * (dd > 0 ? 1.f / dd : 0.f) + biasS[d];
        } else {
            int n = kidx[b * LREL + l - LREL]; int dd = g_ddegK[n];
            v = g_noK[(size_t)n * DIM + d] * (dd > 0 ? 1.f / dd : 0.f) + biasK[d];
        }
        g_related[i] = v;
        return;
    }
    int j = i - NB * LKV * DIM;
    if (j < NB * LCTX * DIM)
        g_context[j] = g_kg[(size_t)cidx[j >> 7] * DIM + (j & 127)];
}

// fused Q/K/V projections + context@aa
__global__ void __launch_bounds__(256) k_qkv(const float* __restrict__ ipb) {
    __shared__ unsigned Ah[128][20], Al[128][20], Bh[128][20], Bl[128][20];
    int b = blockIdx.x;
    if (b < 16) gemm_body(Ah, Al, Bh, Bl, g_context, 15, ipb, g_qh, NB * LCTX, nullptr, b);
    else if (b < 80) gemm_body(Ah, Al, Bh, Bl, g_related, 16, ipb + DIM, g_kh, NB * LKV, nullptr, b - 16);
    else if (b < 144) gemm_body(Ah, Al, Bh, Bl, g_related, 17, ipb + 2 * DIM, g_vh, NB * LKV, nullptr, b - 80);
    else gemm_body(Ah, Al, Bh, Bl, g_context, 20, nullptr, g_t2ctx, NB * LCTX, nullptr, b - 144);
}

// fused attrel-proj + t1 (independent given M1 precombination)
__global__ void __launch_bounds__(256) k_att2(const float* __restrict__ opb) {
    __shared__ unsigned Ah[128][20], Al[128][20], Bh[128][20], Bl[128][20];
    int b = blockIdx.x;
    if (b < 16) gemm_body(Ah, Al, Bh, Bl, g_o, 18, opb, g_attrel, NB * LCTX, nullptr, b);
    else gemm_body(Ah, Al, Bh, Bl, g_o, 19, g_v1, g_t1, NB * LCTX, nullptr, b - 16);
}

// ---------------- attention ----------------
__global__ void k_mha() {
    int b = blockIdx.x / NHEAD, h = blockIdx.x % NHEAD;
    __shared__ float ks[LKV][HDIM], vs[LKV][HDIM];
    int t = threadIdx.x;
    for (int i = t; i < LKV * HDIM; i += 32) {
        int k = i / HDIM, d = i % HDIM;
        size_t off = ((size_t)b * LKV + k) * DIM + h * HDIM + d;
        ks[k][d] = g_kh[off]; vs[k][d] = g_vh[off];
    }
    __syncwarp();
    float q[HDIM];
    size_t qoff = ((size_t)b * LCTX + t) * DIM + h * HDIM;
#pragma unroll
    for (int d = 0; d < HDIM; d++) q[d] = g_qh[qoff + d];
    float lg[LKV], mx = -1e30f;
    for (int k = 0; k < LKV; k++) {
        float s = 0.f;
#pragma unroll
        for (int d = 0; d < HDIM; d++) s += q[d] * ks[k][d];
        s *= 0.25f; lg[k] = s; mx = fmaxf(mx, s);
    }
    float sum = 0.f;
    for (int k = 0; k < LKV; k++) { lg[k] = expf(lg[k] - mx); sum += lg[k]; }
    float inv = 1.f / sum;
    float acc[HDIM];
#pragma unroll
    for (int d = 0; d < HDIM; d++) acc[d] = 0.f;
    for (int k = 0; k < LKV; k++) {
        float w = lg[k];
#pragma unroll
        for (int d = 0; d < HDIM; d++) acc[d] += w * vs[k][d];
    }
#pragma unroll
    for (int d = 0; d < HDIM; d++) g_o[qoff + d] = acc[d] * inv;
}

// his self-attn over attrel (L=32)
__global__ void k_selfattn_his(const float* __restrict__ ahb) {
    int b = blockIdx.x, t = threadIdx.x;
    __shared__ float w[LCTX];
    if (t < LCTX) {
        float e = 0.f;
        const float* tp = g_t1 + ((size_t)b * LCTX + t) * DIM;
        for (int d = 0; d < DIM; d++) e += tanhf(tp[d]) * ahb[d];
        w[t] = e;
    }
    __syncthreads();
    float mx = -1e30f;
    for (int l = 0; l < LCTX; l++) mx = fmaxf(mx, w[l]);
    float sum = 0.f;
    for (int l = 0; l < LCTX; l++) sum += expf(w[l] - mx);
    float inv = 1.f / sum, acc = 0.f;
    for (int l = 0; l < LCTX; l++)
        acc += expf(w[l] - mx) * g_attrel[((size_t)b * LCTX + l) * DIM + t];
    g_his[(size_t)b * DIM + t] = acc * inv;
}

// user self-attn over [context, his] (L=33) + inline his@aa + pack user row
__global__ void k_user(const float* __restrict__ aa, const float* __restrict__ ab) {
    int b = blockIdx.x, t = threadIdx.x;
    __shared__ float hs[DIM], t32[DIM], w[33], outv[DIM];
    hs[t] = g_his[(size_t)b * DIM + t];
    __syncthreads();
    {
        float s = 0.f;
        for (int k = 0; k < DIM; k++) s = fmaf(hs[k], aa[k * DIM + t], s);
        t32[t] = s;
    }
    __syncthreads();
    if (t < 32) {
        float e = 0.f;
        const float* tp = g_t2ctx + ((size_t)b * LCTX + t) * DIM;
        for (int d = 0; d < DIM; d++) e += tanhf(tp[d]) * ab[d];
        w[t] = e;
    } else if (t == 32) {
        float e = 0.f;
        for (int d = 0; d < DIM; d++) e += tanhf(t32[d]) * ab[d];
        w[32] = e;
    }
    __syncthreads();
    float mx = -1e30f;
    for (int l = 0; l < 33; l++) mx = fmaxf(mx, w[l]);
    float sum = 0.f;
    for (int l = 0; l < 33; l++) sum += expf(w[l] - mx);
    float inv = 1.f / sum, acc = 0.f;
    for (int l = 0; l < 32; l++)
        acc += expf(w[l] - mx) * g_context[((size_t)b * LCTX + l) * DIM + t];
    acc += expf(w[32] - mx) * hs[t];
    float uv = acc * inv;
    outv[t] = uv;
    g_user[(size_t)b * DIM + t] = uv;
    __syncthreads();
    if (t < 64) {
        unsigned lo, hi = pack_split(outv[2 * t], outv[2 * t + 1], lo);
        g_Bh[21 * MATW + b * 64 + t] = hi;
        g_Bl[21 * MATW + b * 64 + t] = lo;
    }
}

// ------------- scores via tensor cores, coalesced epilogue -------------
__global__ void __launch_bounds__(128) k_scores_mma(const float* __restrict__ rb,
                                                    float* __restrict__ out) {
    __shared__ unsigned Ah[128][20], Al[128][20], Bh[64][20], Bl[64][20];
    __shared__ float st[128][33];
    const int t = threadIdx.x, lane = t & 31, warp = t >> 5;
    const int m0w = warp * 32;
    const int blkM = blockIdx.x * 128;
    const unsigned* Bhg = g_Bh + 21 * MATW;
    const unsigned* Blg = g_Bl + 21 * MATW;
    float acc[2][8][4];
#pragma unroll
    for (int i = 0; i < 2; i++)
#pragma unroll
        for (int j = 0; j < 8; j++)
#pragma unroll
            for (int q = 0; q < 4; q++) acc[i][j][q] = 0.f;

    for (int k0 = 0; k0 < 128; k0 += 32) {
        int gm = blkM + t;
        if (gm < NN) {
            const float4* ap = reinterpret_cast<const float4*>(g_kg + (size_t)gm * DIM + k0);
            conv_store_row(ap, 1.0f, &Ah[t][0], &Al[t][0]);
            conv_store_row(ap + 4, 1.0f, &Ah[t][8], &Al[t][8]);
        } else {
            uint4 z = make_uint4(0, 0, 0, 0);
#pragma unroll
            for (int q = 0; q < 4; q++) {
                *reinterpret_cast<uint4*>(&Ah[t][4 * q]) = z;
                *reinterpret_cast<uint4*>(&Al[t][4 * q]) = z;
            }
        }
        {
            int nB = t & 63, hB = (t >> 6) * 8;
            const unsigned* sh = Bhg + nB * 64 + k0 / 2 + hB;
            const unsigned* sl = Blg + nB * 64 + k0 / 2 + hB;
            *reinterpret_cast<uint4*>(&Bh[nB][hB])     = *reinterpret_cast<const uint4*>(sh);
            *reinterpret_cast<uint4*>(&Bh[nB][hB + 4]) = *reinterpret_cast<const uint4*>(sh + 4);
            *reinterpret_cast<uint4*>(&Bl[nB][hB])     = *reinterpret_cast<const uint4*>(sl);
            *reinterpret_cast<uint4*>(&Bl[nB][hB + 4]) = *reinterpret_cast<const uint4*>(sl + 4);
        }
        __syncthreads();
        bf_chunk(Ah, Al, Bh, Bl, acc, lane, m0w, 0);
        __syncthreads();
    }
    const int gr = lane >> 2, tg = lane & 3;
    int gmn = blkM + t;
    float rv = (gmn < NN) ? rb[gmn] : 0.f;
#pragma unroll
    for (int halfc = 0; halfc < 2; halfc++) {
        __syncthreads();
#pragma unroll
        for (int ms = 0; ms < 2; ms++) {
#pragma unroll
            for (int hf = 0; hf < 2; hf++) {
                int row = m0w + ms * 16 + gr + hf * 8;
#pragma unroll
                for (int ns = 0; ns < 4; ns++) {
                    int nsg = halfc * 4 + ns;
                    st[row][ns * 8 + 2 * tg]     = acc[ms][nsg][hf * 2];
                    st[row][ns * 8 + 2 * tg + 1] = acc[ms][nsg][hf * 2 + 1];
                }
            }
        }
        __syncthreads();
        if (gmn < NN) {
#pragma unroll
            for (int c = 0; c < 32; c++)
                out[(size_t)(halfc * 32 + c) * NN + gmn] = st[t][c] + rv;
        }
    }
}

// ---------------- host ----------------
static void* sym(const void* s) { void* p = nullptr; cudaGetSymbolAddress(&p, s); return p; }

extern "C" void kernel_launch(void* const* d_in, const int* in_sizes, int n_in,
                              void* d_out, int out_size) {
    const float* emb   = (const float*)d_in[0];
    const float* bases = (const float*)d_in[1];
    const float* comp  = (const float*)d_in[2];
    const float* root  = (const float*)d_in[3];
    const float* rbias = (const float*)d_in[4];
    const float* sth   = (const float*)d_in[5];
    const float* sbi   = (const float*)d_in[6];
    const float* kth   = (const float*)d_in[7];
    const float* kbi   = (const float*)d_in[8];
    const float* ipw   = (const float*)d_in[9];
    const float* ipb   = (const float*)d_in[10];
    const float* opw   = (const float*)d_in[11];
    const float* opb   = (const float*)d_in[12];
    const float* aha   = (const float*)d_in[13];
    const float* ahb   = (const float*)d_in[14];
    const float* aa    = (const float*)d_in[15];
    const float* ab    = (const float*)d_in[16];
    const float* recb  = (const float*)d_in[17];
    const int* esrc = (const int*)d_in[18];
    const int* edst = (const int*)d_in[19];
    const int* ety  = (const int*)d_in[20];
    const int* snod = (const int*)d_in[21];
    const int* sedg = (const int*)d_in[22];
    const int* knod = (const int*)d_in[23];
    const int* kedg = (const int*)d_in[24];
    const int* sri  = (const int*)d_in[25];
    const int* kri  = (const int*)d_in[26];
    const int* cxi  = (const int*)d_in[27];
    float* out = (float*)d_out;

    cudaFuncSetAttribute(k_edge_gemm, cudaFuncAttributeMaxDynamicSharedMemorySize, EDGE_SMEM);

    // single fused memset of all zeroed scratch
    cudaMemsetAsync(sym(g_Z), 0, (size_t)ZW_TOTAL * 4, 0);

    k_prep<<<(21 * MATW + 128 + 255) / 256, 256>>>(bases, comp, root, sth, kth, ipw, opw,
                                                   aha, aa, opb);

    // F1: root GEMM || edge count || hyper counts || flags || pack X (fp16)
    k_fuse1<<<ROOTB + COUNTB + 2 * HCB + 2 * FLAGB + PACKB, 256>>>(
        emb, rbias, edst, ety, snod, sedg, knod, kedg, sri, kri);
    k_sort<<<(NEDGE + 255) / 256, 256>>>(ety);
    k_edge_gemm<<<EDGE_TILES, 256, EDGE_SMEM>>>(esrc, edst);

    // hypergraphs (linearity: scatter kg, then small GEMM with 1/b_deg)
    k_scatter_acc2<<<(2 * NP * 32) / 256, 256>>>(snod, sedg, knod, kedg);
    k_gemm_ef2<<<2 * EFB, 256>>>();
    k_scatter_node2<<<(2 * NP * 32) / 256, 256>>>(snod, sedg, knod, kedg);

    k_gather<<<(NB * LKV * DIM + NB * LCTX * DIM + 255) / 256, 256>>>(sri, kri, sbi, kbi, cxi);

    // MHA
    k_qkv<<<160, 256>>>(ipb);
    k_mha<<<NB * NHEAD, 32>>>();
    k_att2<<<32, 256>>>(opb);

    k_selfattn_his<<<NB, 128>>>(ahb);
    k_user<<<NB, 128>>>(aa, ab);

    // scores on tensor cores
    k_scores_mma<<<(NN + 127) / 128, 128>>>(recb, out);
}